// round 11
// baseline (speedup 1.0000x reference)
#include <cuda_runtime.h>
#include <cuda_bf16.h>
#include <cstdint>

// ---------------- Problem constants ----------------
#define N_NODES 210
#define N_EDGES 4200
#define BATCH   32

// ---------------- Static device scratch ----------------
__device__ float    g_bufA[32ll * 56 * 210 * 64];   // 24.08M floats
__device__ float    g_bufB[32ll * 56 * 210 * 64];
__device__ float    g_bufC[32ll * 48 * 210 * 128];  // 41.29M floats
__device__ int      g_rowptr[N_NODES + 1];
__device__ int      g_cols[N_EDGES];
__device__ float    g_norm[N_EDGES];
__device__ uint32_t g_wt[387072];                   // tf32 weights

// region offsets in g_wt
#define WOFF1 0        // b1_t1 padded (3,9,16,64)   = 27648
#define WOFF2 27648    // b1_t2        (3,9,64,128)  = 221184
#define WOFF3 248832   // b2_t1        (3,5,128,64)  = 122880
#define WOFF4 371712   // b2_t2        (3,5,64,16)   = 15360

// ---------------- helpers ----------------
__device__ __forceinline__ uint32_t f2tf32v(float x) {
    uint32_t r; asm("cvt.rna.tf32.f32 %0, %1;" : "=r"(r) : "f"(x)); return r;
}
__device__ __forceinline__ float roundtf(float x) {
    return __uint_as_float(f2tf32v(x));
}
__device__ __forceinline__ void mma_tf32(float c[4], const uint32_t a[4], const uint32_t b[2]) {
    asm volatile("mma.sync.aligned.m16n8k8.row.col.f32.tf32.tf32.f32 "
        "{%0,%1,%2,%3}, {%4,%5,%6,%7}, {%8,%9}, {%0,%1,%2,%3};"
        : "+f"(c[0]), "+f"(c[1]), "+f"(c[2]), "+f"(c[3])
        : "r"(a[0]), "r"(a[1]), "r"(a[2]), "r"(a[3]), "r"(b[0]), "r"(b[1]));
}
__device__ __forceinline__ uint32_t sptr(const void* p) {
    return (uint32_t)__cvta_generic_to_shared(p);
}
__device__ __forceinline__ void cpa16(uint32_t dst, const void* src, int sz) {
    asm volatile("cp.async.cg.shared.global [%0], [%1], 16, %2;"
                 :: "r"(dst), "l"(src), "r"(sz));
}
__device__ __forceinline__ void cpa_commit() { asm volatile("cp.async.commit_group;"); }
__device__ __forceinline__ void cpa_waitall() { asm volatile("cp.async.wait_group 0;"); }

// ---------------- Weight prepass: fp32 -> tf32 (padded for b1_t1) ----------------
__global__ void wconv_kernel(const float* __restrict__ w1, const float* __restrict__ w2,
                             const float* __restrict__ w3, const float* __restrict__ w4,
                             uint32_t* __restrict__ out)
{
    int i = blockIdx.x * blockDim.x + threadIdx.x;
    if (i < 27648) {  // b1_t1 padded: (g,k,ci<16,co<64); src (3,1,9,14,64)
        int co = i & 63; int r = i >> 6;
        int ci = r % 16; r /= 16;
        int k = r % 9;  int g = r / 9;
        float v = (ci < 14) ? w1[((g * 9 + k) * 14 + ci) * 64 + co] : 0.f;
        out[i] = f2tf32v(v);
        return;
    }
    int j = i - WOFF2;
    if (j >= 0 && j < 221184) { out[i] = f2tf32v(w2[j]); return; }
    j = i - WOFF3;
    if (j >= 0 && j < 122880) { out[i] = f2tf32v(w3[j]); return; }
    j = i - WOFF4;
    if (j >= 0 && j < 15360)  { out[i] = f2tf32v(w4[j]); return; }
}

// ---------------- CSR build (deterministic, 1 block) ----------------
__global__ void build_csr_kernel(const int* __restrict__ edge_index,
                                 const float* __restrict__ eattr,
                                 int* __restrict__ rowptr,
                                 int* __restrict__ cols,
                                 float* __restrict__ norms)
{
    __shared__ int   row_s[N_EDGES];
    __shared__ short col_s[N_EDGES];
    __shared__ float attr_s[N_EDGES];
    __shared__ int   cnt_s[N_NODES + 1];
    __shared__ float dis_s[N_NODES];

    const int tid = threadIdx.x;  // 256
    for (int i = tid; i < N_EDGES; i += 256) {
        row_s[i]  = edge_index[i];
        col_s[i]  = (short)edge_index[N_EDGES + i];
        attr_s[i] = eattr[i];
    }
    __syncthreads();

    if (tid < N_NODES) {
        float deg = 0.f; int cnt = 0;
        for (int e = 0; e < N_EDGES; e++) {
            if (row_s[e] == tid) { deg += attr_s[e]; cnt++; }
        }
        cnt_s[tid] = cnt;
        dis_s[tid] = (deg > 0.f) ? rsqrtf(deg) : 0.f;
    }
    __syncthreads();
    if (tid == 0) {
        int acc = 0;
        for (int n = 0; n < N_NODES; n++) { int c = cnt_s[n]; cnt_s[n] = acc; acc += c; }
        cnt_s[N_NODES] = acc;
    }
    __syncthreads();
    if (tid <= N_NODES) rowptr[tid] = cnt_s[tid];
    if (tid < N_NODES) {
        int wpos = cnt_s[tid];
        const float disr = dis_s[tid];
        for (int e = 0; e < N_EDGES; e++) {
            if (row_s[e] == tid) {
                int c = col_s[e];
                cols[wpos]  = c;
                norms[wpos] = -disr * attr_s[e] * dis_s[c];
                wpos++;
            }
        }
    }
}

// ---------------- Gated temporal conv via tf32 mma.sync ----------------
// 2 m-tiles per warp: B fragments reused across both -> smem bytes/mma halved.
template<int Cin, int CINP, int Cout, int Kt, int Tin, int Tout, int TP, int NG,
         int KSUB, int CO, bool ACP, int MINB>
__global__ void __launch_bounds__((NG * (TP / 16) / 2) * 32, MINB)
tconv_mma(const float* __restrict__ x, const uint32_t* __restrict__ wt,
          const float* __restrict__ bias, float* __restrict__ out)
{
    constexpr int MTN   = TP / 16;         // m-tiles per node
    constexpr int TILES = NG * MTN;
    constexpr int NW    = TILES / 2;       // warps (2 tiles per warp)
    constexpr int THREADS = NW * 32;
    constexpr int XS    = TP + Kt - 1;
    constexpr int SA    = CINP + 4;
    constexpr int COLS  = 3 * CO;
    constexpr int SB    = COLS + 8;
    constexpr int NT    = COLS / 8;
    constexpr int COCH  = Cout / CO;
    constexpr int NKS   = CINP / KSUB;
    constexpr int KPI   = Kt * NKS;
    constexpr int ITERS = COCH * KPI;
    constexpr int BUFSZ = KSUB * SB;
    constexpr int CO4   = CO / 4;
    static_assert(TILES % 2 == 0, "even tiles");

    extern __shared__ uint32_t sh[];
    uint32_t* As = sh;                  // NG*XS*SA
    uint32_t* Bs = sh + NG * XS * SA;   // 2*BUFSZ

    const int n0  = blockIdx.x * NG;
    const int b   = blockIdx.y;
    const int tid = threadIdx.x;
    const int wid = tid >> 5, lane = tid & 31;
    const int gid = lane >> 2, tig = lane & 3;

    const int tile0 = 2 * wid, tile1 = 2 * wid + 1;
    const int nl[2]  = { tile0 / MTN, tile1 / MTN };
    const int t0s[2] = { (tile0 % MTN) * 16, (tile1 % MTN) * 16 };

    // ---- stage A slab ----
    if (ACP) {
        constexpr int C4 = CINP / 4;
        for (int i = tid; i < NG * XS * C4; i += THREADS) {
            int nlx = i / (XS * C4);
            int r   = i % (XS * C4);
            int tp = r / C4, c4 = r % C4;
            int nn = n0 + nlx;
            bool ok = (nn < N_NODES) && (tp < Tin);
            const float* src = x + ((size_t)(b * Tin + (ok ? tp : 0)) * N_NODES
                                    + (nn < N_NODES ? nn : 0)) * Cin + c4 * 4;
            cpa16(sptr(As + nlx * XS * SA + tp * SA + c4 * 4), src, ok ? 16 : 0);
        }
    } else {
        for (int i = tid; i < NG * XS * CINP; i += THREADS) {
            int nlx = i / (XS * CINP);
            int r   = i % (XS * CINP);
            int tp = r / CINP, ci = r % CINP;
            int nn = n0 + nlx;
            float v = 0.f;
            if (nn < N_NODES && tp < Tin && ci < Cin)
                v = x[((size_t)(b * Tin + tp) * N_NODES + nn) * Cin + ci];
            As[nlx * XS * SA + tp * SA + ci] = f2tf32v(v);
        }
    }

    // ---- B stage (cp.async) ----
    auto stageB = [&](int it) {
        int cc = it / KPI, r = it % KPI, k = r / NKS, ks = r % NKS;
        uint32_t* Bb = Bs + (it & 1) * BUFSZ;
        for (int i = tid; i < KSUB * 3 * CO4; i += THREADS) {
            int cil = i / (3 * CO4);
            int rr  = i % (3 * CO4);
            int g   = rr / CO4, c4 = rr % CO4;
            const uint32_t* src = wt + ((size_t)(g * Kt + k) * CINP + ks * KSUB + cil) * Cout
                                     + cc * CO + c4 * 4;
            cpa16(sptr(Bb + cil * SB + g * CO + c4 * 4), src, 16);
        }
    };

    stageB(0);
    cpa_commit();

    const uint32_t* A0 = As + nl[0] * XS * SA;
    const uint32_t* A1 = As + nl[1] * XS * SA;

    float acc[2][NT][4];
    #pragma unroll
    for (int m = 0; m < 2; m++)
        #pragma unroll
        for (int i = 0; i < NT; i++) { acc[m][i][0] = acc[m][i][1] = acc[m][i][2] = acc[m][i][3] = 0.f; }

    #pragma unroll 1
    for (int it = 0; it < ITERS; ++it) {
        cpa_waitall();
        __syncthreads();
        if (it + 1 < ITERS) { stageB(it + 1); cpa_commit(); }

        const int r = it % KPI, k = r / NKS, ks = r % NKS;
        const uint32_t* Bb = Bs + (it & 1) * BUFSZ;
        #pragma unroll
        for (int kk = 0; kk < KSUB / 8; kk++) {
            uint32_t a0[4], a1[4];
            {
                const uint32_t* ap = A0 + (t0s[0] + gid + k) * SA + ks * KSUB + kk * 8 + tig;
                a0[0] = ap[0]; a0[1] = ap[8 * SA]; a0[2] = ap[4]; a0[3] = ap[8 * SA + 4];
            }
            {
                const uint32_t* ap = A1 + (t0s[1] + gid + k) * SA + ks * KSUB + kk * 8 + tig;
                a1[0] = ap[0]; a1[1] = ap[8 * SA]; a1[2] = ap[4]; a1[3] = ap[8 * SA + 4];
            }
            #pragma unroll
            for (int nt = 0; nt < NT; nt++) {
                const uint32_t* bp = Bb + (kk * 8 + tig) * SB + nt * 8 + gid;
                uint32_t bf[2] = { bp[0], bp[4 * SB] };
                mma_tf32(acc[0][nt], a0, bf);
                mma_tf32(acc[1][nt], a1, bf);
            }
        }

        if ((it + 1) % KPI == 0) {
            const int cc = it / KPI;
            #pragma unroll
            for (int m = 0; m < 2; m++) {
                const int n = n0 + nl[m];
                if (n < N_NODES) {
                    #pragma unroll
                    for (int nt3 = 0; nt3 < NT / 3; nt3++) {
                        int co = cc * CO + nt3 * 8 + tig * 2;
                        float bP0 = bias[co],            bP1 = bias[co + 1];
                        float bQ0 = bias[Cout + co],     bQ1 = bias[Cout + co + 1];
                        float bR0 = bias[2 * Cout + co], bR1 = bias[2 * Cout + co + 1];
                        #pragma unroll
                        for (int half = 0; half < 2; half++) {
                            int t = t0s[m] + gid + half * 8;
                            if (t < Tout) {
                                int i0 = half * 2;
                                float P0 = acc[m][nt3][i0] + bP0;
                                float P1 = acc[m][nt3][i0 + 1] + bP1;
                                float Q0 = acc[m][nt3 + NT / 3][i0] + bQ0;
                                float Q1 = acc[m][nt3 + NT / 3][i0 + 1] + bQ1;
                                float R0 = acc[m][nt3 + 2 * NT / 3][i0] + bR0;
                                float R1 = acc[m][nt3 + 2 * NT / 3][i0 + 1] + bR1;
                                float v0 = fmaxf(fmaf(P0, 1.f / (1.f + __expf(-Q0)), R0), 0.f);
                                float v1 = fmaxf(fmaf(P1, 1.f / (1.f + __expf(-Q1)), R1), 0.f);
                                *(float2*)&out[((size_t)(b * Tout + t) * N_NODES + n) * Cout + co] =
                                    make_float2(v0, v1);
                            }
                        }
                    }
                }
            }
            #pragma unroll
            for (int m = 0; m < 2; m++)
                #pragma unroll
                for (int i = 0; i < NT; i++) { acc[m][i][0] = acc[m][i][1] = acc[m][i][2] = acc[m][i][3] = 0.f; }
        }
    }
}

// ---------------- Fused Chebyshev with tf32 MMA combine (1024 thr) ----------------
// A (smem) = [t0 | Lz | L(Lz)] per node: 224(pad) x 192 fp32, stride 196 (==4 mod 32)
// B (smem) = [W0-W2 ; W1 ; 2*W2] tf32: 192 x 64, stride 72 (==8 mod 32)
// Lhat passes: ILP-2 per warp (node with both column halves).
// Combine: A hi MMA always; lo MMA only for Lhat-derived columns (kk>=8).
__global__ void __launch_bounds__(1024, 1)
cheb_mma_kernel(const float* __restrict__ zin, const float* __restrict__ W,
                const float* __restrict__ bias, float* __restrict__ out,
                const int* __restrict__ rowptr, const int* __restrict__ cols,
                const float* __restrict__ norms)
{
    extern __shared__ float fs[];
    float* As = fs;                                   // 224*196
    uint32_t* Ws = (uint32_t*)(fs + 224 * 196);       // 192*72

    const int bt  = blockIdx.x;
    const int tid = threadIdx.x;
    const size_t base = (size_t)bt * N_NODES * 64;

    // stage z into k-columns [0,64); zero pad rows; stage folded B'
    {
        const float4* zin4 = (const float4*)(zin + base);
        for (int i = tid; i < N_NODES * 16; i += 1024) {
            int n = i >> 4, c4 = i & 15;
            *(float4*)&As[n * 196 + c4 * 4] = zin4[i];
        }
        for (int i = tid; i < 14 * 196; i += 1024) {
            As[(210 + i / 196) * 196 + (i % 196)] = 0.f;
        }
        for (int i = tid; i < 3 * 64 * 64; i += 1024) {
            int term = i >> 12, h = (i >> 6) & 63, g = i & 63;
            float v;
            if (term == 0)      v = W[h * 64 + g] - W[2 * 4096 + h * 64 + g];
            else if (term == 1) v = W[4096 + h * 64 + g];
            else                v = 2.f * W[2 * 4096 + h * 64 + g];
            Ws[(term * 64 + h) * 72 + g] = f2tf32v(v);
        }
    }
    __syncthreads();

    const int wid = tid >> 5, lane = tid & 31;
    // Lhat pass 1: write k-columns [64,128). One node per warp, ILP-2 over halves.
    for (int nn = wid; nn < N_NODES; nn += 32) {
        int s = rowptr[nn], e = rowptr[nn + 1];
        float a0 = 0.f, a1 = 0.f;
        for (int i = s; i < e; i++) {
            int c = cols[i]; float w_ = norms[i];
            a0 = fmaf(w_, As[c * 196 + lane], a0);
            a1 = fmaf(w_, As[c * 196 + 32 + lane], a1);
        }
        As[nn * 196 + 64 + lane] = a0;
        As[nn * 196 + 96 + lane] = a1;
    }
    __syncthreads();
    // Lhat pass 2: write k-columns [128,192)
    for (int nn = wid; nn < N_NODES; nn += 32) {
        int s = rowptr[nn], e = rowptr[nn + 1];
        float a0 = 0.f, a1 = 0.f;
        for (int i = s; i < e; i++) {
            int c = cols[i]; float w_ = norms[i];
            a0 = fmaf(w_, As[c * 196 + 64 + lane], a0);
            a1 = fmaf(w_, As[c * 196 + 96 + lane], a1);
        }
        As[nn * 196 + 128 + lane] = a0;
        As[nn * 196 + 160 + lane] = a1;
    }
    __syncthreads();

    // MMA combine: 28 warps = (14 m-tiles) x (2 n-halves); each warp NT=4, K=192
    if (wid < 28) {
        const int gid = lane >> 2, tig = lane & 3;
        const int mt = wid >> 1, nh = wid & 1;
        const int m0 = mt * 16;
        float acc[4][4];
        #pragma unroll
        for (int i = 0; i < 4; i++) { acc[i][0] = acc[i][1] = acc[i][2] = acc[i][3] = 0.f; }

        // kk in [0,8): z columns, tf32-exact -> hi only
        #pragma unroll
        for (int kk = 0; kk < 8; kk++) {
            const float* ap = As + (m0 + gid) * 196 + kk * 8 + tig;
            uint32_t hi[4] = { f2tf32v(ap[0]), f2tf32v(ap[8 * 196]),
                               f2tf32v(ap[4]), f2tf32v(ap[8 * 196 + 4]) };
            #pragma unroll
            for (int j = 0; j < 4; j++) {
                int nt = nh * 4 + j;
                const uint32_t* bp = Ws + (kk * 8 + tig) * 72 + nt * 8 + gid;
                uint32_t bf[2] = { bp[0], bp[4 * 72] };
                mma_tf32(acc[j], hi, bf);
            }
        }
        // kk in [8,24): t1/t2 columns -> hi + lo
        #pragma unroll 4
        for (int kk = 8; kk < 24; kk++) {
            const float* ap = As + (m0 + gid) * 196 + kk * 8 + tig;
            float af[4] = { ap[0], ap[8 * 196], ap[4], ap[8 * 196 + 4] };
            uint32_t hi[4], lo[4];
            #pragma unroll
            for (int e = 0; e < 4; e++) {
                hi[e] = f2tf32v(af[e]);
                lo[e] = f2tf32v(af[e] - __uint_as_float(hi[e]));
            }
            #pragma unroll
            for (int j = 0; j < 4; j++) {
                int nt = nh * 4 + j;
                const uint32_t* bp = Ws + (kk * 8 + tig) * 72 + nt * 8 + gid;
                uint32_t bf[2] = { bp[0], bp[4 * 72] };
                mma_tf32(acc[j], hi, bf);
                mma_tf32(acc[j], lo, bf);
            }
        }

        #pragma unroll
        for (int j = 0; j < 4; j++) {
            int g = (nh * 4 + j) * 8 + tig * 2;
            float b0 = bias[g], b1 = bias[g + 1];
            int n_lo = m0 + gid, n_hi = m0 + gid + 8;
            if (n_lo < N_NODES) {
                float v0 = roundtf(fmaxf(acc[j][0] + b0, 0.f));
                float v1 = roundtf(fmaxf(acc[j][1] + b1, 0.f));
                *(float2*)&out[base + (size_t)n_lo * 64 + g] = make_float2(v0, v1);
            }
            if (n_hi < N_NODES) {
                float v0 = roundtf(fmaxf(acc[j][2] + b0, 0.f));
                float v1 = roundtf(fmaxf(acc[j][3] + b1, 0.f));
                *(float2*)&out[base + (size_t)n_hi * 64 + g] = make_float2(v0, v1);
            }
        }
    }
}

// ---------------- BatchNorm over node channel (in-place, float4) ----------------
template<int C, bool RND>
__global__ void bn_kernel(float* __restrict__ x, const float* __restrict__ gamma,
                          const float* __restrict__ beta, int BT, int N)
{
    constexpr int C4 = C / 4;
    const int n   = blockIdx.x;
    const int tid = threadIdx.x;  // 256
    const int M4  = BT * C4;
    float4* x4 = (float4*)x;
    float s = 0.f, s2 = 0.f;
    for (int i = tid; i < M4; i += 256) {
        int bt = i / C4, c4 = i % C4;
        float4 v = x4[((size_t)bt * N + n) * C4 + c4];
        s  += v.x + v.y + v.z + v.w;
        s2 += v.x * v.x + v.y * v.y + v.z * v.z + v.w * v.w;
    }
    __shared__ float rs[256], rs2[256];
    __shared__ float mean_s, istd_s;
    rs[tid] = s; rs2[tid] = s2;
    __syncthreads();
    for (int o = 128; o > 0; o >>= 1) {
        if (tid < o) { rs[tid] += rs[tid + o]; rs2[tid] += rs2[tid + o]; }
        __syncthreads();
    }
    if (tid == 0) {
        float inv = 1.f / (float)(BT * C);
        float mean = rs[0] * inv;
        float var  = rs2[0] * inv - mean * mean;
        mean_s = mean;
        istd_s = rsqrtf(var + 1e-5f);
    }
    __syncthreads();
    const float gm = gamma[n], bt_ = beta[n];
    const float mean = mean_s, istd = istd_s;
    for (int i = tid; i < M4; i += 256) {
        int bt = i / C4, c4 = i % C4;
        size_t a = ((size_t)bt * N + n) * C4 + c4;
        float4 v = x4[a];
        v.x = (v.x - mean) * istd * gm + bt_;
        v.y = (v.y - mean) * istd * gm + bt_;
        v.z = (v.z - mean) * istd * gm + bt_;
        v.w = (v.w - mean) * istd * gm + bt_;
        if (RND) { v.x = roundtf(v.x); v.y = roundtf(v.y); v.z = roundtf(v.z); v.w = roundtf(v.w); }
        x4[a] = v;
    }
}

// ---------------- Final FC: (R,16) @ (16,3) + b ----------------
__global__ void fc_kernel(const float* __restrict__ h, const float* __restrict__ w,
                          const float* __restrict__ b, float* __restrict__ out, int R)
{
    int r = blockIdx.x * blockDim.x + threadIdx.x;
    if (r >= R) return;
    const float4* hr = (const float4*)(h + (size_t)r * 16);
    float o0 = b[0], o1 = b[1], o2 = b[2];
    #pragma unroll
    for (int c4 = 0; c4 < 4; c4++) {
        float4 v = hr[c4];
        o0 = fmaf(v.x, w[(c4 * 4 + 0) * 3 + 0], o0); o1 = fmaf(v.x, w[(c4 * 4 + 0) * 3 + 1], o1); o2 = fmaf(v.x, w[(c4 * 4 + 0) * 3 + 2], o2);
        o0 = fmaf(v.y, w[(c4 * 4 + 1) * 3 + 0], o0); o1 = fmaf(v.y, w[(c4 * 4 + 1) * 3 + 1], o1); o2 = fmaf(v.y, w[(c4 * 4 + 1) * 3 + 2], o2);
        o0 = fmaf(v.z, w[(c4 * 4 + 2) * 3 + 0], o0); o1 = fmaf(v.z, w[(c4 * 4 + 2) * 3 + 1], o1); o2 = fmaf(v.z, w[(c4 * 4 + 2) * 3 + 2], o2);
        o0 = fmaf(v.w, w[(c4 * 4 + 3) * 3 + 0], o0); o1 = fmaf(v.w, w[(c4 * 4 + 3) * 3 + 1], o1); o2 = fmaf(v.w, w[(c4 * 4 + 3) * 3 + 2], o2);
    }
    out[(size_t)r * 3 + 0] = o0;
    out[(size_t)r * 3 + 1] = o1;
    out[(size_t)r * 3 + 2] = o2;
}

// ---------------- Launch ----------------
extern "C" void kernel_launch(void* const* d_in, const int* in_sizes, int n_in,
                              void* d_out, int out_size)
{
    const float* x        = (const float*)d_in[0];
    const int*   eidx     = (const int*)d_in[1];
    const float* eattr    = (const float*)d_in[2];
    const float* b1_t1_w  = (const float*)d_in[3];
    const float* b1_t1_b  = (const float*)d_in[4];
    const float* b1_ch_w  = (const float*)d_in[5];
    const float* b1_ch_b  = (const float*)d_in[6];
    const float* b1_t2_w  = (const float*)d_in[7];
    const float* b1_t2_b  = (const float*)d_in[8];
    const float* b1_bn_g  = (const float*)d_in[9];
    const float* b1_bn_b  = (const float*)d_in[10];
    const float* b2_t1_w  = (const float*)d_in[11];
    const float* b2_t1_b  = (const float*)d_in[12];
    const float* b2_ch_w  = (const float*)d_in[13];
    const float* b2_ch_b  = (const float*)d_in[14];
    const float* b2_t2_w  = (const float*)d_in[15];
    const float* b2_t2_b  = (const float*)d_in[16];
    const float* b2_bn_g  = (const float*)d_in[17];
    const float* b2_bn_b  = (const float*)d_in[18];
    const float* fc_w     = (const float*)d_in[19];
    const float* fc_b     = (const float*)d_in[20];

    float *bufA, *bufB, *bufC, *nrm;
    int *rowptr, *cols; uint32_t* wt;
    cudaGetSymbolAddress((void**)&bufA,  g_bufA);
    cudaGetSymbolAddress((void**)&bufB,  g_bufB);
    cudaGetSymbolAddress((void**)&bufC,  g_bufC);
    cudaGetSymbolAddress((void**)&rowptr, g_rowptr);
    cudaGetSymbolAddress((void**)&cols,  g_cols);
    cudaGetSymbolAddress((void**)&nrm,   g_norm);
    cudaGetSymbolAddress((void**)&wt,    g_wt);

    const int N = N_NODES;

    // instantiations:           Cin CINP Cout Kt Tin Tout TP NG  KSUB CO  ACP  MINB
    auto k_b1t1 = tconv_mma<14, 16, 64, 9, 64, 56, 64, 8, 16, 32, false, 2>;   // 16 warps, 2 blk/SM
    auto k_b1t2 = tconv_mma<64, 64, 128, 9, 56, 48, 48, 10, 64, 32, true, 1>;  // 15 warps, 1 blk/SM
    auto k_b2t1 = tconv_mma<128, 128, 64, 5, 48, 44, 48, 6, 64, 32, true, 1>;  // 9 warps, 1 blk/SM
    auto k_b2t2 = tconv_mma<64, 64, 16, 5, 44, 40, 48, 4, 64, 16, true, 2>;    // 6 warps, 2 blk/SM

    // smem bytes: (NG*XS*SA + 2*KSUB*SB) * 4
    const int sm_b1t1 = (8 * 72 * 20 + 2 * 16 * 104) * 4;    // 59,392
    const int sm_b1t2 = (10 * 56 * 68 + 2 * 64 * 104) * 4;   // 205,568
    const int sm_b2t1 = (6 * 52 * 132 + 2 * 64 * 104) * 4;   // 217,984
    const int sm_b2t2 = (4 * 52 * 68 + 2 * 64 * 56) * 4;     // 85,248
    const int sm_cheb = (224 * 196 + 192 * 72) * 4;          // 230,912

    cudaFuncSetAttribute(k_b1t1, cudaFuncAttributeMaxDynamicSharedMemorySize, sm_b1t1);
    cudaFuncSetAttribute(k_b1t2, cudaFuncAttributeMaxDynamicSharedMemorySize, sm_b1t2);
    cudaFuncSetAttribute(k_b2t1, cudaFuncAttributeMaxDynamicSharedMemorySize, sm_b2t1);
    cudaFuncSetAttribute(k_b2t2, cudaFuncAttributeMaxDynamicSharedMemorySize, sm_b2t2);
    cudaFuncSetAttribute(cheb_mma_kernel, cudaFuncAttributeMaxDynamicSharedMemorySize, sm_cheb);

    // ---- prep ----
    build_csr_kernel<<<1, 256>>>(eidx, eattr, rowptr, cols, nrm);
    wconv_kernel<<<(387072 + 255) / 256, 256>>>(b1_t1_w, b1_t2_w, b2_t1_w, b2_t2_w, wt);

    // ======== Block 1 ========
    k_b1t1<<<dim3(27, BATCH), 512, sm_b1t1>>>(x, wt + WOFF1, b1_t1_b, bufA);
    cheb_mma_kernel<<<32 * 56, 1024, sm_cheb>>>(bufA, b1_ch_w, b1_ch_b, bufB, rowptr, cols, nrm);
    k_b1t2<<<dim3(21, BATCH), 480, sm_b1t2>>>(bufB, wt + WOFF2, b1_t2_b, bufC);
    bn_kernel<128, true><<<N, 256>>>(bufC, b1_bn_g, b1_bn_b, 32 * 48, N);

    // ======== Block 2 ========
    k_b2t1<<<dim3(35, BATCH), 288, sm_b2t1>>>(bufC, wt + WOFF3, b2_t1_b, bufA);
    cheb_mma_kernel<<<32 * 44, 1024, sm_cheb>>>(bufA, b2_ch_w, b2_ch_b, bufB, rowptr, cols, nrm);
    k_b2t2<<<dim3(53, BATCH), 192, sm_b2t2>>>(bufB, wt + WOFF4, b2_t2_b, bufC);
    bn_kernel<16, false><<<N, 256>>>(bufC, b2_bn_g, b2_bn_b, 32 * 40, N);

    // ---- FC ----
    {
        int R = 32 * 40 * N;  // 268800
        fc_kernel<<<(R + 255) / 256, 256>>>(bufC, fc_w, fc_b, (float*)d_out, R);
    }
    (void)in_sizes; (void)n_in; (void)out_size;
}

// round 12
// speedup vs baseline: 1.4983x; 1.4983x over previous
#include <cuda_runtime.h>
#include <cuda_bf16.h>
#include <cstdint>

// ---------------- Problem constants ----------------
#define N_NODES 210
#define N_EDGES 4200
#define BATCH   32

// ---------------- Static device scratch ----------------
__device__ float    g_bufA[32ll * 56 * 210 * 64];   // 24.08M floats
__device__ float    g_bufB[32ll * 56 * 210 * 64];
__device__ float    g_bufC[32ll * 48 * 210 * 128];  // 41.29M floats
__device__ int      g_rowptr[N_NODES + 1];
__device__ int      g_cols[N_EDGES];
__device__ float    g_norm[N_EDGES];
__device__ uint32_t g_wt[387072];                   // tf32 weights

// region offsets in g_wt
#define WOFF1 0        // b1_t1 padded (3,9,16,64)   = 27648
#define WOFF2 27648    // b1_t2        (3,9,64,128)  = 221184
#define WOFF3 248832   // b2_t1        (3,5,128,64)  = 122880
#define WOFF4 371712   // b2_t2        (3,5,64,16)   = 15360

// ---------------- helpers ----------------
__device__ __forceinline__ uint32_t f2tf32v(float x) {
    uint32_t r; asm("cvt.rna.tf32.f32 %0, %1;" : "=r"(r) : "f"(x)); return r;
}
__device__ __forceinline__ float roundtf(float x) {
    return __uint_as_float(f2tf32v(x));
}
__device__ __forceinline__ void mma_tf32(float c[4], const uint32_t a[4], const uint32_t b[2]) {
    asm volatile("mma.sync.aligned.m16n8k8.row.col.f32.tf32.tf32.f32 "
        "{%0,%1,%2,%3}, {%4,%5,%6,%7}, {%8,%9}, {%0,%1,%2,%3};"
        : "+f"(c[0]), "+f"(c[1]), "+f"(c[2]), "+f"(c[3])
        : "r"(a[0]), "r"(a[1]), "r"(a[2]), "r"(a[3]), "r"(b[0]), "r"(b[1]));
}
__device__ __forceinline__ uint32_t sptr(const void* p) {
    return (uint32_t)__cvta_generic_to_shared(p);
}
__device__ __forceinline__ void cpa16(uint32_t dst, const void* src, int sz) {
    asm volatile("cp.async.cg.shared.global [%0], [%1], 16, %2;"
                 :: "r"(dst), "l"(src), "r"(sz));
}
__device__ __forceinline__ void cpa_commit() { asm volatile("cp.async.commit_group;"); }
__device__ __forceinline__ void cpa_waitall() { asm volatile("cp.async.wait_group 0;"); }

// ---------------- Weight prepass: fp32 -> tf32 (padded for b1_t1) ----------------
__global__ void wconv_kernel(const float* __restrict__ w1, const float* __restrict__ w2,
                             const float* __restrict__ w3, const float* __restrict__ w4,
                             uint32_t* __restrict__ out)
{
    int i = blockIdx.x * blockDim.x + threadIdx.x;
    if (i < 27648) {  // b1_t1 padded: (g,k,ci<16,co<64); src (3,1,9,14,64)
        int co = i & 63; int r = i >> 6;
        int ci = r % 16; r /= 16;
        int k = r % 9;  int g = r / 9;
        float v = (ci < 14) ? w1[((g * 9 + k) * 14 + ci) * 64 + co] : 0.f;
        out[i] = f2tf32v(v);
        return;
    }
    int j = i - WOFF2;
    if (j >= 0 && j < 221184) { out[i] = f2tf32v(w2[j]); return; }
    j = i - WOFF3;
    if (j >= 0 && j < 122880) { out[i] = f2tf32v(w3[j]); return; }
    j = i - WOFF4;
    if (j >= 0 && j < 15360)  { out[i] = f2tf32v(w4[j]); return; }
}

// ---------------- CSR build (deterministic, 1 block) ----------------
__global__ void build_csr_kernel(const int* __restrict__ edge_index,
                                 const float* __restrict__ eattr,
                                 int* __restrict__ rowptr,
                                 int* __restrict__ cols,
                                 float* __restrict__ norms)
{
    __shared__ int   row_s[N_EDGES];
    __shared__ short col_s[N_EDGES];
    __shared__ float attr_s[N_EDGES];
    __shared__ int   cnt_s[N_NODES + 1];
    __shared__ float dis_s[N_NODES];

    const int tid = threadIdx.x;  // 256
    for (int i = tid; i < N_EDGES; i += 256) {
        row_s[i]  = edge_index[i];
        col_s[i]  = (short)edge_index[N_EDGES + i];
        attr_s[i] = eattr[i];
    }
    __syncthreads();

    if (tid < N_NODES) {
        float deg = 0.f; int cnt = 0;
        for (int e = 0; e < N_EDGES; e++) {
            if (row_s[e] == tid) { deg += attr_s[e]; cnt++; }
        }
        cnt_s[tid] = cnt;
        dis_s[tid] = (deg > 0.f) ? rsqrtf(deg) : 0.f;
    }
    __syncthreads();
    if (tid == 0) {
        int acc = 0;
        for (int n = 0; n < N_NODES; n++) { int c = cnt_s[n]; cnt_s[n] = acc; acc += c; }
        cnt_s[N_NODES] = acc;
    }
    __syncthreads();
    if (tid <= N_NODES) rowptr[tid] = cnt_s[tid];
    if (tid < N_NODES) {
        int wpos = cnt_s[tid];
        const float disr = dis_s[tid];
        for (int e = 0; e < N_EDGES; e++) {
            if (row_s[e] == tid) {
                int c = col_s[e];
                cols[wpos]  = c;
                norms[wpos] = -disr * attr_s[e] * dis_s[c];
                wpos++;
            }
        }
    }
}

// ---------------- Gated temporal conv via tf32 mma.sync ----------------
// 2 m-tiles per warp: B fragments reused across both -> smem bytes/mma halved.
template<int Cin, int CINP, int Cout, int Kt, int Tin, int Tout, int TP, int NG,
         int KSUB, int CO, bool ACP, int MINB>
__global__ void __launch_bounds__((NG * (TP / 16) / 2) * 32, MINB)
tconv_mma(const float* __restrict__ x, const uint32_t* __restrict__ wt,
          const float* __restrict__ bias, float* __restrict__ out)
{
    constexpr int MTN   = TP / 16;         // m-tiles per node
    constexpr int TILES = NG * MTN;
    constexpr int NW    = TILES / 2;       // warps (2 tiles per warp)
    constexpr int THREADS = NW * 32;
    constexpr int XS    = TP + Kt - 1;
    constexpr int SA    = CINP + 4;
    constexpr int COLS  = 3 * CO;
    constexpr int SB    = COLS + 8;
    constexpr int NT    = COLS / 8;
    constexpr int COCH  = Cout / CO;
    constexpr int NKS   = CINP / KSUB;
    constexpr int KPI   = Kt * NKS;
    constexpr int ITERS = COCH * KPI;
    constexpr int BUFSZ = KSUB * SB;
    constexpr int CO4   = CO / 4;
    static_assert(TILES % 2 == 0, "even tiles");

    extern __shared__ uint32_t sh[];
    uint32_t* As = sh;                  // NG*XS*SA
    uint32_t* Bs = sh + NG * XS * SA;   // 2*BUFSZ

    const int n0  = blockIdx.x * NG;
    const int b   = blockIdx.y;
    const int tid = threadIdx.x;
    const int wid = tid >> 5, lane = tid & 31;
    const int gid = lane >> 2, tig = lane & 3;

    const int tile0 = 2 * wid, tile1 = 2 * wid + 1;
    const int nl[2]  = { tile0 / MTN, tile1 / MTN };
    const int t0s[2] = { (tile0 % MTN) * 16, (tile1 % MTN) * 16 };

    // ---- stage A slab ----
    if (ACP) {
        constexpr int C4 = CINP / 4;
        for (int i = tid; i < NG * XS * C4; i += THREADS) {
            int nlx = i / (XS * C4);
            int r   = i % (XS * C4);
            int tp = r / C4, c4 = r % C4;
            int nn = n0 + nlx;
            bool ok = (nn < N_NODES) && (tp < Tin);
            const float* src = x + ((size_t)(b * Tin + (ok ? tp : 0)) * N_NODES
                                    + (nn < N_NODES ? nn : 0)) * Cin + c4 * 4;
            cpa16(sptr(As + nlx * XS * SA + tp * SA + c4 * 4), src, ok ? 16 : 0);
        }
    } else {
        for (int i = tid; i < NG * XS * CINP; i += THREADS) {
            int nlx = i / (XS * CINP);
            int r   = i % (XS * CINP);
            int tp = r / CINP, ci = r % CINP;
            int nn = n0 + nlx;
            float v = 0.f;
            if (nn < N_NODES && tp < Tin && ci < Cin)
                v = x[((size_t)(b * Tin + tp) * N_NODES + nn) * Cin + ci];
            As[nlx * XS * SA + tp * SA + ci] = f2tf32v(v);
        }
    }

    // ---- B stage (cp.async) ----
    auto stageB = [&](int it) {
        int cc = it / KPI, r = it % KPI, k = r / NKS, ks = r % NKS;
        uint32_t* Bb = Bs + (it & 1) * BUFSZ;
        for (int i = tid; i < KSUB * 3 * CO4; i += THREADS) {
            int cil = i / (3 * CO4);
            int rr  = i % (3 * CO4);
            int g   = rr / CO4, c4 = rr % CO4;
            const uint32_t* src = wt + ((size_t)(g * Kt + k) * CINP + ks * KSUB + cil) * Cout
                                     + cc * CO + c4 * 4;
            cpa16(sptr(Bb + cil * SB + g * CO + c4 * 4), src, 16);
        }
    };

    stageB(0);
    cpa_commit();

    const uint32_t* A0 = As + nl[0] * XS * SA;
    const uint32_t* A1 = As + nl[1] * XS * SA;

    float acc[2][NT][4];
    #pragma unroll
    for (int m = 0; m < 2; m++)
        #pragma unroll
        for (int i = 0; i < NT; i++) { acc[m][i][0] = acc[m][i][1] = acc[m][i][2] = acc[m][i][3] = 0.f; }

    #pragma unroll 1
    for (int it = 0; it < ITERS; ++it) {
        cpa_waitall();
        __syncthreads();
        if (it + 1 < ITERS) { stageB(it + 1); cpa_commit(); }

        const int r = it % KPI, k = r / NKS, ks = r % NKS;
        const uint32_t* Bb = Bs + (it & 1) * BUFSZ;
        #pragma unroll
        for (int kk = 0; kk < KSUB / 8; kk++) {
            uint32_t a0[4], a1[4];
            {
                const uint32_t* ap = A0 + (t0s[0] + gid + k) * SA + ks * KSUB + kk * 8 + tig;
                a0[0] = ap[0]; a0[1] = ap[8 * SA]; a0[2] = ap[4]; a0[3] = ap[8 * SA + 4];
            }
            {
                const uint32_t* ap = A1 + (t0s[1] + gid + k) * SA + ks * KSUB + kk * 8 + tig;
                a1[0] = ap[0]; a1[1] = ap[8 * SA]; a1[2] = ap[4]; a1[3] = ap[8 * SA + 4];
            }
            #pragma unroll
            for (int nt = 0; nt < NT; nt++) {
                const uint32_t* bp = Bb + (kk * 8 + tig) * SB + nt * 8 + gid;
                uint32_t bf[2] = { bp[0], bp[4 * SB] };
                mma_tf32(acc[0][nt], a0, bf);
                mma_tf32(acc[1][nt], a1, bf);
            }
        }

        if ((it + 1) % KPI == 0) {
            const int cc = it / KPI;
            #pragma unroll
            for (int m = 0; m < 2; m++) {
                const int n = n0 + nl[m];
                if (n < N_NODES) {
                    #pragma unroll
                    for (int nt3 = 0; nt3 < NT / 3; nt3++) {
                        int co = cc * CO + nt3 * 8 + tig * 2;
                        float bP0 = bias[co],            bP1 = bias[co + 1];
                        float bQ0 = bias[Cout + co],     bQ1 = bias[Cout + co + 1];
                        float bR0 = bias[2 * Cout + co], bR1 = bias[2 * Cout + co + 1];
                        #pragma unroll
                        for (int half = 0; half < 2; half++) {
                            int t = t0s[m] + gid + half * 8;
                            if (t < Tout) {
                                int i0 = half * 2;
                                float P0 = acc[m][nt3][i0] + bP0;
                                float P1 = acc[m][nt3][i0 + 1] + bP1;
                                float Q0 = acc[m][nt3 + NT / 3][i0] + bQ0;
                                float Q1 = acc[m][nt3 + NT / 3][i0 + 1] + bQ1;
                                float R0 = acc[m][nt3 + 2 * NT / 3][i0] + bR0;
                                float R1 = acc[m][nt3 + 2 * NT / 3][i0 + 1] + bR1;
                                float v0 = fmaxf(fmaf(P0, 1.f / (1.f + __expf(-Q0)), R0), 0.f);
                                float v1 = fmaxf(fmaf(P1, 1.f / (1.f + __expf(-Q1)), R1), 0.f);
                                *(float2*)&out[((size_t)(b * Tout + t) * N_NODES + n) * Cout + co] =
                                    make_float2(v0, v1);
                            }
                        }
                    }
                }
            }
            #pragma unroll
            for (int m = 0; m < 2; m++)
                #pragma unroll
                for (int i = 0; i < NT; i++) { acc[m][i][0] = acc[m][i][1] = acc[m][i][2] = acc[m][i][3] = 0.f; }
        }
    }
}

// ---------------- Fused Chebyshev with tf32 MMA combine (1024 thr) ----------------
// A (smem) = [t0 | Lz | L(Lz)] per node: 224(pad) x 192 fp32, stride 196 (==4 mod 32)
// B (smem) = [W0-W2 ; W1 ; 2*W2] tf32: 192 x 64, stride 72 (==8 mod 32)
// Lhat passes: ILP-2 per warp (node with both column halves).
// Combine: A hi MMA always; lo MMA only for Lhat-derived columns (kk>=8).
__global__ void __launch_bounds__(1024, 1)
cheb_mma_kernel(const float* __restrict__ zin, const float* __restrict__ W,
                const float* __restrict__ bias, float* __restrict__ out,
                const int* __restrict__ rowptr, const int* __restrict__ cols,
                const float* __restrict__ norms)
{
    extern __shared__ float fs[];
    float* As = fs;                                   // 224*196
    uint32_t* Ws = (uint32_t*)(fs + 224 * 196);       // 192*72

    const int bt  = blockIdx.x;
    const int tid = threadIdx.x;
    const size_t base = (size_t)bt * N_NODES * 64;

    // stage z into k-columns [0,64); zero pad rows; stage folded B'
    {
        const float4* zin4 = (const float4*)(zin + base);
        for (int i = tid; i < N_NODES * 16; i += 1024) {
            int n = i >> 4, c4 = i & 15;
            *(float4*)&As[n * 196 + c4 * 4] = zin4[i];
        }
        for (int i = tid; i < 14 * 196; i += 1024) {
            As[(210 + i / 196) * 196 + (i % 196)] = 0.f;
        }
        for (int i = tid; i < 3 * 64 * 64; i += 1024) {
            int term = i >> 12, h = (i >> 6) & 63, g = i & 63;
            float v;
            if (term == 0)      v = W[h * 64 + g] - W[2 * 4096 + h * 64 + g];
            else if (term == 1) v = W[4096 + h * 64 + g];
            else                v = 2.f * W[2 * 4096 + h * 64 + g];
            Ws[(term * 64 + h) * 72 + g] = f2tf32v(v);
        }
    }
    __syncthreads();

    const int wid = tid >> 5, lane = tid & 31;
    // Lhat pass 1: write k-columns [64,128). One node per warp, ILP-2 over halves.
    for (int nn = wid; nn < N_NODES; nn += 32) {
        int s = rowptr[nn], e = rowptr[nn + 1];
        float a0 = 0.f, a1 = 0.f;
        for (int i = s; i < e; i++) {
            int c = cols[i]; float w_ = norms[i];
            a0 = fmaf(w_, As[c * 196 + lane], a0);
            a1 = fmaf(w_, As[c * 196 + 32 + lane], a1);
        }
        As[nn * 196 + 64 + lane] = a0;
        As[nn * 196 + 96 + lane] = a1;
    }
    __syncthreads();
    // Lhat pass 2: write k-columns [128,192)
    for (int nn = wid; nn < N_NODES; nn += 32) {
        int s = rowptr[nn], e = rowptr[nn + 1];
        float a0 = 0.f, a1 = 0.f;
        for (int i = s; i < e; i++) {
            int c = cols[i]; float w_ = norms[i];
            a0 = fmaf(w_, As[c * 196 + 64 + lane], a0);
            a1 = fmaf(w_, As[c * 196 + 96 + lane], a1);
        }
        As[nn * 196 + 128 + lane] = a0;
        As[nn * 196 + 160 + lane] = a1;
    }
    __syncthreads();

    // MMA combine: 28 warps = (14 m-tiles) x (2 n-halves); each warp NT=4, K=192
    if (wid < 28) {
        const int gid = lane >> 2, tig = lane & 3;
        const int mt = wid >> 1, nh = wid & 1;
        const int m0 = mt * 16;
        float acc[4][4];
        #pragma unroll
        for (int i = 0; i < 4; i++) { acc[i][0] = acc[i][1] = acc[i][2] = acc[i][3] = 0.f; }

        // kk in [0,8): z columns, tf32-exact -> hi only
        #pragma unroll
        for (int kk = 0; kk < 8; kk++) {
            const float* ap = As + (m0 + gid) * 196 + kk * 8 + tig;
            uint32_t hi[4] = { f2tf32v(ap[0]), f2tf32v(ap[8 * 196]),
                               f2tf32v(ap[4]), f2tf32v(ap[8 * 196 + 4]) };
            #pragma unroll
            for (int j = 0; j < 4; j++) {
                int nt = nh * 4 + j;
                const uint32_t* bp = Ws + (kk * 8 + tig) * 72 + nt * 8 + gid;
                uint32_t bf[2] = { bp[0], bp[4 * 72] };
                mma_tf32(acc[j], hi, bf);
            }
        }
        // kk in [8,24): t1/t2 columns -> hi + lo
        #pragma unroll 4
        for (int kk = 8; kk < 24; kk++) {
            const float* ap = As + (m0 + gid) * 196 + kk * 8 + tig;
            float af[4] = { ap[0], ap[8 * 196], ap[4], ap[8 * 196 + 4] };
            uint32_t hi[4], lo[4];
            #pragma unroll
            for (int e = 0; e < 4; e++) {
                hi[e] = f2tf32v(af[e]);
                lo[e] = f2tf32v(af[e] - __uint_as_float(hi[e]));
            }
            #pragma unroll
            for (int j = 0; j < 4; j++) {
                int nt = nh * 4 + j;
                const uint32_t* bp = Ws + (kk * 8 + tig) * 72 + nt * 8 + gid;
                uint32_t bf[2] = { bp[0], bp[4 * 72] };
                mma_tf32(acc[j], hi, bf);
                mma_tf32(acc[j], lo, bf);
            }
        }

        #pragma unroll
        for (int j = 0; j < 4; j++) {
            int g = (nh * 4 + j) * 8 + tig * 2;
            float b0 = bias[g], b1 = bias[g + 1];
            int n_lo = m0 + gid, n_hi = m0 + gid + 8;
            if (n_lo < N_NODES) {
                float v0 = roundtf(fmaxf(acc[j][0] + b0, 0.f));
                float v1 = roundtf(fmaxf(acc[j][1] + b1, 0.f));
                *(float2*)&out[base + (size_t)n_lo * 64 + g] = make_float2(v0, v1);
            }
            if (n_hi < N_NODES) {
                float v0 = roundtf(fmaxf(acc[j][2] + b0, 0.f));
                float v1 = roundtf(fmaxf(acc[j][3] + b1, 0.f));
                *(float2*)&out[base + (size_t)n_hi * 64 + g] = make_float2(v0, v1);
            }
        }
    }
}

// ---------------- BatchNorm over node channel (in-place, float4) ----------------
template<int C, bool RND>
__global__ void bn_kernel(float* __restrict__ x, const float* __restrict__ gamma,
                          const float* __restrict__ beta, int BT, int N)
{
    constexpr int C4 = C / 4;
    const int n   = blockIdx.x;
    const int tid = threadIdx.x;  // 256
    const int M4  = BT * C4;
    float4* x4 = (float4*)x;
    float s = 0.f, s2 = 0.f;
    for (int i = tid; i < M4; i += 256) {
        int bt = i / C4, c4 = i % C4;
        float4 v = x4[((size_t)bt * N + n) * C4 + c4];
        s  += v.x + v.y + v.z + v.w;
        s2 += v.x * v.x + v.y * v.y + v.z * v.z + v.w * v.w;
    }
    __shared__ float rs[256], rs2[256];
    __shared__ float mean_s, istd_s;
    rs[tid] = s; rs2[tid] = s2;
    __syncthreads();
    for (int o = 128; o > 0; o >>= 1) {
        if (tid < o) { rs[tid] += rs[tid + o]; rs2[tid] += rs2[tid + o]; }
        __syncthreads();
    }
    if (tid == 0) {
        float inv = 1.f / (float)(BT * C);
        float mean = rs[0] * inv;
        float var  = rs2[0] * inv - mean * mean;
        mean_s = mean;
        istd_s = rsqrtf(var + 1e-5f);
    }
    __syncthreads();
    const float gm = gamma[n], bt_ = beta[n];
    const float mean = mean_s, istd = istd_s;
    for (int i = tid; i < M4; i += 256) {
        int bt = i / C4, c4 = i % C4;
        size_t a = ((size_t)bt * N + n) * C4 + c4;
        float4 v = x4[a];
        v.x = (v.x - mean) * istd * gm + bt_;
        v.y = (v.y - mean) * istd * gm + bt_;
        v.z = (v.z - mean) * istd * gm + bt_;
        v.w = (v.w - mean) * istd * gm + bt_;
        if (RND) { v.x = roundtf(v.x); v.y = roundtf(v.y); v.z = roundtf(v.z); v.w = roundtf(v.w); }
        x4[a] = v;
    }
}

// ---------------- Fused BN(C=16) + FC: out = BN(x) @ fc_w + fc_b ----------------
// x: (BT, N, 16) read-only; out: (BT*N, 3). One block per node.
__global__ void bnfc_kernel(const float* __restrict__ x, const float* __restrict__ gamma,
                            const float* __restrict__ beta, const float* __restrict__ fw,
                            const float* __restrict__ fb, float* __restrict__ out,
                            int BT, int N)
{
    const int n   = blockIdx.x;
    const int tid = threadIdx.x;  // 256
    const int M4  = BT * 4;       // float4 count for C=16
    const float4* x4 = (const float4*)x;

    __shared__ float fws[48];
    __shared__ float fbs[3];
    if (tid < 48) fws[tid] = fw[tid];
    if (tid < 3)  fbs[tid] = fb[tid];

    float s = 0.f, s2 = 0.f;
    for (int i = tid; i < M4; i += 256) {
        int bt = i >> 2, c4 = i & 3;
        float4 v = x4[((size_t)bt * N + n) * 4 + c4];
        s  += v.x + v.y + v.z + v.w;
        s2 += v.x * v.x + v.y * v.y + v.z * v.z + v.w * v.w;
    }
    __shared__ float rs[256], rs2[256];
    __shared__ float mean_s, istd_s;
    rs[tid] = s; rs2[tid] = s2;
    __syncthreads();
    for (int o = 128; o > 0; o >>= 1) {
        if (tid < o) { rs[tid] += rs[tid + o]; rs2[tid] += rs2[tid + o]; }
        __syncthreads();
    }
    if (tid == 0) {
        float inv = 1.f / (float)(BT * 16);
        float mean = rs[0] * inv;
        float var  = rs2[0] * inv - mean * mean;
        mean_s = mean;
        istd_s = rsqrtf(var + 1e-5f);
    }
    __syncthreads();
    const float gm = gamma[n], bt_ = beta[n];
    const float mean = mean_s, istd = istd_s;

    for (int bt = tid; bt < BT; bt += 256) {
        const float4* row = &x4[((size_t)bt * N + n) * 4];
        float o0 = fbs[0], o1 = fbs[1], o2 = fbs[2];
        #pragma unroll
        for (int c4 = 0; c4 < 4; c4++) {
            float4 v = row[c4];
            float h0 = (v.x - mean) * istd * gm + bt_;
            float h1 = (v.y - mean) * istd * gm + bt_;
            float h2 = (v.z - mean) * istd * gm + bt_;
            float h3 = (v.w - mean) * istd * gm + bt_;
            int c = c4 * 4;
            o0 = fmaf(h0, fws[(c + 0) * 3 + 0], o0); o1 = fmaf(h0, fws[(c + 0) * 3 + 1], o1); o2 = fmaf(h0, fws[(c + 0) * 3 + 2], o2);
            o0 = fmaf(h1, fws[(c + 1) * 3 + 0], o0); o1 = fmaf(h1, fws[(c + 1) * 3 + 1], o1); o2 = fmaf(h1, fws[(c + 1) * 3 + 2], o2);
            o0 = fmaf(h2, fws[(c + 2) * 3 + 0], o0); o1 = fmaf(h2, fws[(c + 2) * 3 + 1], o1); o2 = fmaf(h2, fws[(c + 2) * 3 + 2], o2);
            o0 = fmaf(h3, fws[(c + 3) * 3 + 0], o0); o1 = fmaf(h3, fws[(c + 3) * 3 + 1], o1); o2 = fmaf(h3, fws[(c + 3) * 3 + 2], o2);
        }
        size_t r = (size_t)bt * N + n;
        out[r * 3 + 0] = o0;
        out[r * 3 + 1] = o1;
        out[r * 3 + 2] = o2;
    }
}

// ---------------- Launch ----------------
extern "C" void kernel_launch(void* const* d_in, const int* in_sizes, int n_in,
                              void* d_out, int out_size)
{
    const float* x        = (const float*)d_in[0];
    const int*   eidx     = (const int*)d_in[1];
    const float* eattr    = (const float*)d_in[2];
    const float* b1_t1_w  = (const float*)d_in[3];
    const float* b1_t1_b  = (const float*)d_in[4];
    const float* b1_ch_w  = (const float*)d_in[5];
    const float* b1_ch_b  = (const float*)d_in[6];
    const float* b1_t2_w  = (const float*)d_in[7];
    const float* b1_t2_b  = (const float*)d_in[8];
    const float* b1_bn_g  = (const float*)d_in[9];
    const float* b1_bn_b  = (const float*)d_in[10];
    const float* b2_t1_w  = (const float*)d_in[11];
    const float* b2_t1_b  = (const float*)d_in[12];
    const float* b2_ch_w  = (const float*)d_in[13];
    const float* b2_ch_b  = (const float*)d_in[14];
    const float* b2_t2_w  = (const float*)d_in[15];
    const float* b2_t2_b  = (const float*)d_in[16];
    const float* b2_bn_g  = (const float*)d_in[17];
    const float* b2_bn_b  = (const float*)d_in[18];
    const float* fc_w     = (const float*)d_in[19];
    const float* fc_b     = (const float*)d_in[20];

    float *bufA, *bufB, *bufC, *nrm;
    int *rowptr, *cols; uint32_t* wt;
    cudaGetSymbolAddress((void**)&bufA,  g_bufA);
    cudaGetSymbolAddress((void**)&bufB,  g_bufB);
    cudaGetSymbolAddress((void**)&bufC,  g_bufC);
    cudaGetSymbolAddress((void**)&rowptr, g_rowptr);
    cudaGetSymbolAddress((void**)&cols,  g_cols);
    cudaGetSymbolAddress((void**)&nrm,   g_norm);
    cudaGetSymbolAddress((void**)&wt,    g_wt);

    const int N = N_NODES;

    // instantiations:           Cin CINP Cout Kt Tin Tout TP NG KSUB CO  ACP  MINB
    auto k_b1t1 = tconv_mma<14, 16, 64, 9, 64, 56, 64, 4, 16, 32, false, 2>;  // 8 warps, 2 blk/SM
    auto k_b1t2 = tconv_mma<64, 64, 128, 9, 56, 48, 48, 4, 64, 32, true, 2>;  // 6 warps, 2 blk/SM
    auto k_b2t1 = tconv_mma<128, 128, 64, 5, 48, 44, 48, 6, 64, 32, true, 1>; // 9 warps, 1 blk/SM
    auto k_b2t2 = tconv_mma<64, 64, 16, 5, 44, 40, 48, 4, 64, 16, true, 2>;   // 6 warps, 2 blk/SM

    // smem bytes: (NG*XS*SA + 2*KSUB*SB) * 4
    const int sm_b1t1 = (4 * 72 * 20 + 2 * 16 * 104) * 4;    // 36,352
    const int sm_b1t2 = (4 * 56 * 68 + 2 * 64 * 104) * 4;    // 114,176
    const int sm_b2t1 = (6 * 52 * 132 + 2 * 64 * 104) * 4;   // 217,984
    const int sm_b2t2 = (4 * 52 * 68 + 2 * 64 * 56) * 4;     // 85,248
    const int sm_cheb = (224 * 196 + 192 * 72) * 4;          // 230,912

    cudaFuncSetAttribute(k_b1t1, cudaFuncAttributeMaxDynamicSharedMemorySize, sm_b1t1);
    cudaFuncSetAttribute(k_b1t2, cudaFuncAttributeMaxDynamicSharedMemorySize, sm_b1t2);
    cudaFuncSetAttribute(k_b2t1, cudaFuncAttributeMaxDynamicSharedMemorySize, sm_b2t1);
    cudaFuncSetAttribute(k_b2t2, cudaFuncAttributeMaxDynamicSharedMemorySize, sm_b2t2);
    cudaFuncSetAttribute(cheb_mma_kernel, cudaFuncAttributeMaxDynamicSharedMemorySize, sm_cheb);

    // ---- prep ----
    build_csr_kernel<<<1, 256>>>(eidx, eattr, rowptr, cols, nrm);
    wconv_kernel<<<(387072 + 255) / 256, 256>>>(b1_t1_w, b1_t2_w, b2_t1_w, b2_t2_w, wt);

    // ======== Block 1 ========
    k_b1t1<<<dim3(53, BATCH), 256, sm_b1t1>>>(x, wt + WOFF1, b1_t1_b, bufA);
    cheb_mma_kernel<<<32 * 56, 1024, sm_cheb>>>(bufA, b1_ch_w, b1_ch_b, bufB, rowptr, cols, nrm);
    k_b1t2<<<dim3(53, BATCH), 192, sm_b1t2>>>(bufB, wt + WOFF2, b1_t2_b, bufC);
    bn_kernel<128, true><<<N, 256>>>(bufC, b1_bn_g, b1_bn_b, 32 * 48, N);

    // ======== Block 2 ========
    k_b2t1<<<dim3(35, BATCH), 288, sm_b2t1>>>(bufC, wt + WOFF3, b2_t1_b, bufA);
    cheb_mma_kernel<<<32 * 44, 1024, sm_cheb>>>(bufA, b2_ch_w, b2_ch_b, bufB, rowptr, cols, nrm);
    k_b2t2<<<dim3(53, BATCH), 192, sm_b2t2>>>(bufB, wt + WOFF4, b2_t2_b, bufC);

    // ---- fused BN2 + FC ----
    bnfc_kernel<<<N, 256>>>(bufC, b2_bn_g, b2_bn_b, fc_w, fc_b, (float*)d_out, 32 * 40, N);

    (void)in_sizes; (void)n_in; (void)out_size;
}

// round 13
// speedup vs baseline: 1.5408x; 1.0283x over previous
#include <cuda_runtime.h>
#include <cuda_bf16.h>
#include <cstdint>

// ---------------- Problem constants ----------------
#define N_NODES 210
#define N_EDGES 4200
#define BATCH   32

// ---------------- Static device scratch ----------------
__device__ float    g_bufA[32ll * 56 * 210 * 64];   // 24.08M floats
__device__ float    g_bufB[32ll * 56 * 210 * 64];
__device__ float    g_bufC[32ll * 48 * 210 * 128];  // 41.29M floats
__device__ int      g_rowptr[N_NODES + 1];
__device__ int      g_cols[N_EDGES];
__device__ float    g_norm[N_EDGES];
__device__ uint32_t g_wt[387072];                   // tf32 tconv weights
__device__ uint32_t g_bp[2 * 13824];                // folded cheb W images (192x72) x2

// region offsets in g_wt
#define WOFF1 0        // b1_t1 padded (3,9,16,64)   = 27648
#define WOFF2 27648    // b1_t2        (3,9,64,128)  = 221184
#define WOFF3 248832   // b2_t1        (3,5,128,64)  = 122880
#define WOFF4 371712   // b2_t2        (3,5,64,16)   = 15360

// ---------------- helpers ----------------
__device__ __forceinline__ uint32_t f2tf32v(float x) {
    uint32_t r; asm("cvt.rna.tf32.f32 %0, %1;" : "=r"(r) : "f"(x)); return r;
}
__device__ __forceinline__ float roundtf(float x) {
    return __uint_as_float(f2tf32v(x));
}
__device__ __forceinline__ void mma_tf32(float c[4], const uint32_t a[4], const uint32_t b[2]) {
    asm volatile("mma.sync.aligned.m16n8k8.row.col.f32.tf32.tf32.f32 "
        "{%0,%1,%2,%3}, {%4,%5,%6,%7}, {%8,%9}, {%0,%1,%2,%3};"
        : "+f"(c[0]), "+f"(c[1]), "+f"(c[2]), "+f"(c[3])
        : "r"(a[0]), "r"(a[1]), "r"(a[2]), "r"(a[3]), "r"(b[0]), "r"(b[1]));
}
__device__ __forceinline__ uint32_t sptr(const void* p) {
    return (uint32_t)__cvta_generic_to_shared(p);
}
__device__ __forceinline__ void cpa16(uint32_t dst, const void* src, int sz) {
    asm volatile("cp.async.cg.shared.global [%0], [%1], 16, %2;"
                 :: "r"(dst), "l"(src), "r"(sz));
}
__device__ __forceinline__ void cpa_commit() { asm volatile("cp.async.commit_group;"); }
__device__ __forceinline__ void cpa_waitall() { asm volatile("cp.async.wait_group 0;"); }
__device__ __forceinline__ void cpa_wait1()  { asm volatile("cp.async.wait_group 1;"); }

// ---------------- Weight prepass: fp32 -> tf32 (padded for b1_t1) ----------------
__global__ void wconv_kernel(const float* __restrict__ w1, const float* __restrict__ w2,
                             const float* __restrict__ w3, const float* __restrict__ w4,
                             uint32_t* __restrict__ out)
{
    int i = blockIdx.x * blockDim.x + threadIdx.x;
    if (i < 27648) {  // b1_t1 padded: (g,k,ci<16,co<64); src (3,1,9,14,64)
        int co = i & 63; int r = i >> 6;
        int ci = r % 16; r /= 16;
        int k = r % 9;  int g = r / 9;
        float v = (ci < 14) ? w1[((g * 9 + k) * 14 + ci) * 64 + co] : 0.f;
        out[i] = f2tf32v(v);
        return;
    }
    int j = i - WOFF2;
    if (j >= 0 && j < 221184) { out[i] = f2tf32v(w2[j]); return; }
    j = i - WOFF3;
    if (j >= 0 && j < 122880) { out[i] = f2tf32v(w3[j]); return; }
    j = i - WOFF4;
    if (j >= 0 && j < 15360)  { out[i] = f2tf32v(w4[j]); return; }
}

// ---------------- Folded cheb W images: [W0-W2 ; W1 ; 2*W2] tf32, stride 72 ----------------
__global__ void bp_build_kernel(const float* __restrict__ W1, const float* __restrict__ W2)
{
    int i = blockIdx.x * blockDim.x + threadIdx.x;
    if (i >= 2 * 13824) return;
    int which = i / 13824, r = i % 13824;
    int row = r / 72, g = r % 72;
    int term = row >> 6, h = row & 63;
    const float* W = which ? W2 : W1;
    float v = 0.f;
    if (g < 64) {
        if (term == 0)      v = W[h * 64 + g] - W[2 * 4096 + h * 64 + g];
        else if (term == 1) v = W[4096 + h * 64 + g];
        else                v = 2.f * W[2 * 4096 + h * 64 + g];
    }
    g_bp[i] = f2tf32v(v);
}

// ---------------- CSR build (deterministic, 1 block) ----------------
__global__ void build_csr_kernel(const int* __restrict__ edge_index,
                                 const float* __restrict__ eattr,
                                 int* __restrict__ rowptr,
                                 int* __restrict__ cols,
                                 float* __restrict__ norms)
{
    __shared__ int   row_s[N_EDGES];
    __shared__ short col_s[N_EDGES];
    __shared__ float attr_s[N_EDGES];
    __shared__ int   cnt_s[N_NODES + 1];
    __shared__ float dis_s[N_NODES];

    const int tid = threadIdx.x;  // 256
    for (int i = tid; i < N_EDGES; i += 256) {
        row_s[i]  = edge_index[i];
        col_s[i]  = (short)edge_index[N_EDGES + i];
        attr_s[i] = eattr[i];
    }
    __syncthreads();

    if (tid < N_NODES) {
        float deg = 0.f; int cnt = 0;
        for (int e = 0; e < N_EDGES; e++) {
            if (row_s[e] == tid) { deg += attr_s[e]; cnt++; }
        }
        cnt_s[tid] = cnt;
        dis_s[tid] = (deg > 0.f) ? rsqrtf(deg) : 0.f;
    }
    __syncthreads();
    if (tid == 0) {
        int acc = 0;
        for (int n = 0; n < N_NODES; n++) { int c = cnt_s[n]; cnt_s[n] = acc; acc += c; }
        cnt_s[N_NODES] = acc;
    }
    __syncthreads();
    if (tid <= N_NODES) rowptr[tid] = cnt_s[tid];
    if (tid < N_NODES) {
        int wpos = cnt_s[tid];
        const float disr = dis_s[tid];
        for (int e = 0; e < N_EDGES; e++) {
            if (row_s[e] == tid) {
                int c = col_s[e];
                cols[wpos]  = c;
                norms[wpos] = -disr * attr_s[e] * dis_s[c];
                wpos++;
            }
        }
    }
}

// ---------------- Gated temporal conv via tf32 mma.sync ----------------
// 2 m-tiles per warp: B fragments reused across both -> smem bytes/mma halved.
template<int Cin, int CINP, int Cout, int Kt, int Tin, int Tout, int TP, int NG,
         int KSUB, int CO, bool ACP, int MINB>
__global__ void __launch_bounds__((NG * (TP / 16) / 2) * 32, MINB)
tconv_mma(const float* __restrict__ x, const uint32_t* __restrict__ wt,
          const float* __restrict__ bias, float* __restrict__ out)
{
    constexpr int MTN   = TP / 16;         // m-tiles per node
    constexpr int TILES = NG * MTN;
    constexpr int NW    = TILES / 2;       // warps (2 tiles per warp)
    constexpr int THREADS = NW * 32;
    constexpr int XS    = TP + Kt - 1;
    constexpr int SA    = CINP + 4;
    constexpr int COLS  = 3 * CO;
    constexpr int SB    = COLS + 8;
    constexpr int NT    = COLS / 8;
    constexpr int COCH  = Cout / CO;
    constexpr int NKS   = CINP / KSUB;
    constexpr int KPI   = Kt * NKS;
    constexpr int ITERS = COCH * KPI;
    constexpr int BUFSZ = KSUB * SB;
    constexpr int CO4   = CO / 4;
    static_assert(TILES % 2 == 0, "even tiles");

    extern __shared__ uint32_t sh[];
    uint32_t* As = sh;                  // NG*XS*SA
    uint32_t* Bs = sh + NG * XS * SA;   // 2*BUFSZ

    const int n0  = blockIdx.x * NG;
    const int b   = blockIdx.y;
    const int tid = threadIdx.x;
    const int wid = tid >> 5, lane = tid & 31;
    const int gid = lane >> 2, tig = lane & 3;

    const int tile0 = 2 * wid, tile1 = 2 * wid + 1;
    const int nl[2]  = { tile0 / MTN, tile1 / MTN };
    const int t0s[2] = { (tile0 % MTN) * 16, (tile1 % MTN) * 16 };

    // ---- stage A slab ----
    if (ACP) {
        constexpr int C4 = CINP / 4;
        for (int i = tid; i < NG * XS * C4; i += THREADS) {
            int nlx = i / (XS * C4);
            int r   = i % (XS * C4);
            int tp = r / C4, c4 = r % C4;
            int nn = n0 + nlx;
            bool ok = (nn < N_NODES) && (tp < Tin);
            const float* src = x + ((size_t)(b * Tin + (ok ? tp : 0)) * N_NODES
                                    + (nn < N_NODES ? nn : 0)) * Cin + c4 * 4;
            cpa16(sptr(As + nlx * XS * SA + tp * SA + c4 * 4), src, ok ? 16 : 0);
        }
    } else {
        for (int i = tid; i < NG * XS * CINP; i += THREADS) {
            int nlx = i / (XS * CINP);
            int r   = i % (XS * CINP);
            int tp = r / CINP, ci = r % CINP;
            int nn = n0 + nlx;
            float v = 0.f;
            if (nn < N_NODES && tp < Tin && ci < Cin)
                v = x[((size_t)(b * Tin + tp) * N_NODES + nn) * Cin + ci];
            As[nlx * XS * SA + tp * SA + ci] = f2tf32v(v);
        }
    }

    // ---- B stage (cp.async) ----
    auto stageB = [&](int it) {
        int cc = it / KPI, r = it % KPI, k = r / NKS, ks = r % NKS;
        uint32_t* Bb = Bs + (it & 1) * BUFSZ;
        for (int i = tid; i < KSUB * 3 * CO4; i += THREADS) {
            int cil = i / (3 * CO4);
            int rr  = i % (3 * CO4);
            int g   = rr / CO4, c4 = rr % CO4;
            const uint32_t* src = wt + ((size_t)(g * Kt + k) * CINP + ks * KSUB + cil) * Cout
                                     + cc * CO + c4 * 4;
            cpa16(sptr(Bb + cil * SB + g * CO + c4 * 4), src, 16);
        }
    };

    stageB(0);
    cpa_commit();

    const uint32_t* A0 = As + nl[0] * XS * SA;
    const uint32_t* A1 = As + nl[1] * XS * SA;

    float acc[2][NT][4];
    #pragma unroll
    for (int m = 0; m < 2; m++)
        #pragma unroll
        for (int i = 0; i < NT; i++) { acc[m][i][0] = acc[m][i][1] = acc[m][i][2] = acc[m][i][3] = 0.f; }

    #pragma unroll 1
    for (int it = 0; it < ITERS; ++it) {
        cpa_waitall();
        __syncthreads();
        if (it + 1 < ITERS) { stageB(it + 1); cpa_commit(); }

        const int r = it % KPI, k = r / NKS, ks = r % NKS;
        const uint32_t* Bb = Bs + (it & 1) * BUFSZ;
        #pragma unroll
        for (int kk = 0; kk < KSUB / 8; kk++) {
            uint32_t a0[4], a1[4];
            {
                const uint32_t* ap = A0 + (t0s[0] + gid + k) * SA + ks * KSUB + kk * 8 + tig;
                a0[0] = ap[0]; a0[1] = ap[8 * SA]; a0[2] = ap[4]; a0[3] = ap[8 * SA + 4];
            }
            {
                const uint32_t* ap = A1 + (t0s[1] + gid + k) * SA + ks * KSUB + kk * 8 + tig;
                a1[0] = ap[0]; a1[1] = ap[8 * SA]; a1[2] = ap[4]; a1[3] = ap[8 * SA + 4];
            }
            #pragma unroll
            for (int nt = 0; nt < NT; nt++) {
                const uint32_t* bp = Bb + (kk * 8 + tig) * SB + nt * 8 + gid;
                uint32_t bf[2] = { bp[0], bp[4 * SB] };
                mma_tf32(acc[0][nt], a0, bf);
                mma_tf32(acc[1][nt], a1, bf);
            }
        }

        if ((it + 1) % KPI == 0) {
            const int cc = it / KPI;
            #pragma unroll
            for (int m = 0; m < 2; m++) {
                const int n = n0 + nl[m];
                if (n < N_NODES) {
                    #pragma unroll
                    for (int nt3 = 0; nt3 < NT / 3; nt3++) {
                        int co = cc * CO + nt3 * 8 + tig * 2;
                        float bP0 = bias[co],            bP1 = bias[co + 1];
                        float bQ0 = bias[Cout + co],     bQ1 = bias[Cout + co + 1];
                        float bR0 = bias[2 * Cout + co], bR1 = bias[2 * Cout + co + 1];
                        #pragma unroll
                        for (int half = 0; half < 2; half++) {
                            int t = t0s[m] + gid + half * 8;
                            if (t < Tout) {
                                int i0 = half * 2;
                                float P0 = acc[m][nt3][i0] + bP0;
                                float P1 = acc[m][nt3][i0 + 1] + bP1;
                                float Q0 = acc[m][nt3 + NT / 3][i0] + bQ0;
                                float Q1 = acc[m][nt3 + NT / 3][i0 + 1] + bQ1;
                                float R0 = acc[m][nt3 + 2 * NT / 3][i0] + bR0;
                                float R1 = acc[m][nt3 + 2 * NT / 3][i0 + 1] + bR1;
                                float v0 = fmaxf(fmaf(P0, 1.f / (1.f + __expf(-Q0)), R0), 0.f);
                                float v1 = fmaxf(fmaf(P1, 1.f / (1.f + __expf(-Q1)), R1), 0.f);
                                *(float2*)&out[((size_t)(b * Tout + t) * N_NODES + n) * Cout + co] =
                                    make_float2(v0, v1);
                            }
                        }
                    }
                }
            }
            #pragma unroll
            for (int m = 0; m < 2; m++)
                #pragma unroll
                for (int i = 0; i < NT; i++) { acc[m][i][0] = acc[m][i][1] = acc[m][i][2] = acc[m][i][3] = 0.f; }
        }
    }
}

// ---------------- Fused Chebyshev with tf32 MMA combine (1024 thr) ----------------
// A (smem) = [t0 | Lz | L(Lz)] per node: 224(pad) x 192 fp32, stride 196
// B (smem) = precomputed folded W image (192x72 tf32), cp.async overlapped with Lhat.
// Staging groups: z (group0, needed before Lhat) then W (group1, needed before combine).
__global__ void __launch_bounds__(1024, 1)
cheb_mma_kernel(const float* __restrict__ zin, const uint32_t* __restrict__ bpimg,
                const float* __restrict__ bias, float* __restrict__ out,
                const int* __restrict__ rowptr, const int* __restrict__ cols,
                const float* __restrict__ norms)
{
    extern __shared__ float fs[];
    float* As = fs;                                   // 224*196
    uint32_t* Ws = (uint32_t*)(fs + 224 * 196);       // 192*72

    const int bt  = blockIdx.x;
    const int tid = threadIdx.x;
    const size_t base = (size_t)bt * N_NODES * 64;

    // group 0: z into k-columns [0,64)
    for (int i = tid; i < N_NODES * 16; i += 1024) {
        int n = i >> 4, c4 = i & 15;
        cpa16(sptr(As + n * 196 + c4 * 4), zin + base + (size_t)n * 64 + c4 * 4, 16);
    }
    cpa_commit();
    // group 1: W image (55 KB) — overlaps the Lhat passes
    for (int i = tid; i < 3456; i += 1024)
        cpa16(sptr(Ws + i * 4), bpimg + i * 4, 16);
    cpa_commit();
    // zero pad rows (STS, concurrent with cp.async)
    for (int i = tid; i < 14 * 196; i += 1024)
        As[(210 + i / 196) * 196 + (i % 196)] = 0.f;

    cpa_wait1();          // z resident (W may still be in flight)
    __syncthreads();

    const int wid = tid >> 5, lane = tid & 31;
    // Lhat pass 1: write k-columns [64,128). One node per warp, ILP-2 over halves.
    for (int nn = wid; nn < N_NODES; nn += 32) {
        int s = rowptr[nn], e = rowptr[nn + 1];
        float a0 = 0.f, a1 = 0.f;
        for (int i = s; i < e; i++) {
            int c = cols[i]; float w_ = norms[i];
            a0 = fmaf(w_, As[c * 196 + lane], a0);
            a1 = fmaf(w_, As[c * 196 + 32 + lane], a1);
        }
        As[nn * 196 + 64 + lane] = a0;
        As[nn * 196 + 96 + lane] = a1;
    }
    __syncthreads();
    // Lhat pass 2: write k-columns [128,192)
    for (int nn = wid; nn < N_NODES; nn += 32) {
        int s = rowptr[nn], e = rowptr[nn + 1];
        float a0 = 0.f, a1 = 0.f;
        for (int i = s; i < e; i++) {
            int c = cols[i]; float w_ = norms[i];
            a0 = fmaf(w_, As[c * 196 + 64 + lane], a0);
            a1 = fmaf(w_, As[c * 196 + 96 + lane], a1);
        }
        As[nn * 196 + 128 + lane] = a0;
        As[nn * 196 + 160 + lane] = a1;
    }
    cpa_waitall();        // W image resident
    __syncthreads();

    // MMA combine: 28 warps = (14 m-tiles) x (2 n-halves); each warp NT=4, K=192
    if (wid < 28) {
        const int gid = lane >> 2, tig = lane & 3;
        const int mt = wid >> 1, nh = wid & 1;
        const int m0 = mt * 16;
        float acc[4][4];
        #pragma unroll
        for (int i = 0; i < 4; i++) { acc[i][0] = acc[i][1] = acc[i][2] = acc[i][3] = 0.f; }

        // kk in [0,8): z columns, tf32-exact -> hi only
        #pragma unroll
        for (int kk = 0; kk < 8; kk++) {
            const float* ap = As + (m0 + gid) * 196 + kk * 8 + tig;
            uint32_t hi[4] = { f2tf32v(ap[0]), f2tf32v(ap[8 * 196]),
                               f2tf32v(ap[4]), f2tf32v(ap[8 * 196 + 4]) };
            #pragma unroll
            for (int j = 0; j < 4; j++) {
                int nt = nh * 4 + j;
                const uint32_t* bp = Ws + (kk * 8 + tig) * 72 + nt * 8 + gid;
                uint32_t bf[2] = { bp[0], bp[4 * 72] };
                mma_tf32(acc[j], hi, bf);
            }
        }
        // kk in [8,24): t1/t2 columns -> hi + lo
        #pragma unroll 4
        for (int kk = 8; kk < 24; kk++) {
            const float* ap = As + (m0 + gid) * 196 + kk * 8 + tig;
            float af[4] = { ap[0], ap[8 * 196], ap[4], ap[8 * 196 + 4] };
            uint32_t hi[4], lo[4];
            #pragma unroll
            for (int e = 0; e < 4; e++) {
                hi[e] = f2tf32v(af[e]);
                lo[e] = f2tf32v(af[e] - __uint_as_float(hi[e]));
            }
            #pragma unroll
            for (int j = 0; j < 4; j++) {
                int nt = nh * 4 + j;
                const uint32_t* bp = Ws + (kk * 8 + tig) * 72 + nt * 8 + gid;
                uint32_t bf[2] = { bp[0], bp[4 * 72] };
                mma_tf32(acc[j], hi, bf);
                mma_tf32(acc[j], lo, bf);
            }
        }

        #pragma unroll
        for (int j = 0; j < 4; j++) {
            int g = (nh * 4 + j) * 8 + tig * 2;
            float b0 = bias[g], b1 = bias[g + 1];
            int n_lo = m0 + gid, n_hi = m0 + gid + 8;
            if (n_lo < N_NODES) {
                float v0 = roundtf(fmaxf(acc[j][0] + b0, 0.f));
                float v1 = roundtf(fmaxf(acc[j][1] + b1, 0.f));
                *(float2*)&out[base + (size_t)n_lo * 64 + g] = make_float2(v0, v1);
            }
            if (n_hi < N_NODES) {
                float v0 = roundtf(fmaxf(acc[j][2] + b0, 0.f));
                float v1 = roundtf(fmaxf(acc[j][3] + b1, 0.f));
                *(float2*)&out[base + (size_t)n_hi * 64 + g] = make_float2(v0, v1);
            }
        }
    }
}

// ---------------- BatchNorm over node channel (in-place, float4) ----------------
template<int C, bool RND>
__global__ void bn_kernel(float* __restrict__ x, const float* __restrict__ gamma,
                          const float* __restrict__ beta, int BT, int N)
{
    constexpr int C4 = C / 4;
    const int n   = blockIdx.x;
    const int tid = threadIdx.x;  // 256
    const int M4  = BT * C4;
    float4* x4 = (float4*)x;
    float s = 0.f, s2 = 0.f;
    for (int i = tid; i < M4; i += 256) {
        int bt = i / C4, c4 = i % C4;
        float4 v = x4[((size_t)bt * N + n) * C4 + c4];
        s  += v.x + v.y + v.z + v.w;
        s2 += v.x * v.x + v.y * v.y + v.z * v.z + v.w * v.w;
    }
    __shared__ float rs[256], rs2[256];
    __shared__ float mean_s, istd_s;
    rs[tid] = s; rs2[tid] = s2;
    __syncthreads();
    for (int o = 128; o > 0; o >>= 1) {
        if (tid < o) { rs[tid] += rs[tid + o]; rs2[tid] += rs2[tid + o]; }
        __syncthreads();
    }
    if (tid == 0) {
        float inv = 1.f / (float)(BT * C);
        float mean = rs[0] * inv;
        float var  = rs2[0] * inv - mean * mean;
        mean_s = mean;
        istd_s = rsqrtf(var + 1e-5f);
    }
    __syncthreads();
    const float gm = gamma[n], bt_ = beta[n];
    const float mean = mean_s, istd = istd_s;
    for (int i = tid; i < M4; i += 256) {
        int bt = i / C4, c4 = i % C4;
        size_t a = ((size_t)bt * N + n) * C4 + c4;
        float4 v = x4[a];
        v.x = (v.x - mean) * istd * gm + bt_;
        v.y = (v.y - mean) * istd * gm + bt_;
        v.z = (v.z - mean) * istd * gm + bt_;
        v.w = (v.w - mean) * istd * gm + bt_;
        if (RND) { v.x = roundtf(v.x); v.y = roundtf(v.y); v.z = roundtf(v.z); v.w = roundtf(v.w); }
        x4[a] = v;
    }
}

// ---------------- Fused BN(C=16) + FC: out = BN(x) @ fc_w + fc_b ----------------
__global__ void bnfc_kernel(const float* __restrict__ x, const float* __restrict__ gamma,
                            const float* __restrict__ beta, const float* __restrict__ fw,
                            const float* __restrict__ fb, float* __restrict__ out,
                            int BT, int N)
{
    const int n   = blockIdx.x;
    const int tid = threadIdx.x;  // 256
    const int M4  = BT * 4;       // float4 count for C=16
    const float4* x4 = (const float4*)x;

    __shared__ float fws[48];
    __shared__ float fbs[3];
    if (tid < 48) fws[tid] = fw[tid];
    if (tid < 3)  fbs[tid] = fb[tid];

    float s = 0.f, s2 = 0.f;
    for (int i = tid; i < M4; i += 256) {
        int bt = i >> 2, c4 = i & 3;
        float4 v = x4[((size_t)bt * N + n) * 4 + c4];
        s  += v.x + v.y + v.z + v.w;
        s2 += v.x * v.x + v.y * v.y + v.z * v.z + v.w * v.w;
    }
    __shared__ float rs[256], rs2[256];
    __shared__ float mean_s, istd_s;
    rs[tid] = s; rs2[tid] = s2;
    __syncthreads();
    for (int o = 128; o > 0; o >>= 1) {
        if (tid < o) { rs[tid] += rs[tid + o]; rs2[tid] += rs2[tid + o]; }
        __syncthreads();
    }
    if (tid == 0) {
        float inv = 1.f / (float)(BT * 16);
        float mean = rs[0] * inv;
        float var  = rs2[0] * inv - mean * mean;
        mean_s = mean;
        istd_s = rsqrtf(var + 1e-5f);
    }
    __syncthreads();
    const float gm = gamma[n], bt_ = beta[n];
    const float mean = mean_s, istd = istd_s;

    for (int bt = tid; bt < BT; bt += 256) {
        const float4* row = &x4[((size_t)bt * N + n) * 4];
        float o0 = fbs[0], o1 = fbs[1], o2 = fbs[2];
        #pragma unroll
        for (int c4 = 0; c4 < 4; c4++) {
            float4 v = row[c4];
            float h0 = (v.x - mean) * istd * gm + bt_;
            float h1 = (v.y - mean) * istd * gm + bt_;
            float h2 = (v.z - mean) * istd * gm + bt_;
            float h3 = (v.w - mean) * istd * gm + bt_;
            int c = c4 * 4;
            o0 = fmaf(h0, fws[(c + 0) * 3 + 0], o0); o1 = fmaf(h0, fws[(c + 0) * 3 + 1], o1); o2 = fmaf(h0, fws[(c + 0) * 3 + 2], o2);
            o0 = fmaf(h1, fws[(c + 1) * 3 + 0], o0); o1 = fmaf(h1, fws[(c + 1) * 3 + 1], o1); o2 = fmaf(h1, fws[(c + 1) * 3 + 2], o2);
            o0 = fmaf(h2, fws[(c + 2) * 3 + 0], o0); o1 = fmaf(h2, fws[(c + 2) * 3 + 1], o1); o2 = fmaf(h2, fws[(c + 2) * 3 + 2], o2);
            o0 = fmaf(h3, fws[(c + 3) * 3 + 0], o0); o1 = fmaf(h3, fws[(c + 3) * 3 + 1], o1); o2 = fmaf(h3, fws[(c + 3) * 3 + 2], o2);
        }
        size_t r = (size_t)bt * N + n;
        out[r * 3 + 0] = o0;
        out[r * 3 + 1] = o1;
        out[r * 3 + 2] = o2;
    }
}

// ---------------- Launch ----------------
extern "C" void kernel_launch(void* const* d_in, const int* in_sizes, int n_in,
                              void* d_out, int out_size)
{
    const float* x        = (const float*)d_in[0];
    const int*   eidx     = (const int*)d_in[1];
    const float* eattr    = (const float*)d_in[2];
    const float* b1_t1_w  = (const float*)d_in[3];
    const float* b1_t1_b  = (const float*)d_in[4];
    const float* b1_ch_w  = (const float*)d_in[5];
    const float* b1_ch_b  = (const float*)d_in[6];
    const float* b1_t2_w  = (const float*)d_in[7];
    const float* b1_t2_b  = (const float*)d_in[8];
    const float* b1_bn_g  = (const float*)d_in[9];
    const float* b1_bn_b  = (const float*)d_in[10];
    const float* b2_t1_w  = (const float*)d_in[11];
    const float* b2_t1_b  = (const float*)d_in[12];
    const float* b2_ch_w  = (const float*)d_in[13];
    const float* b2_ch_b  = (const float*)d_in[14];
    const float* b2_t2_w  = (const float*)d_in[15];
    const float* b2_t2_b  = (const float*)d_in[16];
    const float* b2_bn_g  = (const float*)d_in[17];
    const float* b2_bn_b  = (const float*)d_in[18];
    const float* fc_w     = (const float*)d_in[19];
    const float* fc_b     = (const float*)d_in[20];

    float *bufA, *bufB, *bufC, *nrm;
    int *rowptr, *cols; uint32_t *wt, *bp;
    cudaGetSymbolAddress((void**)&bufA,  g_bufA);
    cudaGetSymbolAddress((void**)&bufB,  g_bufB);
    cudaGetSymbolAddress((void**)&bufC,  g_bufC);
    cudaGetSymbolAddress((void**)&rowptr, g_rowptr);
    cudaGetSymbolAddress((void**)&cols,  g_cols);
    cudaGetSymbolAddress((void**)&nrm,   g_norm);
    cudaGetSymbolAddress((void**)&wt,    g_wt);
    cudaGetSymbolAddress((void**)&bp,    g_bp);

    const int N = N_NODES;

    // instantiations:           Cin CINP Cout Kt Tin Tout TP NG KSUB CO  ACP  MINB
    auto k_b1t1 = tconv_mma<14, 16, 64, 9, 64, 56, 64, 4, 16, 32, false, 2>;  // 8 warps, 2 blk/SM
    auto k_b1t2 = tconv_mma<64, 64, 128, 9, 56, 48, 48, 4, 64, 32, true, 2>;  // 6 warps, 2 blk/SM
    auto k_b2t1 = tconv_mma<128, 128, 64, 5, 48, 44, 48, 6, 64, 32, true, 1>; // 9 warps, 1 blk/SM
    auto k_b2t2 = tconv_mma<64, 64, 16, 5, 44, 40, 48, 4, 64, 16, true, 2>;   // 6 warps, 2 blk/SM

    // smem bytes: (NG*XS*SA + 2*KSUB*SB) * 4
    const int sm_b1t1 = (4 * 72 * 20 + 2 * 16 * 104) * 4;    // 36,352
    const int sm_b1t2 = (4 * 56 * 68 + 2 * 64 * 104) * 4;    // 114,176
    const int sm_b2t1 = (6 * 52 * 132 + 2 * 64 * 104) * 4;   // 217,984
    const int sm_b2t2 = (4 * 52 * 68 + 2 * 64 * 56) * 4;     // 85,248
    const int sm_cheb = (224 * 196 + 192 * 72) * 4;          // 230,912

    cudaFuncSetAttribute(k_b1t1, cudaFuncAttributeMaxDynamicSharedMemorySize, sm_b1t1);
    cudaFuncSetAttribute(k_b1t2, cudaFuncAttributeMaxDynamicSharedMemorySize, sm_b1t2);
    cudaFuncSetAttribute(k_b2t1, cudaFuncAttributeMaxDynamicSharedMemorySize, sm_b2t1);
    cudaFuncSetAttribute(k_b2t2, cudaFuncAttributeMaxDynamicSharedMemorySize, sm_b2t2);
    cudaFuncSetAttribute(cheb_mma_kernel, cudaFuncAttributeMaxDynamicSharedMemorySize, sm_cheb);

    // ---- prep ----
    build_csr_kernel<<<1, 256>>>(eidx, eattr, rowptr, cols, nrm);
    wconv_kernel<<<(387072 + 255) / 256, 256>>>(b1_t1_w, b1_t2_w, b2_t1_w, b2_t2_w, wt);
    bp_build_kernel<<<(2 * 13824 + 255) / 256, 256>>>(b1_ch_w, b2_ch_w);

    // ======== Block 1 ========
    k_b1t1<<<dim3(53, BATCH), 256, sm_b1t1>>>(x, wt + WOFF1, b1_t1_b, bufA);
    cheb_mma_kernel<<<32 * 56, 1024, sm_cheb>>>(bufA, bp, b1_ch_b, bufB, rowptr, cols, nrm);
    k_b1t2<<<dim3(53, BATCH), 192, sm_b1t2>>>(bufB, wt + WOFF2, b1_t2_b, bufC);
    bn_kernel<128, true><<<N, 256>>>(bufC, b1_bn_g, b1_bn_b, 32 * 48, N);

    // ======== Block 2 ========
    k_b2t1<<<dim3(35, BATCH), 288, sm_b2t1>>>(bufC, wt + WOFF3, b2_t1_b, bufA);
    cheb_mma_kernel<<<32 * 44, 1024, sm_cheb>>>(bufA, bp + 13824, b2_ch_b, bufB, rowptr, cols, nrm);
    k_b2t2<<<dim3(53, BATCH), 192, sm_b2t2>>>(bufB, wt + WOFF4, b2_t2_b, bufC);

    // ---- fused BN2 + FC ----
    bnfc_kernel<<<N, 256>>>(bufC, b2_bn_g, b2_bn_b, fc_w, fc_b, (float*)d_out, 32 * 40, N);

    (void)in_sizes; (void)n_in; (void)out_size;
}

// round 14
// speedup vs baseline: 1.5411x; 1.0002x over previous
#include <cuda_runtime.h>
#include <cuda_bf16.h>
#include <cstdint>

// ---------------- Problem constants ----------------
#define N_NODES 210
#define N_EDGES 4200
#define BATCH   32

// ---------------- Static device scratch ----------------
__device__ float    g_bufA[32ll * 56 * 210 * 64];   // 24.08M floats
__device__ float    g_bufB[32ll * 56 * 210 * 64];
__device__ float    g_bufC[32ll * 48 * 210 * 128];  // 41.29M floats
__device__ float    g_xpad[32ll * 64 * 210 * 16];   // padded tf32-rounded input (6.88M)
__device__ int      g_rowptr[N_NODES + 1];
__device__ int      g_cols[N_EDGES];
__device__ float    g_norm[N_EDGES];
__device__ uint32_t g_wt[387072];                   // tf32 tconv weights
__device__ uint32_t g_bp[2 * 13824];                // folded cheb W images (192x72) x2

// region offsets in g_wt
#define WOFF1 0        // b1_t1 padded (3,9,16,64)   = 27648
#define WOFF2 27648    // b1_t2        (3,9,64,128)  = 221184
#define WOFF3 248832   // b2_t1        (3,5,128,64)  = 122880
#define WOFF4 371712   // b2_t2        (3,5,64,16)   = 15360

// ---------------- helpers ----------------
__device__ __forceinline__ uint32_t f2tf32v(float x) {
    uint32_t r; asm("cvt.rna.tf32.f32 %0, %1;" : "=r"(r) : "f"(x)); return r;
}
__device__ __forceinline__ float roundtf(float x) {
    return __uint_as_float(f2tf32v(x));
}
__device__ __forceinline__ void mma_tf32(float c[4], const uint32_t a[4], const uint32_t b[2]) {
    asm volatile("mma.sync.aligned.m16n8k8.row.col.f32.tf32.tf32.f32 "
        "{%0,%1,%2,%3}, {%4,%5,%6,%7}, {%8,%9}, {%0,%1,%2,%3};"
        : "+f"(c[0]), "+f"(c[1]), "+f"(c[2]), "+f"(c[3])
        : "r"(a[0]), "r"(a[1]), "r"(a[2]), "r"(a[3]), "r"(b[0]), "r"(b[1]));
}
__device__ __forceinline__ uint32_t sptr(const void* p) {
    return (uint32_t)__cvta_generic_to_shared(p);
}
__device__ __forceinline__ void cpa16(uint32_t dst, const void* src, int sz) {
    asm volatile("cp.async.cg.shared.global [%0], [%1], 16, %2;"
                 :: "r"(dst), "l"(src), "r"(sz));
}
__device__ __forceinline__ void cpa_commit() { asm volatile("cp.async.commit_group;"); }
__device__ __forceinline__ void cpa_waitall() { asm volatile("cp.async.wait_group 0;"); }
__device__ __forceinline__ void cpa_wait1()  { asm volatile("cp.async.wait_group 1;"); }

// ---------------- Input pad prepass: x (B,64,210,14) -> xpad (B,64,210,16) tf32 ----------------
__global__ void xpad_kernel(const float* __restrict__ x)
{
    int i = blockIdx.x * blockDim.x + threadIdx.x;
    if (i >= 32 * 64 * 210 * 16) return;
    int c = i & 15;
    int r = i >> 4;          // (b*64+t)*210+n
    float v = (c < 14) ? roundtf(x[(size_t)r * 14 + c]) : 0.f;
    g_xpad[i] = v;
}

// ---------------- Weight prepass: fp32 -> tf32 (padded for b1_t1) ----------------
__global__ void wconv_kernel(const float* __restrict__ w1, const float* __restrict__ w2,
                             const float* __restrict__ w3, const float* __restrict__ w4,
                             uint32_t* __restrict__ out)
{
    int i = blockIdx.x * blockDim.x + threadIdx.x;
    if (i < 27648) {  // b1_t1 padded: (g,k,ci<16,co<64); src (3,1,9,14,64)
        int co = i & 63; int r = i >> 6;
        int ci = r % 16; r /= 16;
        int k = r % 9;  int g = r / 9;
        float v = (ci < 14) ? w1[((g * 9 + k) * 14 + ci) * 64 + co] : 0.f;
        out[i] = f2tf32v(v);
        return;
    }
    int j = i - WOFF2;
    if (j >= 0 && j < 221184) { out[i] = f2tf32v(w2[j]); return; }
    j = i - WOFF3;
    if (j >= 0 && j < 122880) { out[i] = f2tf32v(w3[j]); return; }
    j = i - WOFF4;
    if (j >= 0 && j < 15360)  { out[i] = f2tf32v(w4[j]); return; }
}

// ---------------- Folded cheb W images: [W0-W2 ; W1 ; 2*W2] tf32, stride 72 ----------------
__global__ void bp_build_kernel(const float* __restrict__ W1, const float* __restrict__ W2)
{
    int i = blockIdx.x * blockDim.x + threadIdx.x;
    if (i >= 2 * 13824) return;
    int which = i / 13824, r = i % 13824;
    int row = r / 72, g = r % 72;
    int term = row >> 6, h = row & 63;
    const float* W = which ? W2 : W1;
    float v = 0.f;
    if (g < 64) {
        if (term == 0)      v = W[h * 64 + g] - W[2 * 4096 + h * 64 + g];
        else if (term == 1) v = W[4096 + h * 64 + g];
        else                v = 2.f * W[2 * 4096 + h * 64 + g];
    }
    g_bp[i] = f2tf32v(v);
}

// ---------------- CSR build (deterministic, 1 block) ----------------
__global__ void build_csr_kernel(const int* __restrict__ edge_index,
                                 const float* __restrict__ eattr,
                                 int* __restrict__ rowptr,
                                 int* __restrict__ cols,
                                 float* __restrict__ norms)
{
    __shared__ int   row_s[N_EDGES];
    __shared__ short col_s[N_EDGES];
    __shared__ float attr_s[N_EDGES];
    __shared__ int   cnt_s[N_NODES + 1];
    __shared__ float dis_s[N_NODES];

    const int tid = threadIdx.x;  // 256
    for (int i = tid; i < N_EDGES; i += 256) {
        row_s[i]  = edge_index[i];
        col_s[i]  = (short)edge_index[N_EDGES + i];
        attr_s[i] = eattr[i];
    }
    __syncthreads();

    if (tid < N_NODES) {
        float deg = 0.f; int cnt = 0;
        for (int e = 0; e < N_EDGES; e++) {
            if (row_s[e] == tid) { deg += attr_s[e]; cnt++; }
        }
        cnt_s[tid] = cnt;
        dis_s[tid] = (deg > 0.f) ? rsqrtf(deg) : 0.f;
    }
    __syncthreads();
    if (tid == 0) {
        int acc = 0;
        for (int n = 0; n < N_NODES; n++) { int c = cnt_s[n]; cnt_s[n] = acc; acc += c; }
        cnt_s[N_NODES] = acc;
    }
    __syncthreads();
    if (tid <= N_NODES) rowptr[tid] = cnt_s[tid];
    if (tid < N_NODES) {
        int wpos = cnt_s[tid];
        const float disr = dis_s[tid];
        for (int e = 0; e < N_EDGES; e++) {
            if (row_s[e] == tid) {
                int c = col_s[e];
                cols[wpos]  = c;
                norms[wpos] = -disr * attr_s[e] * dis_s[c];
                wpos++;
            }
        }
    }
}

// ---------------- Gated temporal conv via tf32 mma.sync ----------------
// 2 m-tiles per warp: B fragments reused across both -> smem bytes/mma halved.
template<int Cin, int CINP, int Cout, int Kt, int Tin, int Tout, int TP, int NG,
         int KSUB, int CO, bool ACP, int MINB>
__global__ void __launch_bounds__((NG * (TP / 16) / 2) * 32, MINB)
tconv_mma(const float* __restrict__ x, const uint32_t* __restrict__ wt,
          const float* __restrict__ bias, float* __restrict__ out)
{
    constexpr int MTN   = TP / 16;         // m-tiles per node
    constexpr int TILES = NG * MTN;
    constexpr int NW    = TILES / 2;       // warps (2 tiles per warp)
    constexpr int THREADS = NW * 32;
    constexpr int XS    = TP + Kt - 1;
    constexpr int SA    = CINP + 4;
    constexpr int COLS  = 3 * CO;
    constexpr int SB    = COLS + 8;
    constexpr int NT    = COLS / 8;
    constexpr int COCH  = Cout / CO;
    constexpr int NKS   = CINP / KSUB;
    constexpr int KPI   = Kt * NKS;
    constexpr int ITERS = COCH * KPI;
    constexpr int BUFSZ = KSUB * SB;
    constexpr int CO4   = CO / 4;
    static_assert(TILES % 2 == 0, "even tiles");

    extern __shared__ uint32_t sh[];
    uint32_t* As = sh;                  // NG*XS*SA
    uint32_t* Bs = sh + NG * XS * SA;   // 2*BUFSZ

    const int n0  = blockIdx.x * NG;
    const int b   = blockIdx.y;
    const int tid = threadIdx.x;
    const int wid = tid >> 5, lane = tid & 31;
    const int gid = lane >> 2, tig = lane & 3;

    const int tile0 = 2 * wid, tile1 = 2 * wid + 1;
    const int nl[2]  = { tile0 / MTN, tile1 / MTN };
    const int t0s[2] = { (tile0 % MTN) * 16, (tile1 % MTN) * 16 };

    // ---- stage A slab ----
    if (ACP) {
        constexpr int C4 = CINP / 4;
        for (int i = tid; i < NG * XS * C4; i += THREADS) {
            int nlx = i / (XS * C4);
            int r   = i % (XS * C4);
            int tp = r / C4, c4 = r % C4;
            int nn = n0 + nlx;
            bool ok = (nn < N_NODES) && (tp < Tin);
            const float* src = x + ((size_t)(b * Tin + (ok ? tp : 0)) * N_NODES
                                    + (nn < N_NODES ? nn : 0)) * Cin + c4 * 4;
            cpa16(sptr(As + nlx * XS * SA + tp * SA + c4 * 4), src, ok ? 16 : 0);
        }
    } else {
        for (int i = tid; i < NG * XS * CINP; i += THREADS) {
            int nlx = i / (XS * CINP);
            int r   = i % (XS * CINP);
            int tp = r / CINP, ci = r % CINP;
            int nn = n0 + nlx;
            float v = 0.f;
            if (nn < N_NODES && tp < Tin && ci < Cin)
                v = x[((size_t)(b * Tin + tp) * N_NODES + nn) * Cin + ci];
            As[nlx * XS * SA + tp * SA + ci] = f2tf32v(v);
        }
    }

    // ---- B stage (cp.async) ----
    auto stageB = [&](int it) {
        int cc = it / KPI, r = it % KPI, k = r / NKS, ks = r % NKS;
        uint32_t* Bb = Bs + (it & 1) * BUFSZ;
        for (int i = tid; i < KSUB * 3 * CO4; i += THREADS) {
            int cil = i / (3 * CO4);
            int rr  = i % (3 * CO4);
            int g   = rr / CO4, c4 = rr % CO4;
            const uint32_t* src = wt + ((size_t)(g * Kt + k) * CINP + ks * KSUB + cil) * Cout
                                     + cc * CO + c4 * 4;
            cpa16(sptr(Bb + cil * SB + g * CO + c4 * 4), src, 16);
        }
    };

    stageB(0);
    cpa_commit();

    const uint32_t* A0 = As + nl[0] * XS * SA;
    const uint32_t* A1 = As + nl[1] * XS * SA;

    float acc[2][NT][4];
    #pragma unroll
    for (int m = 0; m < 2; m++)
        #pragma unroll
        for (int i = 0; i < NT; i++) { acc[m][i][0] = acc[m][i][1] = acc[m][i][2] = acc[m][i][3] = 0.f; }

    #pragma unroll 1
    for (int it = 0; it < ITERS; ++it) {
        cpa_waitall();
        __syncthreads();
        if (it + 1 < ITERS) { stageB(it + 1); cpa_commit(); }

        const int r = it % KPI, k = r / NKS, ks = r % NKS;
        const uint32_t* Bb = Bs + (it & 1) * BUFSZ;
        #pragma unroll
        for (int kk = 0; kk < KSUB / 8; kk++) {
            uint32_t a0[4], a1[4];
            {
                const uint32_t* ap = A0 + (t0s[0] + gid + k) * SA + ks * KSUB + kk * 8 + tig;
                a0[0] = ap[0]; a0[1] = ap[8 * SA]; a0[2] = ap[4]; a0[3] = ap[8 * SA + 4];
            }
            {
                const uint32_t* ap = A1 + (t0s[1] + gid + k) * SA + ks * KSUB + kk * 8 + tig;
                a1[0] = ap[0]; a1[1] = ap[8 * SA]; a1[2] = ap[4]; a1[3] = ap[8 * SA + 4];
            }
            #pragma unroll
            for (int nt = 0; nt < NT; nt++) {
                const uint32_t* bp = Bb + (kk * 8 + tig) * SB + nt * 8 + gid;
                uint32_t bf[2] = { bp[0], bp[4 * SB] };
                mma_tf32(acc[0][nt], a0, bf);
                mma_tf32(acc[1][nt], a1, bf);
            }
        }

        if ((it + 1) % KPI == 0) {
            const int cc = it / KPI;
            #pragma unroll
            for (int m = 0; m < 2; m++) {
                const int n = n0 + nl[m];
                if (n < N_NODES) {
                    #pragma unroll
                    for (int nt3 = 0; nt3 < NT / 3; nt3++) {
                        int co = cc * CO + nt3 * 8 + tig * 2;
                        float bP0 = bias[co],            bP1 = bias[co + 1];
                        float bQ0 = bias[Cout + co],     bQ1 = bias[Cout + co + 1];
                        float bR0 = bias[2 * Cout + co], bR1 = bias[2 * Cout + co + 1];
                        #pragma unroll
                        for (int half = 0; half < 2; half++) {
                            int t = t0s[m] + gid + half * 8;
                            if (t < Tout) {
                                int i0 = half * 2;
                                float P0 = acc[m][nt3][i0] + bP0;
                                float P1 = acc[m][nt3][i0 + 1] + bP1;
                                float Q0 = acc[m][nt3 + NT / 3][i0] + bQ0;
                                float Q1 = acc[m][nt3 + NT / 3][i0 + 1] + bQ1;
                                float R0 = acc[m][nt3 + 2 * NT / 3][i0] + bR0;
                                float R1 = acc[m][nt3 + 2 * NT / 3][i0 + 1] + bR1;
                                float v0 = fmaxf(fmaf(P0, 1.f / (1.f + __expf(-Q0)), R0), 0.f);
                                float v1 = fmaxf(fmaf(P1, 1.f / (1.f + __expf(-Q1)), R1), 0.f);
                                *(float2*)&out[((size_t)(b * Tout + t) * N_NODES + n) * Cout + co] =
                                    make_float2(v0, v1);
                            }
                        }
                    }
                }
            }
            #pragma unroll
            for (int m = 0; m < 2; m++)
                #pragma unroll
                for (int i = 0; i < NT; i++) { acc[m][i][0] = acc[m][i][1] = acc[m][i][2] = acc[m][i][3] = 0.f; }
        }
    }
}

// ---------------- Fused Chebyshev with tf32 MMA combine (1024 thr) ----------------
// A (smem) = [t0 | Lz | L(Lz)] per node: 224(pad) x 192 fp32, stride 196
// B (smem) = precomputed folded W image (192x72 tf32), cp.async overlapped with Lhat.
__global__ void __launch_bounds__(1024, 1)
cheb_mma_kernel(const float* __restrict__ zin, const uint32_t* __restrict__ bpimg,
                const float* __restrict__ bias, float* __restrict__ out,
                const int* __restrict__ rowptr, const int* __restrict__ cols,
                const float* __restrict__ norms)
{
    extern __shared__ float fs[];
    float* As = fs;                                   // 224*196
    uint32_t* Ws = (uint32_t*)(fs + 224 * 196);       // 192*72

    const int bt  = blockIdx.x;
    const int tid = threadIdx.x;
    const size_t base = (size_t)bt * N_NODES * 64;

    // group 0: z into k-columns [0,64)
    for (int i = tid; i < N_NODES * 16; i += 1024) {
        int n = i >> 4, c4 = i & 15;
        cpa16(sptr(As + n * 196 + c4 * 4), zin + base + (size_t)n * 64 + c4 * 4, 16);
    }
    cpa_commit();
    // group 1: W image (55 KB) — overlaps the Lhat passes
    for (int i = tid; i < 3456; i += 1024)
        cpa16(sptr(Ws + i * 4), bpimg + i * 4, 16);
    cpa_commit();
    // zero pad rows (STS, concurrent with cp.async)
    for (int i = tid; i < 14 * 196; i += 1024)
        As[(210 + i / 196) * 196 + (i % 196)] = 0.f;

    cpa_wait1();          // z resident (W may still be in flight)
    __syncthreads();

    const int wid = tid >> 5, lane = tid & 31;
    // Lhat pass 1: write k-columns [64,128). One node per warp, ILP-2 over halves.
    for (int nn = wid; nn < N_NODES; nn += 32) {
        int s = rowptr[nn], e = rowptr[nn + 1];
        float a0 = 0.f, a1 = 0.f;
        for (int i = s; i < e; i++) {
            int c = cols[i]; float w_ = norms[i];
            a0 = fmaf(w_, As[c * 196 + lane], a0);
            a1 = fmaf(w_, As[c * 196 + 32 + lane], a1);
        }
        As[nn * 196 + 64 + lane] = a0;
        As[nn * 196 + 96 + lane] = a1;
    }
    __syncthreads();
    // Lhat pass 2: write k-columns [128,192)
    for (int nn = wid; nn < N_NODES; nn += 32) {
        int s = rowptr[nn], e = rowptr[nn + 1];
        float a0 = 0.f, a1 = 0.f;
        for (int i = s; i < e; i++) {
            int c = cols[i]; float w_ = norms[i];
            a0 = fmaf(w_, As[c * 196 + 64 + lane], a0);
            a1 = fmaf(w_, As[c * 196 + 96 + lane], a1);
        }
        As[nn * 196 + 128 + lane] = a0;
        As[nn * 196 + 160 + lane] = a1;
    }
    cpa_waitall();        // W image resident
    __syncthreads();

    // MMA combine: 28 warps = (14 m-tiles) x (2 n-halves); each warp NT=4, K=192
    if (wid < 28) {
        const int gid = lane >> 2, tig = lane & 3;
        const int mt = wid >> 1, nh = wid & 1;
        const int m0 = mt * 16;
        float acc[4][4];
        #pragma unroll
        for (int i = 0; i < 4; i++) { acc[i][0] = acc[i][1] = acc[i][2] = acc[i][3] = 0.f; }

        // kk in [0,8): z columns, tf32-exact -> hi only
        #pragma unroll
        for (int kk = 0; kk < 8; kk++) {
            const float* ap = As + (m0 + gid) * 196 + kk * 8 + tig;
            uint32_t hi[4] = { f2tf32v(ap[0]), f2tf32v(ap[8 * 196]),
                               f2tf32v(ap[4]), f2tf32v(ap[8 * 196 + 4]) };
            #pragma unroll
            for (int j = 0; j < 4; j++) {
                int nt = nh * 4 + j;
                const uint32_t* bp = Ws + (kk * 8 + tig) * 72 + nt * 8 + gid;
                uint32_t bf[2] = { bp[0], bp[4 * 72] };
                mma_tf32(acc[j], hi, bf);
            }
        }
        // kk in [8,24): t1/t2 columns -> hi + lo
        #pragma unroll 4
        for (int kk = 8; kk < 24; kk++) {
            const float* ap = As + (m0 + gid) * 196 + kk * 8 + tig;
            float af[4] = { ap[0], ap[8 * 196], ap[4], ap[8 * 196 + 4] };
            uint32_t hi[4], lo[4];
            #pragma unroll
            for (int e = 0; e < 4; e++) {
                hi[e] = f2tf32v(af[e]);
                lo[e] = f2tf32v(af[e] - __uint_as_float(hi[e]));
            }
            #pragma unroll
            for (int j = 0; j < 4; j++) {
                int nt = nh * 4 + j;
                const uint32_t* bp = Ws + (kk * 8 + tig) * 72 + nt * 8 + gid;
                uint32_t bf[2] = { bp[0], bp[4 * 72] };
                mma_tf32(acc[j], hi, bf);
                mma_tf32(acc[j], lo, bf);
            }
        }

        #pragma unroll
        for (int j = 0; j < 4; j++) {
            int g = (nh * 4 + j) * 8 + tig * 2;
            float b0 = bias[g], b1 = bias[g + 1];
            int n_lo = m0 + gid, n_hi = m0 + gid + 8;
            if (n_lo < N_NODES) {
                float v0 = roundtf(fmaxf(acc[j][0] + b0, 0.f));
                float v1 = roundtf(fmaxf(acc[j][1] + b1, 0.f));
                *(float2*)&out[base + (size_t)n_lo * 64 + g] = make_float2(v0, v1);
            }
            if (n_hi < N_NODES) {
                float v0 = roundtf(fmaxf(acc[j][2] + b0, 0.f));
                float v1 = roundtf(fmaxf(acc[j][3] + b1, 0.f));
                *(float2*)&out[base + (size_t)n_hi * 64 + g] = make_float2(v0, v1);
            }
        }
    }
}

// ---------------- BatchNorm over node channel (in-place, float4) ----------------
template<int C, bool RND>
__global__ void bn_kernel(float* __restrict__ x, const float* __restrict__ gamma,
                          const float* __restrict__ beta, int BT, int N)
{
    constexpr int C4 = C / 4;
    const int n   = blockIdx.x;
    const int tid = threadIdx.x;  // 256
    const int M4  = BT * C4;
    float4* x4 = (float4*)x;
    float s = 0.f, s2 = 0.f;
    for (int i = tid; i < M4; i += 256) {
        int bt = i / C4, c4 = i % C4;
        float4 v = x4[((size_t)bt * N + n) * C4 + c4];
        s  += v.x + v.y + v.z + v.w;
        s2 += v.x * v.x + v.y * v.y + v.z * v.z + v.w * v.w;
    }
    __shared__ float rs[256], rs2[256];
    __shared__ float mean_s, istd_s;
    rs[tid] = s; rs2[tid] = s2;
    __syncthreads();
    for (int o = 128; o > 0; o >>= 1) {
        if (tid < o) { rs[tid] += rs[tid + o]; rs2[tid] += rs2[tid + o]; }
        __syncthreads();
    }
    if (tid == 0) {
        float inv = 1.f / (float)(BT * C);
        float mean = rs[0] * inv;
        float var  = rs2[0] * inv - mean * mean;
        mean_s = mean;
        istd_s = rsqrtf(var + 1e-5f);
    }
    __syncthreads();
    const float gm = gamma[n], bt_ = beta[n];
    const float mean = mean_s, istd = istd_s;
    for (int i = tid; i < M4; i += 256) {
        int bt = i / C4, c4 = i % C4;
        size_t a = ((size_t)bt * N + n) * C4 + c4;
        float4 v = x4[a];
        v.x = (v.x - mean) * istd * gm + bt_;
        v.y = (v.y - mean) * istd * gm + bt_;
        v.z = (v.z - mean) * istd * gm + bt_;
        v.w = (v.w - mean) * istd * gm + bt_;
        if (RND) { v.x = roundtf(v.x); v.y = roundtf(v.y); v.z = roundtf(v.z); v.w = roundtf(v.w); }
        x4[a] = v;
    }
}

// ---------------- Fused BN(C=16) + FC: out = BN(x) @ fc_w + fc_b ----------------
__global__ void bnfc_kernel(const float* __restrict__ x, const float* __restrict__ gamma,
                            const float* __restrict__ beta, const float* __restrict__ fw,
                            const float* __restrict__ fb, float* __restrict__ out,
                            int BT, int N)
{
    const int n   = blockIdx.x;
    const int tid = threadIdx.x;  // 256
    const int M4  = BT * 4;       // float4 count for C=16
    const float4* x4 = (const float4*)x;

    __shared__ float fws[48];
    __shared__ float fbs[3];
    if (tid < 48) fws[tid] = fw[tid];
    if (tid < 3)  fbs[tid] = fb[tid];

    float s = 0.f, s2 = 0.f;
    for (int i = tid; i < M4; i += 256) {
        int bt = i >> 2, c4 = i & 3;
        float4 v = x4[((size_t)bt * N + n) * 4 + c4];
        s  += v.x + v.y + v.z + v.w;
        s2 += v.x * v.x + v.y * v.y + v.z * v.z + v.w * v.w;
    }
    __shared__ float rs[256], rs2[256];
    __shared__ float mean_s, istd_s;
    rs[tid] = s; rs2[tid] = s2;
    __syncthreads();
    for (int o = 128; o > 0; o >>= 1) {
        if (tid < o) { rs[tid] += rs[tid + o]; rs2[tid] += rs2[tid + o]; }
        __syncthreads();
    }
    if (tid == 0) {
        float inv = 1.f / (float)(BT * 16);
        float mean = rs[0] * inv;
        float var  = rs2[0] * inv - mean * mean;
        mean_s = mean;
        istd_s = rsqrtf(var + 1e-5f);
    }
    __syncthreads();
    const float gm = gamma[n], bt_ = beta[n];
    const float mean = mean_s, istd = istd_s;

    for (int bt = tid; bt < BT; bt += 256) {
        const float4* row = &x4[((size_t)bt * N + n) * 4];
        float o0 = fbs[0], o1 = fbs[1], o2 = fbs[2];
        #pragma unroll
        for (int c4 = 0; c4 < 4; c4++) {
            float4 v = row[c4];
            float h0 = (v.x - mean) * istd * gm + bt_;
            float h1 = (v.y - mean) * istd * gm + bt_;
            float h2 = (v.z - mean) * istd * gm + bt_;
            float h3 = (v.w - mean) * istd * gm + bt_;
            int c = c4 * 4;
            o0 = fmaf(h0, fws[(c + 0) * 3 + 0], o0); o1 = fmaf(h0, fws[(c + 0) * 3 + 1], o1); o2 = fmaf(h0, fws[(c + 0) * 3 + 2], o2);
            o0 = fmaf(h1, fws[(c + 1) * 3 + 0], o0); o1 = fmaf(h1, fws[(c + 1) * 3 + 1], o1); o2 = fmaf(h1, fws[(c + 1) * 3 + 2], o2);
            o0 = fmaf(h2, fws[(c + 2) * 3 + 0], o0); o1 = fmaf(h2, fws[(c + 2) * 3 + 1], o1); o2 = fmaf(h2, fws[(c + 2) * 3 + 2], o2);
            o0 = fmaf(h3, fws[(c + 3) * 3 + 0], o0); o1 = fmaf(h3, fws[(c + 3) * 3 + 1], o1); o2 = fmaf(h3, fws[(c + 3) * 3 + 2], o2);
        }
        size_t r = (size_t)bt * N + n;
        out[r * 3 + 0] = o0;
        out[r * 3 + 1] = o1;
        out[r * 3 + 2] = o2;
    }
}

// ---------------- Launch ----------------
extern "C" void kernel_launch(void* const* d_in, const int* in_sizes, int n_in,
                              void* d_out, int out_size)
{
    const float* x        = (const float*)d_in[0];
    const int*   eidx     = (const int*)d_in[1];
    const float* eattr    = (const float*)d_in[2];
    const float* b1_t1_w  = (const float*)d_in[3];
    const float* b1_t1_b  = (const float*)d_in[4];
    const float* b1_ch_w  = (const float*)d_in[5];
    const float* b1_ch_b  = (const float*)d_in[6];
    const float* b1_t2_w  = (const float*)d_in[7];
    const float* b1_t2_b  = (const float*)d_in[8];
    const float* b1_bn_g  = (const float*)d_in[9];
    const float* b1_bn_b  = (const float*)d_in[10];
    const float* b2_t1_w  = (const float*)d_in[11];
    const float* b2_t1_b  = (const float*)d_in[12];
    const float* b2_ch_w  = (const float*)d_in[13];
    const float* b2_ch_b  = (const float*)d_in[14];
    const float* b2_t2_w  = (const float*)d_in[15];
    const float* b2_t2_b  = (const float*)d_in[16];
    const float* b2_bn_g  = (const float*)d_in[17];
    const float* b2_bn_b  = (const float*)d_in[18];
    const float* fc_w     = (const float*)d_in[19];
    const float* fc_b     = (const float*)d_in[20];

    float *bufA, *bufB, *bufC, *nrm, *xpad;
    int *rowptr, *cols; uint32_t *wt, *bp;
    cudaGetSymbolAddress((void**)&bufA,  g_bufA);
    cudaGetSymbolAddress((void**)&bufB,  g_bufB);
    cudaGetSymbolAddress((void**)&bufC,  g_bufC);
    cudaGetSymbolAddress((void**)&xpad,  g_xpad);
    cudaGetSymbolAddress((void**)&rowptr, g_rowptr);
    cudaGetSymbolAddress((void**)&cols,  g_cols);
    cudaGetSymbolAddress((void**)&nrm,   g_norm);
    cudaGetSymbolAddress((void**)&wt,    g_wt);
    cudaGetSymbolAddress((void**)&bp,    g_bp);

    const int N = N_NODES;

    // instantiations:           Cin CINP Cout Kt Tin Tout TP NG KSUB CO  ACP  MINB
    auto k_b1t1 = tconv_mma<16, 16, 64, 9, 64, 56, 64, 4, 16, 32, true, 2>;   // 8 warps, 2 blk/SM
    auto k_b1t2 = tconv_mma<64, 64, 128, 9, 56, 48, 48, 4, 64, 32, true, 2>;  // 6 warps, 2 blk/SM
    auto k_b2t1 = tconv_mma<128, 128, 64, 5, 48, 44, 48, 6, 64, 32, true, 1>; // 9 warps, 1 blk/SM
    auto k_b2t2 = tconv_mma<64, 64, 16, 5, 44, 40, 48, 4, 64, 16, true, 2>;   // 6 warps, 2 blk/SM

    // smem bytes: (NG*XS*SA + 2*KSUB*SB) * 4
    const int sm_b1t1 = (4 * 72 * 20 + 2 * 16 * 104) * 4;    // 36,352
    const int sm_b1t2 = (4 * 56 * 68 + 2 * 64 * 104) * 4;    // 114,176
    const int sm_b2t1 = (6 * 52 * 132 + 2 * 64 * 104) * 4;   // 217,984
    const int sm_b2t2 = (4 * 52 * 68 + 2 * 64 * 56) * 4;     // 85,248
    const int sm_cheb = (224 * 196 + 192 * 72) * 4;          // 230,912

    cudaFuncSetAttribute(k_b1t1, cudaFuncAttributeMaxDynamicSharedMemorySize, sm_b1t1);
    cudaFuncSetAttribute(k_b1t2, cudaFuncAttributeMaxDynamicSharedMemorySize, sm_b1t2);
    cudaFuncSetAttribute(k_b2t1, cudaFuncAttributeMaxDynamicSharedMemorySize, sm_b2t1);
    cudaFuncSetAttribute(k_b2t2, cudaFuncAttributeMaxDynamicSharedMemorySize, sm_b2t2);
    cudaFuncSetAttribute(cheb_mma_kernel, cudaFuncAttributeMaxDynamicSharedMemorySize, sm_cheb);

    // ---- prep ----
    build_csr_kernel<<<1, 256>>>(eidx, eattr, rowptr, cols, nrm);
    wconv_kernel<<<(387072 + 255) / 256, 256>>>(b1_t1_w, b1_t2_w, b2_t1_w, b2_t2_w, wt);
    bp_build_kernel<<<(2 * 13824 + 255) / 256, 256>>>(b1_ch_w, b2_ch_w);
    xpad_kernel<<<(32 * 64 * 210 * 16 + 255) / 256, 256>>>(x);

    // ======== Block 1 ========
    k_b1t1<<<dim3(53, BATCH), 256, sm_b1t1>>>(xpad, wt + WOFF1, b1_t1_b, bufA);
    cheb_mma_kernel<<<32 * 56, 1024, sm_cheb>>>(bufA, bp, b1_ch_b, bufB, rowptr, cols, nrm);
    k_b1t2<<<dim3(53, BATCH), 192, sm_b1t2>>>(bufB, wt + WOFF2, b1_t2_b, bufC);
    bn_kernel<128, true><<<N, 256>>>(bufC, b1_bn_g, b1_bn_b, 32 * 48, N);

    // ======== Block 2 ========
    k_b2t1<<<dim3(35, BATCH), 288, sm_b2t1>>>(bufC, wt + WOFF3, b2_t1_b, bufA);
    cheb_mma_kernel<<<32 * 44, 1024, sm_cheb>>>(bufA, bp + 13824, b2_ch_b, bufB, rowptr, cols, nrm);
    k_b2t2<<<dim3(53, BATCH), 192, sm_b2t2>>>(bufB, wt + WOFF4, b2_t2_b, bufC);

    // ---- fused BN2 + FC ----
    bnfc_kernel<<<N, 256>>>(bufC, b2_bn_g, b2_bn_b, fc_w, fc_b, (float*)d_out, 32 * 40, N);

    (void)in_sizes; (void)n_in; (void)out_size;
}

// round 15
// speedup vs baseline: 1.6118x; 1.0459x over previous
#include <cuda_runtime.h>
#include <cuda_bf16.h>
#include <cstdint>

// ---------------- Problem constants ----------------
#define N_NODES 210
#define N_EDGES 4200
#define BATCH   32

// ---------------- Static device scratch ----------------
__device__ float    g_bufA[32ll * 56 * 210 * 64];   // 24.08M floats
__device__ float    g_bufB[32ll * 56 * 210 * 64];
__device__ float    g_bufC[32ll * 48 * 210 * 128];  // 41.29M floats
__device__ float    g_xpad[32ll * 64 * 210 * 16];   // padded tf32-rounded input (6.88M)
__device__ int      g_rowptr[N_NODES + 1];
__device__ int      g_cols[N_EDGES];
__device__ float    g_norm[N_EDGES];
__device__ uint32_t g_wt[387072];                   // tf32 tconv weights
__device__ uint32_t g_bp[2 * 13824];                // folded cheb W images (192x72) x2

// region offsets in g_wt
#define WOFF1 0        // b1_t1 padded (3,9,16,64)   = 27648
#define WOFF2 27648    // b1_t2        (3,9,64,128)  = 221184
#define WOFF3 248832   // b2_t1        (3,5,128,64)  = 122880
#define WOFF4 371712   // b2_t2        (3,5,64,16)   = 15360

// ---------------- helpers ----------------
__device__ __forceinline__ uint32_t f2tf32v(float x) {
    uint32_t r; asm("cvt.rna.tf32.f32 %0, %1;" : "=r"(r) : "f"(x)); return r;
}
__device__ __forceinline__ float roundtf(float x) {
    return __uint_as_float(f2tf32v(x));
}
__device__ __forceinline__ void mma_tf32(float c[4], const uint32_t a[4], const uint32_t b[2]) {
    asm volatile("mma.sync.aligned.m16n8k8.row.col.f32.tf32.tf32.f32 "
        "{%0,%1,%2,%3}, {%4,%5,%6,%7}, {%8,%9}, {%0,%1,%2,%3};"
        : "+f"(c[0]), "+f"(c[1]), "+f"(c[2]), "+f"(c[3])
        : "r"(a[0]), "r"(a[1]), "r"(a[2]), "r"(a[3]), "r"(b[0]), "r"(b[1]));
}
__device__ __forceinline__ uint32_t sptr(const void* p) {
    return (uint32_t)__cvta_generic_to_shared(p);
}
__device__ __forceinline__ void cpa16(uint32_t dst, const void* src, int sz) {
    asm volatile("cp.async.cg.shared.global [%0], [%1], 16, %2;"
                 :: "r"(dst), "l"(src), "r"(sz));
}
__device__ __forceinline__ void cpa_commit() { asm volatile("cp.async.commit_group;"); }
__device__ __forceinline__ void cpa_waitall() { asm volatile("cp.async.wait_group 0;"); }
__device__ __forceinline__ void cpa_wait1()  { asm volatile("cp.async.wait_group 1;"); }

// ---------------- Input pad prepass: x (B,64,210,14) -> xpad (B,64,210,16) tf32 ----------------
__global__ void xpad_kernel(const float* __restrict__ x)
{
    int i = blockIdx.x * blockDim.x + threadIdx.x;
    if (i >= 32 * 64 * 210 * 16) return;
    int c = i & 15;
    int r = i >> 4;          // (b*64+t)*210+n
    float v = (c < 14) ? roundtf(x[(size_t)r * 14 + c]) : 0.f;
    g_xpad[i] = v;
}

// ---------------- Weight prepass: fp32 -> tf32 (padded for b1_t1) ----------------
__global__ void wconv_kernel(const float* __restrict__ w1, const float* __restrict__ w2,
                             const float* __restrict__ w3, const float* __restrict__ w4,
                             uint32_t* __restrict__ out)
{
    int i = blockIdx.x * blockDim.x + threadIdx.x;
    if (i < 27648) {  // b1_t1 padded: (g,k,ci<16,co<64); src (3,1,9,14,64)
        int co = i & 63; int r = i >> 6;
        int ci = r % 16; r /= 16;
        int k = r % 9;  int g = r / 9;
        float v = (ci < 14) ? w1[((g * 9 + k) * 14 + ci) * 64 + co] : 0.f;
        out[i] = f2tf32v(v);
        return;
    }
    int j = i - WOFF2;
    if (j >= 0 && j < 221184) { out[i] = f2tf32v(w2[j]); return; }
    j = i - WOFF3;
    if (j >= 0 && j < 122880) { out[i] = f2tf32v(w3[j]); return; }
    j = i - WOFF4;
    if (j >= 0 && j < 15360)  { out[i] = f2tf32v(w4[j]); return; }
}

// ---------------- Folded cheb W images: [W0-W2 ; W1 ; 2*W2] tf32, stride 72 ----------------
__global__ void bp_build_kernel(const float* __restrict__ W1, const float* __restrict__ W2)
{
    int i = blockIdx.x * blockDim.x + threadIdx.x;
    if (i >= 2 * 13824) return;
    int which = i / 13824, r = i % 13824;
    int row = r / 72, g = r % 72;
    int term = row >> 6, h = row & 63;
    const float* W = which ? W2 : W1;
    float v = 0.f;
    if (g < 64) {
        if (term == 0)      v = W[h * 64 + g] - W[2 * 4096 + h * 64 + g];
        else if (term == 1) v = W[4096 + h * 64 + g];
        else                v = 2.f * W[2 * 4096 + h * 64 + g];
    }
    g_bp[i] = f2tf32v(v);
}

// ---------------- CSR build (deterministic, 1 block) ----------------
__global__ void build_csr_kernel(const int* __restrict__ edge_index,
                                 const float* __restrict__ eattr,
                                 int* __restrict__ rowptr,
                                 int* __restrict__ cols,
                                 float* __restrict__ norms)
{
    __shared__ int   row_s[N_EDGES];
    __shared__ short col_s[N_EDGES];
    __shared__ float attr_s[N_EDGES];
    __shared__ int   cnt_s[N_NODES + 1];
    __shared__ float dis_s[N_NODES];

    const int tid = threadIdx.x;  // 256
    for (int i = tid; i < N_EDGES; i += 256) {
        row_s[i]  = edge_index[i];
        col_s[i]  = (short)edge_index[N_EDGES + i];
        attr_s[i] = eattr[i];
    }
    __syncthreads();

    if (tid < N_NODES) {
        float deg = 0.f; int cnt = 0;
        for (int e = 0; e < N_EDGES; e++) {
            if (row_s[e] == tid) { deg += attr_s[e]; cnt++; }
        }
        cnt_s[tid] = cnt;
        dis_s[tid] = (deg > 0.f) ? rsqrtf(deg) : 0.f;
    }
    __syncthreads();
    if (tid == 0) {
        int acc = 0;
        for (int n = 0; n < N_NODES; n++) { int c = cnt_s[n]; cnt_s[n] = acc; acc += c; }
        cnt_s[N_NODES] = acc;
    }
    __syncthreads();
    if (tid <= N_NODES) rowptr[tid] = cnt_s[tid];
    if (tid < N_NODES) {
        int wpos = cnt_s[tid];
        const float disr = dis_s[tid];
        for (int e = 0; e < N_EDGES; e++) {
            if (row_s[e] == tid) {
                int c = col_s[e];
                cols[wpos]  = c;
                norms[wpos] = -disr * attr_s[e] * dis_s[c];
                wpos++;
            }
        }
    }
}

// ---------------- b1_t1 dedicated kernel: all weights smem-resident, 2 stages ----------------
// x = xpad (B,64,210,16) tf32-rounded; wt layout (3,9,16,64); out (B,56,210,64)
__global__ void __launch_bounds__(256, 2)
t1conv_kernel(const float* __restrict__ x, const uint32_t* __restrict__ wt,
              const float* __restrict__ bias, float* __restrict__ out)
{
    // NG=4 nodes, TP=64, XS=72, SA=20, CO=32 (2 halves), COLS=96, SB=104, NT=12
    extern __shared__ uint32_t sh[];
    uint32_t* As = sh;            // 4*72*20 = 5760
    uint32_t* Bs = sh + 5760;     // 144*104 = 14976

    const int n0  = blockIdx.x * 4;
    const int b   = blockIdx.y;
    const int tid = threadIdx.x;
    const int wid = tid >> 5, lane = tid & 31;
    const int gid = lane >> 2, tig = lane & 3;

    const int tile0 = 2 * wid, tile1 = 2 * wid + 1;
    const int nl0 = tile0 >> 2, nl1 = tile1 >> 2;
    const int t00 = (tile0 & 3) * 16, t01 = (tile1 & 3) * 16;

    // stage A slab (cp.async from xpad)
    for (int i = tid; i < 4 * 72 * 4; i += 256) {
        int nlx = i / (72 * 4);
        int r   = i % (72 * 4);
        int tp = r >> 2, c4 = r & 3;
        int nn = n0 + nlx;
        bool ok = (nn < N_NODES) && (tp < 64);
        const float* src = x + ((size_t)(b * 64 + (ok ? tp : 0)) * N_NODES
                                + (nn < N_NODES ? nn : 0)) * 16 + c4 * 4;
        cpa16(sptr(As + nlx * 72 * 20 + tp * 20 + c4 * 4), src, ok ? 16 : 0);
    }

    // stage B half cc: Bs[k*16+ci][g*32+col], 144 rows x 96 cols (stride 104)
    auto stageB = [&](int cc) {
        for (int i = tid; i < 144 * 24; i += 256) {
            int cil = i / 24;            // combined row k*16+ci
            int rr  = i % 24;
            int g = rr >> 3, c4 = rr & 7;
            const uint32_t* src = wt + ((size_t)g * 144 + cil) * 64 + cc * 32 + c4 * 4;
            cpa16(sptr(Bs + cil * 104 + g * 32 + c4 * 4), src, 16);
        }
    };

    stageB(0);
    cpa_commit();

    const uint32_t* A0 = As + nl0 * 72 * 20;
    const uint32_t* A1 = As + nl1 * 72 * 20;

    #pragma unroll 1
    for (int cc = 0; cc < 2; cc++) {
        if (cc) {
            __syncthreads();         // all warps done reading Bs(0)
            stageB(1);
            cpa_commit();
        }
        cpa_waitall();
        __syncthreads();

        float acc[2][12][4];
        #pragma unroll
        for (int m = 0; m < 2; m++)
            #pragma unroll
            for (int i = 0; i < 12; i++) { acc[m][i][0] = acc[m][i][1] = acc[m][i][2] = acc[m][i][3] = 0.f; }

        #pragma unroll 1
        for (int k = 0; k < 9; k++) {
            #pragma unroll
            for (int kk = 0; kk < 2; kk++) {
                uint32_t a0[4], a1[4];
                {
                    const uint32_t* ap = A0 + (t00 + gid + k) * 20 + kk * 8 + tig;
                    a0[0] = ap[0]; a0[1] = ap[8 * 20]; a0[2] = ap[4]; a0[3] = ap[8 * 20 + 4];
                }
                {
                    const uint32_t* ap = A1 + (t01 + gid + k) * 20 + kk * 8 + tig;
                    a1[0] = ap[0]; a1[1] = ap[8 * 20]; a1[2] = ap[4]; a1[3] = ap[8 * 20 + 4];
                }
                const int brow = k * 16 + kk * 8 + tig;
                #pragma unroll
                for (int nt = 0; nt < 12; nt++) {
                    const uint32_t* bp = Bs + brow * 104 + nt * 8 + gid;
                    uint32_t bf[2] = { bp[0], bp[4 * 104] };
                    mma_tf32(acc[0][nt], a0, bf);
                    mma_tf32(acc[1][nt], a1, bf);
                }
            }
        }

        // epilogue for this co-half
        const int nls[2] = { nl0, nl1 };
        const int t0s[2] = { t00, t01 };
        #pragma unroll
        for (int m = 0; m < 2; m++) {
            const int n = n0 + nls[m];
            if (n < N_NODES) {
                #pragma unroll
                for (int nt3 = 0; nt3 < 4; nt3++) {
                    int co = cc * 32 + nt3 * 8 + tig * 2;
                    float bP0 = bias[co],       bP1 = bias[co + 1];
                    float bQ0 = bias[64 + co],  bQ1 = bias[64 + co + 1];
                    float bR0 = bias[128 + co], bR1 = bias[128 + co + 1];
                    #pragma unroll
                    for (int half = 0; half < 2; half++) {
                        int t = t0s[m] + gid + half * 8;
                        if (t < 56) {
                            int i0 = half * 2;
                            float P0 = acc[m][nt3][i0] + bP0;
                            float P1 = acc[m][nt3][i0 + 1] + bP1;
                            float Q0 = acc[m][nt3 + 4][i0] + bQ0;
                            float Q1 = acc[m][nt3 + 4][i0 + 1] + bQ1;
                            float R0 = acc[m][nt3 + 8][i0] + bR0;
                            float R1 = acc[m][nt3 + 8][i0 + 1] + bR1;
                            float v0 = fmaxf(fmaf(P0, 1.f / (1.f + __expf(-Q0)), R0), 0.f);
                            float v1 = fmaxf(fmaf(P1, 1.f / (1.f + __expf(-Q1)), R1), 0.f);
                            *(float2*)&out[((size_t)(b * 56 + t) * N_NODES + n) * 64 + co] =
                                make_float2(v0, v1);
                        }
                    }
                }
            }
        }
    }
}

// ---------------- Gated temporal conv via tf32 mma.sync (generic) ----------------
template<int Cin, int CINP, int Cout, int Kt, int Tin, int Tout, int TP, int NG,
         int KSUB, int CO, bool ACP, int MINB>
__global__ void __launch_bounds__((NG * (TP / 16) / 2) * 32, MINB)
tconv_mma(const float* __restrict__ x, const uint32_t* __restrict__ wt,
          const float* __restrict__ bias, float* __restrict__ out)
{
    constexpr int MTN   = TP / 16;         // m-tiles per node
    constexpr int TILES = NG * MTN;
    constexpr int NW    = TILES / 2;       // warps (2 tiles per warp)
    constexpr int THREADS = NW * 32;
    constexpr int XS    = TP + Kt - 1;
    constexpr int SA    = CINP + 4;
    constexpr int COLS  = 3 * CO;
    constexpr int SB    = COLS + 8;
    constexpr int NT    = COLS / 8;
    constexpr int COCH  = Cout / CO;
    constexpr int NKS   = CINP / KSUB;
    constexpr int KPI   = Kt * NKS;
    constexpr int ITERS = COCH * KPI;
    constexpr int BUFSZ = KSUB * SB;
    constexpr int CO4   = CO / 4;
    static_assert(TILES % 2 == 0, "even tiles");

    extern __shared__ uint32_t sh[];
    uint32_t* As = sh;                  // NG*XS*SA
    uint32_t* Bs = sh + NG * XS * SA;   // 2*BUFSZ

    const int n0  = blockIdx.x * NG;
    const int b   = blockIdx.y;
    const int tid = threadIdx.x;
    const int wid = tid >> 5, lane = tid & 31;
    const int gid = lane >> 2, tig = lane & 3;

    const int tile0 = 2 * wid, tile1 = 2 * wid + 1;
    const int nl[2]  = { tile0 / MTN, tile1 / MTN };
    const int t0s[2] = { (tile0 % MTN) * 16, (tile1 % MTN) * 16 };

    // ---- stage A slab ----
    if (ACP) {
        constexpr int C4 = CINP / 4;
        for (int i = tid; i < NG * XS * C4; i += THREADS) {
            int nlx = i / (XS * C4);
            int r   = i % (XS * C4);
            int tp = r / C4, c4 = r % C4;
            int nn = n0 + nlx;
            bool ok = (nn < N_NODES) && (tp < Tin);
            const float* src = x + ((size_t)(b * Tin + (ok ? tp : 0)) * N_NODES
                                    + (nn < N_NODES ? nn : 0)) * Cin + c4 * 4;
            cpa16(sptr(As + nlx * XS * SA + tp * SA + c4 * 4), src, ok ? 16 : 0);
        }
    } else {
        for (int i = tid; i < NG * XS * CINP; i += THREADS) {
            int nlx = i / (XS * CINP);
            int r   = i % (XS * CINP);
            int tp = r / CINP, ci = r % CINP;
            int nn = n0 + nlx;
            float v = 0.f;
            if (nn < N_NODES && tp < Tin && ci < Cin)
                v = x[((size_t)(b * Tin + tp) * N_NODES + nn) * Cin + ci];
            As[nlx * XS * SA + tp * SA + ci] = f2tf32v(v);
        }
    }

    // ---- B stage (cp.async) ----
    auto stageB = [&](int it) {
        int cc = it / KPI, r = it % KPI, k = r / NKS, ks = r % NKS;
        uint32_t* Bb = Bs + (it & 1) * BUFSZ;
        for (int i = tid; i < KSUB * 3 * CO4; i += THREADS) {
            int cil = i / (3 * CO4);
            int rr  = i % (3 * CO4);
            int g   = rr / CO4, c4 = rr % CO4;
            const uint32_t* src = wt + ((size_t)(g * Kt + k) * CINP + ks * KSUB + cil) * Cout
                                     + cc * CO + c4 * 4;
            cpa16(sptr(Bb + cil * SB + g * CO + c4 * 4), src, 16);
        }
    };

    stageB(0);
    cpa_commit();

    const uint32_t* A0 = As + nl[0] * XS * SA;
    const uint32_t* A1 = As + nl[1] * XS * SA;

    float acc[2][NT][4];
    #pragma unroll
    for (int m = 0; m < 2; m++)
        #pragma unroll
        for (int i = 0; i < NT; i++) { acc[m][i][0] = acc[m][i][1] = acc[m][i][2] = acc[m][i][3] = 0.f; }

    #pragma unroll 1
    for (int it = 0; it < ITERS; ++it) {
        cpa_waitall();
        __syncthreads();
        if (it + 1 < ITERS) { stageB(it + 1); cpa_commit(); }

        const int r = it % KPI, k = r / NKS, ks = r % NKS;
        const uint32_t* Bb = Bs + (it & 1) * BUFSZ;
        #pragma unroll
        for (int kk = 0; kk < KSUB / 8; kk++) {
            uint32_t a0[4], a1[4];
            {
                const uint32_t* ap = A0 + (t0s[0] + gid + k) * SA + ks * KSUB + kk * 8 + tig;
                a0[0] = ap[0]; a0[1] = ap[8 * SA]; a0[2] = ap[4]; a0[3] = ap[8 * SA + 4];
            }
            {
                const uint32_t* ap = A1 + (t0s[1] + gid + k) * SA + ks * KSUB + kk * 8 + tig;
                a1[0] = ap[0]; a1[1] = ap[8 * SA]; a1[2] = ap[4]; a1[3] = ap[8 * SA + 4];
            }
            #pragma unroll
            for (int nt = 0; nt < NT; nt++) {
                const uint32_t* bp = Bb + (kk * 8 + tig) * SB + nt * 8 + gid;
                uint32_t bf[2] = { bp[0], bp[4 * SB] };
                mma_tf32(acc[0][nt], a0, bf);
                mma_tf32(acc[1][nt], a1, bf);
            }
        }

        if ((it + 1) % KPI == 0) {
            const int cc = it / KPI;
            #pragma unroll
            for (int m = 0; m < 2; m++) {
                const int n = n0 + nl[m];
                if (n < N_NODES) {
                    #pragma unroll
                    for (int nt3 = 0; nt3 < NT / 3; nt3++) {
                        int co = cc * CO + nt3 * 8 + tig * 2;
                        float bP0 = bias[co],            bP1 = bias[co + 1];
                        float bQ0 = bias[Cout + co],     bQ1 = bias[Cout + co + 1];
                        float bR0 = bias[2 * Cout + co], bR1 = bias[2 * Cout + co + 1];
                        #pragma unroll
                        for (int half = 0; half < 2; half++) {
                            int t = t0s[m] + gid + half * 8;
                            if (t < Tout) {
                                int i0 = half * 2;
                                float P0 = acc[m][nt3][i0] + bP0;
                                float P1 = acc[m][nt3][i0 + 1] + bP1;
                                float Q0 = acc[m][nt3 + NT / 3][i0] + bQ0;
                                float Q1 = acc[m][nt3 + NT / 3][i0 + 1] + bQ1;
                                float R0 = acc[m][nt3 + 2 * NT / 3][i0] + bR0;
                                float R1 = acc[m][nt3 + 2 * NT / 3][i0 + 1] + bR1;
                                float v0 = fmaxf(fmaf(P0, 1.f / (1.f + __expf(-Q0)), R0), 0.f);
                                float v1 = fmaxf(fmaf(P1, 1.f / (1.f + __expf(-Q1)), R1), 0.f);
                                *(float2*)&out[((size_t)(b * Tout + t) * N_NODES + n) * Cout + co] =
                                    make_float2(v0, v1);
                            }
                        }
                    }
                }
            }
            #pragma unroll
            for (int m = 0; m < 2; m++)
                #pragma unroll
                for (int i = 0; i < NT; i++) { acc[m][i][0] = acc[m][i][1] = acc[m][i][2] = acc[m][i][3] = 0.f; }
        }
    }
}

// ---------------- Fused Chebyshev with tf32 MMA combine (1024 thr) ----------------
__global__ void __launch_bounds__(1024, 1)
cheb_mma_kernel(const float* __restrict__ zin, const uint32_t* __restrict__ bpimg,
                const float* __restrict__ bias, float* __restrict__ out,
                const int* __restrict__ rowptr, const int* __restrict__ cols,
                const float* __restrict__ norms)
{
    extern __shared__ float fs[];
    float* As = fs;                                   // 224*196
    uint32_t* Ws = (uint32_t*)(fs + 224 * 196);       // 192*72

    const int bt  = blockIdx.x;
    const int tid = threadIdx.x;
    const size_t base = (size_t)bt * N_NODES * 64;

    // group 0: z into k-columns [0,64)
    for (int i = tid; i < N_NODES * 16; i += 1024) {
        int n = i >> 4, c4 = i & 15;
        cpa16(sptr(As + n * 196 + c4 * 4), zin + base + (size_t)n * 64 + c4 * 4, 16);
    }
    cpa_commit();
    // group 1: W image (55 KB) — overlaps the Lhat passes
    for (int i = tid; i < 3456; i += 1024)
        cpa16(sptr(Ws + i * 4), bpimg + i * 4, 16);
    cpa_commit();
    // zero pad rows (STS, concurrent with cp.async)
    for (int i = tid; i < 14 * 196; i += 1024)
        As[(210 + i / 196) * 196 + (i % 196)] = 0.f;

    cpa_wait1();          // z resident (W may still be in flight)
    __syncthreads();

    const int wid = tid >> 5, lane = tid & 31;
    // Lhat pass 1: write k-columns [64,128). One node per warp, ILP-2 over halves.
    for (int nn = wid; nn < N_NODES; nn += 32) {
        int s = rowptr[nn], e = rowptr[nn + 1];
        float a0 = 0.f, a1 = 0.f;
        for (int i = s; i < e; i++) {
            int c = cols[i]; float w_ = norms[i];
            a0 = fmaf(w_, As[c * 196 + lane], a0);
            a1 = fmaf(w_, As[c * 196 + 32 + lane], a1);
        }
        As[nn * 196 + 64 + lane] = a0;
        As[nn * 196 + 96 + lane] = a1;
    }
    __syncthreads();
    // Lhat pass 2: write k-columns [128,192)
    for (int nn = wid; nn < N_NODES; nn += 32) {
        int s = rowptr[nn], e = rowptr[nn + 1];
        float a0 = 0.f, a1 = 0.f;
        for (int i = s; i < e; i++) {
            int c = cols[i]; float w_ = norms[i];
            a0 = fmaf(w_, As[c * 196 + 64 + lane], a0);
            a1 = fmaf(w_, As[c * 196 + 96 + lane], a1);
        }
        As[nn * 196 + 128 + lane] = a0;
        As[nn * 196 + 160 + lane] = a1;
    }
    cpa_waitall();        // W image resident
    __syncthreads();

    // MMA combine: 28 warps = (14 m-tiles) x (2 n-halves); each warp NT=4, K=192
    if (wid < 28) {
        const int gid = lane >> 2, tig = lane & 3;
        const int mt = wid >> 1, nh = wid & 1;
        const int m0 = mt * 16;
        float acc[4][4];
        #pragma unroll
        for (int i = 0; i < 4; i++) { acc[i][0] = acc[i][1] = acc[i][2] = acc[i][3] = 0.f; }

        // kk in [0,8): z columns, tf32-exact -> hi only
        #pragma unroll
        for (int kk = 0; kk < 8; kk++) {
            const float* ap = As + (m0 + gid) * 196 + kk * 8 + tig;
            uint32_t hi[4] = { f2tf32v(ap[0]), f2tf32v(ap[8 * 196]),
                               f2tf32v(ap[4]), f2tf32v(ap[8 * 196 + 4]) };
            #pragma unroll
            for (int j = 0; j < 4; j++) {
                int nt = nh * 4 + j;
                const uint32_t* bp = Ws + (kk * 8 + tig) * 72 + nt * 8 + gid;
                uint32_t bf[2] = { bp[0], bp[4 * 72] };
                mma_tf32(acc[j], hi, bf);
            }
        }
        // kk in [8,24): t1/t2 columns -> hi + lo
        #pragma unroll 4
        for (int kk = 8; kk < 24; kk++) {
            const float* ap = As + (m0 + gid) * 196 + kk * 8 + tig;
            float af[4] = { ap[0], ap[8 * 196], ap[4], ap[8 * 196 + 4] };
            uint32_t hi[4], lo[4];
            #pragma unroll
            for (int e = 0; e < 4; e++) {
                hi[e] = f2tf32v(af[e]);
                lo[e] = f2tf32v(af[e] - __uint_as_float(hi[e]));
            }
            #pragma unroll
            for (int j = 0; j < 4; j++) {
                int nt = nh * 4 + j;
                const uint32_t* bp = Ws + (kk * 8 + tig) * 72 + nt * 8 + gid;
                uint32_t bf[2] = { bp[0], bp[4 * 72] };
                mma_tf32(acc[j], hi, bf);
                mma_tf32(acc[j], lo, bf);
            }
        }

        #pragma unroll
        for (int j = 0; j < 4; j++) {
            int g = (nh * 4 + j) * 8 + tig * 2;
            float b0 = bias[g], b1 = bias[g + 1];
            int n_lo = m0 + gid, n_hi = m0 + gid + 8;
            if (n_lo < N_NODES) {
                float v0 = roundtf(fmaxf(acc[j][0] + b0, 0.f));
                float v1 = roundtf(fmaxf(acc[j][1] + b1, 0.f));
                *(float2*)&out[base + (size_t)n_lo * 64 + g] = make_float2(v0, v1);
            }
            if (n_hi < N_NODES) {
                float v0 = roundtf(fmaxf(acc[j][2] + b0, 0.f));
                float v1 = roundtf(fmaxf(acc[j][3] + b1, 0.f));
                *(float2*)&out[base + (size_t)n_hi * 64 + g] = make_float2(v0, v1);
            }
        }
    }
}

// ---------------- BatchNorm over node channel (in-place, float4) ----------------
template<int C, bool RND>
__global__ void bn_kernel(float* __restrict__ x, const float* __restrict__ gamma,
                          const float* __restrict__ beta, int BT, int N)
{
    constexpr int C4 = C / 4;
    const int n   = blockIdx.x;
    const int tid = threadIdx.x;  // 256
    const int M4  = BT * C4;
    float4* x4 = (float4*)x;
    float s = 0.f, s2 = 0.f;
    for (int i = tid; i < M4; i += 256) {
        int bt = i / C4, c4 = i % C4;
        float4 v = x4[((size_t)bt * N + n) * C4 + c4];
        s  += v.x + v.y + v.z + v.w;
        s2 += v.x * v.x + v.y * v.y + v.z * v.z + v.w * v.w;
    }
    __shared__ float rs[256], rs2[256];
    __shared__ float mean_s, istd_s;
    rs[tid] = s; rs2[tid] = s2;
    __syncthreads();
    for (int o = 128; o > 0; o >>= 1) {
        if (tid < o) { rs[tid] += rs[tid + o]; rs2[tid] += rs2[tid + o]; }
        __syncthreads();
    }
    if (tid == 0) {
        float inv = 1.f / (float)(BT * C);
        float mean = rs[0] * inv;
        float var  = rs2[0] * inv - mean * mean;
        mean_s = mean;
        istd_s = rsqrtf(var + 1e-5f);
    }
    __syncthreads();
    const float gm = gamma[n], bt_ = beta[n];
    const float mean = mean_s, istd = istd_s;
    for (int i = tid; i < M4; i += 256) {
        int bt = i / C4, c4 = i % C4;
        size_t a = ((size_t)bt * N + n) * C4 + c4;
        float4 v = x4[a];
        v.x = (v.x - mean) * istd * gm + bt_;
        v.y = (v.y - mean) * istd * gm + bt_;
        v.z = (v.z - mean) * istd * gm + bt_;
        v.w = (v.w - mean) * istd * gm + bt_;
        if (RND) { v.x = roundtf(v.x); v.y = roundtf(v.y); v.z = roundtf(v.z); v.w = roundtf(v.w); }
        x4[a] = v;
    }
}

// ---------------- Fused BN(C=16) + FC: out = BN(x) @ fc_w + fc_b ----------------
__global__ void bnfc_kernel(const float* __restrict__ x, const float* __restrict__ gamma,
                            const float* __restrict__ beta, const float* __restrict__ fw,
                            const float* __restrict__ fb, float* __restrict__ out,
                            int BT, int N)
{
    const int n   = blockIdx.x;
    const int tid = threadIdx.x;  // 256
    const int M4  = BT * 4;       // float4 count for C=16
    const float4* x4 = (const float4*)x;

    __shared__ float fws[48];
    __shared__ float fbs[3];
    if (tid < 48) fws[tid] = fw[tid];
    if (tid < 3)  fbs[tid] = fb[tid];

    float s = 0.f, s2 = 0.f;
    for (int i = tid; i < M4; i += 256) {
        int bt = i >> 2, c4 = i & 3;
        float4 v = x4[((size_t)bt * N + n) * 4 + c4];
        s  += v.x + v.y + v.z + v.w;
        s2 += v.x * v.x + v.y * v.y + v.z * v.z + v.w * v.w;
    }
    __shared__ float rs[256], rs2[256];
    __shared__ float mean_s, istd_s;
    rs[tid] = s; rs2[tid] = s2;
    __syncthreads();
    for (int o = 128; o > 0; o >>= 1) {
        if (tid < o) { rs[tid] += rs[tid + o]; rs2[tid] += rs2[tid + o]; }
        __syncthreads();
    }
    if (tid == 0) {
        float inv = 1.f / (float)(BT * 16);
        float mean = rs[0] * inv;
        float var  = rs2[0] * inv - mean * mean;
        mean_s = mean;
        istd_s = rsqrtf(var + 1e-5f);
    }
    __syncthreads();
    const float gm = gamma[n], bt_ = beta[n];
    const float mean = mean_s, istd = istd_s;

    for (int bt = tid; bt < BT; bt += 256) {
        const float4* row = &x4[((size_t)bt * N + n) * 4];
        float o0 = fbs[0], o1 = fbs[1], o2 = fbs[2];
        #pragma unroll
        for (int c4 = 0; c4 < 4; c4++) {
            float4 v = row[c4];
            float h0 = (v.x - mean) * istd * gm + bt_;
            float h1 = (v.y - mean) * istd * gm + bt_;
            float h2 = (v.z - mean) * istd * gm + bt_;
            float h3 = (v.w - mean) * istd * gm + bt_;
            int c = c4 * 4;
            o0 = fmaf(h0, fws[(c + 0) * 3 + 0], o0); o1 = fmaf(h0, fws[(c + 0) * 3 + 1], o1); o2 = fmaf(h0, fws[(c + 0) * 3 + 2], o2);
            o0 = fmaf(h1, fws[(c + 1) * 3 + 0], o0); o1 = fmaf(h1, fws[(c + 1) * 3 + 1], o1); o2 = fmaf(h1, fws[(c + 1) * 3 + 2], o2);
            o0 = fmaf(h2, fws[(c + 2) * 3 + 0], o0); o1 = fmaf(h2, fws[(c + 2) * 3 + 1], o1); o2 = fmaf(h2, fws[(c + 2) * 3 + 2], o2);
            o0 = fmaf(h3, fws[(c + 3) * 3 + 0], o0); o1 = fmaf(h3, fws[(c + 3) * 3 + 1], o1); o2 = fmaf(h3, fws[(c + 3) * 3 + 2], o2);
        }
        size_t r = (size_t)bt * N + n;
        out[r * 3 + 0] = o0;
        out[r * 3 + 1] = o1;
        out[r * 3 + 2] = o2;
    }
}

// ---------------- Launch ----------------
extern "C" void kernel_launch(void* const* d_in, const int* in_sizes, int n_in,
                              void* d_out, int out_size)
{
    const float* x        = (const float*)d_in[0];
    const int*   eidx     = (const int*)d_in[1];
    const float* eattr    = (const float*)d_in[2];
    const float* b1_t1_w  = (const float*)d_in[3];
    const float* b1_t1_b  = (const float*)d_in[4];
    const float* b1_ch_w  = (const float*)d_in[5];
    const float* b1_ch_b  = (const float*)d_in[6];
    const float* b1_t2_w  = (const float*)d_in[7];
    const float* b1_t2_b  = (const float*)d_in[8];
    const float* b1_bn_g  = (const float*)d_in[9];
    const float* b1_bn_b  = (const float*)d_in[10];
    const float* b2_t1_w  = (const float*)d_in[11];
    const float* b2_t1_b  = (const float*)d_in[12];
    const float* b2_ch_w  = (const float*)d_in[13];
    const float* b2_ch_b  = (const float*)d_in[14];
    const float* b2_t2_w  = (const float*)d_in[15];
    const float* b2_t2_b  = (const float*)d_in[16];
    const float* b2_bn_g  = (const float*)d_in[17];
    const float* b2_bn_b  = (const float*)d_in[18];
    const float* fc_w     = (const float*)d_in[19];
    const float* fc_b     = (const float*)d_in[20];

    float *bufA, *bufB, *bufC, *nrm, *xpad;
    int *rowptr, *cols; uint32_t *wt, *bp;
    cudaGetSymbolAddress((void**)&bufA,  g_bufA);
    cudaGetSymbolAddress((void**)&bufB,  g_bufB);
    cudaGetSymbolAddress((void**)&bufC,  g_bufC);
    cudaGetSymbolAddress((void**)&xpad,  g_xpad);
    cudaGetSymbolAddress((void**)&rowptr, g_rowptr);
    cudaGetSymbolAddress((void**)&cols,  g_cols);
    cudaGetSymbolAddress((void**)&nrm,   g_norm);
    cudaGetSymbolAddress((void**)&wt,    g_wt);
    cudaGetSymbolAddress((void**)&bp,    g_bp);

    const int N = N_NODES;

    // instantiations:           Cin CINP Cout Kt Tin Tout TP NG KSUB CO  ACP  MINB
    auto k_b1t2 = tconv_mma<64, 64, 128, 9, 56, 48, 48, 4, 64, 32, true, 2>;  // 6 warps, 2 blk/SM
    auto k_b2t1 = tconv_mma<128, 128, 64, 5, 48, 44, 48, 6, 64, 32, true, 1>; // 9 warps, 1 blk/SM
    auto k_b2t2 = tconv_mma<64, 64, 16, 5, 44, 40, 48, 4, 64, 16, true, 2>;   // 6 warps, 2 blk/SM

    const int sm_t1c  = (4 * 72 * 20 + 144 * 104) * 4;       // 82,944
    const int sm_b1t2 = (4 * 56 * 68 + 2 * 64 * 104) * 4;    // 114,176
    const int sm_b2t1 = (6 * 52 * 132 + 2 * 64 * 104) * 4;   // 217,984
    const int sm_b2t2 = (4 * 52 * 68 + 2 * 64 * 56) * 4;     // 85,248
    const int sm_cheb = (224 * 196 + 192 * 72) * 4;          // 230,912

    cudaFuncSetAttribute(t1conv_kernel, cudaFuncAttributeMaxDynamicSharedMemorySize, sm_t1c);
    cudaFuncSetAttribute(k_b1t2, cudaFuncAttributeMaxDynamicSharedMemorySize, sm_b1t2);
    cudaFuncSetAttribute(k_b2t1, cudaFuncAttributeMaxDynamicSharedMemorySize, sm_b2t1);
    cudaFuncSetAttribute(k_b2t2, cudaFuncAttributeMaxDynamicSharedMemorySize, sm_b2t2);
    cudaFuncSetAttribute(cheb_mma_kernel, cudaFuncAttributeMaxDynamicSharedMemorySize, sm_cheb);

    // ---- prep ----
    build_csr_kernel<<<1, 256>>>(eidx, eattr, rowptr, cols, nrm);
    wconv_kernel<<<(387072 + 255) / 256, 256>>>(b1_t1_w, b1_t2_w, b2_t1_w, b2_t2_w, wt);
    bp_build_kernel<<<(2 * 13824 + 255) / 256, 256>>>(b1_ch_w, b2_ch_w);
    xpad_kernel<<<(32 * 64 * 210 * 16 + 255) / 256, 256>>>(x);

    // ======== Block 1 ========
    t1conv_kernel<<<dim3(53, BATCH), 256, sm_t1c>>>(xpad, wt + WOFF1, b1_t1_b, bufA);
    cheb_mma_kernel<<<32 * 56, 1024, sm_cheb>>>(bufA, bp, b1_ch_b, bufB, rowptr, cols, nrm);
    k_b1t2<<<dim3(53, BATCH), 192, sm_b1t2>>>(bufB, wt + WOFF2, b1_t2_b, bufC);
    bn_kernel<128, true><<<N, 256>>>(bufC, b1_bn_g, b1_bn_b, 32 * 48, N);

    // ======== Block 2 ========
    k_b2t1<<<dim3(35, BATCH), 288, sm_b2t1>>>(bufC, wt + WOFF3, b2_t1_b, bufA);
    cheb_mma_kernel<<<32 * 44, 1024, sm_cheb>>>(bufA, bp + 13824, b2_ch_b, bufB, rowptr, cols, nrm);
    k_b2t2<<<dim3(53, BATCH), 192, sm_b2t2>>>(bufB, wt + WOFF4, b2_t2_b, bufC);

    // ---- fused BN2 + FC ----
    bnfc_kernel<<<N, 256>>>(bufC, b2_bn_g, b2_bn_b, fc_w, fc_b, (float*)d_out, 32 * 40, N);

    (void)in_sizes; (void)n_in; (void)out_size;
}

// round 16
// speedup vs baseline: 1.6629x; 1.0317x over previous
#include <cuda_runtime.h>
#include <cuda_bf16.h>
#include <cstdint>

// ---------------- Problem constants ----------------
#define N_NODES 210
#define N_EDGES 4200
#define BATCH   32

// ---------------- Static device scratch ----------------
__device__ float    g_bufA[32ll * 56 * 210 * 64];   // 24.08M floats
__device__ float    g_bufB[32ll * 56 * 210 * 64];
__device__ float    g_bufC[32ll * 48 * 210 * 128];  // 41.29M floats
__device__ float    g_xpad[32ll * 64 * 210 * 16];   // padded tf32-rounded input (6.88M)
__device__ int      g_rowptr[N_NODES + 1];
__device__ int      g_cols[N_EDGES];
__device__ float    g_norm[N_EDGES];
__device__ uint32_t g_wt[387072];                   // tf32 tconv weights
__device__ uint32_t g_bp[2 * 13824];                // folded cheb W images (192x72) x2

// region offsets in g_wt
#define WOFF1 0        // b1_t1 padded (3,9,16,64)   = 27648
#define WOFF2 27648    // b1_t2        (3,9,64,128)  = 221184
#define WOFF3 248832   // b2_t1        (3,5,128,64)  = 122880
#define WOFF4 371712   // b2_t2        (3,5,64,16)   = 15360

// ---------------- helpers ----------------
__device__ __forceinline__ uint32_t f2tf32v(float x) {
    uint32_t r; asm("cvt.rna.tf32.f32 %0, %1;" : "=r"(r) : "f"(x)); return r;
}
__device__ __forceinline__ float roundtf(float x) {
    return __uint_as_float(f2tf32v(x));
}
__device__ __forceinline__ void mma_tf32(float c[4], const uint32_t a[4], const uint32_t b[2]) {
    asm volatile("mma.sync.aligned.m16n8k8.row.col.f32.tf32.tf32.f32 "
        "{%0,%1,%2,%3}, {%4,%5,%6,%7}, {%8,%9}, {%0,%1,%2,%3};"
        : "+f"(c[0]), "+f"(c[1]), "+f"(c[2]), "+f"(c[3])
        : "r"(a[0]), "r"(a[1]), "r"(a[2]), "r"(a[3]), "r"(b[0]), "r"(b[1]));
}
__device__ __forceinline__ uint32_t sptr(const void* p) {
    return (uint32_t)__cvta_generic_to_shared(p);
}
__device__ __forceinline__ void cpa16(uint32_t dst, const void* src, int sz) {
    asm volatile("cp.async.cg.shared.global [%0], [%1], 16, %2;"
                 :: "r"(dst), "l"(src), "r"(sz));
}
__device__ __forceinline__ void cpa_commit() { asm volatile("cp.async.commit_group;"); }
__device__ __forceinline__ void cpa_waitall() { asm volatile("cp.async.wait_group 0;"); }
__device__ __forceinline__ void cpa_wait1()  { asm volatile("cp.async.wait_group 1;"); }

// ---------------- Input pad prepass: x (B,64,210,14) -> xpad (B,64,210,16) tf32 ----------------
__global__ void xpad_kernel(const float* __restrict__ x)
{
    const int total = 32 * 64 * 210 * 16;
    for (int i = blockIdx.x * blockDim.x + threadIdx.x; i < total; i += gridDim.x * blockDim.x) {
        int c = i & 15;
        int r = i >> 4;          // (b*64+t)*210+n
        float v = (c < 14) ? roundtf(x[(size_t)r * 14 + c]) : 0.f;
        g_xpad[i] = v;
    }
}

// ---------------- Weight prepass: fp32 -> tf32 (padded for b1_t1) ----------------
__global__ void wconv_kernel(const float* __restrict__ w1, const float* __restrict__ w2,
                             const float* __restrict__ w3, const float* __restrict__ w4,
                             uint32_t* __restrict__ out)
{
    int i = blockIdx.x * blockDim.x + threadIdx.x;
    if (i < 27648) {  // b1_t1 padded: (g,k,ci<16,co<64); src (3,1,9,14,64)
        int co = i & 63; int r = i >> 6;
        int ci = r % 16; r /= 16;
        int k = r % 9;  int g = r / 9;
        float v = (ci < 14) ? w1[((g * 9 + k) * 14 + ci) * 64 + co] : 0.f;
        out[i] = f2tf32v(v);
        return;
    }
    int j = i - WOFF2;
    if (j >= 0 && j < 221184) { out[i] = f2tf32v(w2[j]); return; }
    j = i - WOFF3;
    if (j >= 0 && j < 122880) { out[i] = f2tf32v(w3[j]); return; }
    j = i - WOFF4;
    if (j >= 0 && j < 15360)  { out[i] = f2tf32v(w4[j]); return; }
}

// ---------------- Folded cheb W images: [W0-W2 ; W1 ; 2*W2] tf32, stride 72 ----------------
__global__ void bp_build_kernel(const float* __restrict__ W1, const float* __restrict__ W2)
{
    int i = blockIdx.x * blockDim.x + threadIdx.x;
    if (i >= 2 * 13824) return;
    int which = i / 13824, r = i % 13824;
    int row = r / 72, g = r % 72;
    int term = row >> 6, h = row & 63;
    const float* W = which ? W2 : W1;
    float v = 0.f;
    if (g < 64) {
        if (term == 0)      v = W[h * 64 + g] - W[2 * 4096 + h * 64 + g];
        else if (term == 1) v = W[4096 + h * 64 + g];
        else                v = 2.f * W[2 * 4096 + h * 64 + g];
    }
    g_bp[i] = f2tf32v(v);
}

// ---------------- CSR build (deterministic, 1 block) ----------------
__global__ void build_csr_kernel(const int* __restrict__ edge_index,
                                 const float* __restrict__ eattr,
                                 int* __restrict__ rowptr,
                                 int* __restrict__ cols,
                                 float* __restrict__ norms)
{
    __shared__ int   row_s[N_EDGES];
    __shared__ short col_s[N_EDGES];
    __shared__ float attr_s[N_EDGES];
    __shared__ int   cnt_s[N_NODES + 1];
    __shared__ float dis_s[N_NODES];

    const int tid = threadIdx.x;  // 256
    for (int i = tid; i < N_EDGES; i += 256) {
        row_s[i]  = edge_index[i];
        col_s[i]  = (short)edge_index[N_EDGES + i];
        attr_s[i] = eattr[i];
    }
    __syncthreads();

    if (tid < N_NODES) {
        float deg = 0.f; int cnt = 0;
        for (int e = 0; e < N_EDGES; e++) {
            if (row_s[e] == tid) { deg += attr_s[e]; cnt++; }
        }
        cnt_s[tid] = cnt;
        dis_s[tid] = (deg > 0.f) ? rsqrtf(deg) : 0.f;
    }
    __syncthreads();
    if (tid == 0) {
        int acc = 0;
        for (int n = 0; n < N_NODES; n++) { int c = cnt_s[n]; cnt_s[n] = acc; acc += c; }
        cnt_s[N_NODES] = acc;
    }
    __syncthreads();
    if (tid <= N_NODES) rowptr[tid] = cnt_s[tid];
    if (tid < N_NODES) {
        int wpos = cnt_s[tid];
        const float disr = dis_s[tid];
        for (int e = 0; e < N_EDGES; e++) {
            if (row_s[e] == tid) {
                int c = col_s[e];
                cols[wpos]  = c;
                norms[wpos] = -disr * attr_s[e] * dis_s[c];
                wpos++;
            }
        }
    }
}

// ---------------- b1_t1 dedicated kernel: all weights smem-resident, 2 stages ----------------
__global__ void __launch_bounds__(256, 2)
t1conv_kernel(const float* __restrict__ x, const uint32_t* __restrict__ wt,
              const float* __restrict__ bias, float* __restrict__ out)
{
    extern __shared__ uint32_t sh[];
    uint32_t* As = sh;            // 4*72*20 = 5760
    uint32_t* Bs = sh + 5760;     // 144*104 = 14976

    const int n0  = blockIdx.x * 4;
    const int b   = blockIdx.y;
    const int tid = threadIdx.x;
    const int wid = tid >> 5, lane = tid & 31;
    const int gid = lane >> 2, tig = lane & 3;

    const int tile0 = 2 * wid, tile1 = 2 * wid + 1;
    const int nl0 = tile0 >> 2, nl1 = tile1 >> 2;
    const int t00 = (tile0 & 3) * 16, t01 = (tile1 & 3) * 16;

    for (int i = tid; i < 4 * 72 * 4; i += 256) {
        int nlx = i / (72 * 4);
        int r   = i % (72 * 4);
        int tp = r >> 2, c4 = r & 3;
        int nn = n0 + nlx;
        bool ok = (nn < N_NODES) && (tp < 64);
        const float* src = x + ((size_t)(b * 64 + (ok ? tp : 0)) * N_NODES
                                + (nn < N_NODES ? nn : 0)) * 16 + c4 * 4;
        cpa16(sptr(As + nlx * 72 * 20 + tp * 20 + c4 * 4), src, ok ? 16 : 0);
    }

    auto stageB = [&](int cc) {
        for (int i = tid; i < 144 * 24; i += 256) {
            int cil = i / 24;
            int rr  = i % 24;
            int g = rr >> 3, c4 = rr & 7;
            const uint32_t* src = wt + ((size_t)g * 144 + cil) * 64 + cc * 32 + c4 * 4;
            cpa16(sptr(Bs + cil * 104 + g * 32 + c4 * 4), src, 16);
        }
    };

    stageB(0);
    cpa_commit();

    const uint32_t* A0 = As + nl0 * 72 * 20;
    const uint32_t* A1 = As + nl1 * 72 * 20;

    #pragma unroll 1
    for (int cc = 0; cc < 2; cc++) {
        if (cc) {
            __syncthreads();
            stageB(1);
            cpa_commit();
        }
        cpa_waitall();
        __syncthreads();

        float acc[2][12][4];
        #pragma unroll
        for (int m = 0; m < 2; m++)
            #pragma unroll
            for (int i = 0; i < 12; i++) { acc[m][i][0] = acc[m][i][1] = acc[m][i][2] = acc[m][i][3] = 0.f; }

        #pragma unroll 1
        for (int k = 0; k < 9; k++) {
            #pragma unroll
            for (int kk = 0; kk < 2; kk++) {
                uint32_t a0[4], a1[4];
                {
                    const uint32_t* ap = A0 + (t00 + gid + k) * 20 + kk * 8 + tig;
                    a0[0] = ap[0]; a0[1] = ap[8 * 20]; a0[2] = ap[4]; a0[3] = ap[8 * 20 + 4];
                }
                {
                    const uint32_t* ap = A1 + (t01 + gid + k) * 20 + kk * 8 + tig;
                    a1[0] = ap[0]; a1[1] = ap[8 * 20]; a1[2] = ap[4]; a1[3] = ap[8 * 20 + 4];
                }
                const int brow = k * 16 + kk * 8 + tig;
                #pragma unroll
                for (int nt = 0; nt < 12; nt++) {
                    const uint32_t* bp = Bs + brow * 104 + nt * 8 + gid;
                    uint32_t bf[2] = { bp[0], bp[4 * 104] };
                    mma_tf32(acc[0][nt], a0, bf);
                    mma_tf32(acc[1][nt], a1, bf);
                }
            }
        }

        const int nls[2] = { nl0, nl1 };
        const int t0s[2] = { t00, t01 };
        #pragma unroll
        for (int m = 0; m < 2; m++) {
            const int n = n0 + nls[m];
            if (n < N_NODES) {
                #pragma unroll
                for (int nt3 = 0; nt3 < 4; nt3++) {
                    int co = cc * 32 + nt3 * 8 + tig * 2;
                    float bP0 = bias[co],       bP1 = bias[co + 1];
                    float bQ0 = bias[64 + co],  bQ1 = bias[64 + co + 1];
                    float bR0 = bias[128 + co], bR1 = bias[128 + co + 1];
                    #pragma unroll
                    for (int half = 0; half < 2; half++) {
                        int t = t0s[m] + gid + half * 8;
                        if (t < 56) {
                            int i0 = half * 2;
                            float P0 = acc[m][nt3][i0] + bP0;
                            float P1 = acc[m][nt3][i0 + 1] + bP1;
                            float Q0 = acc[m][nt3 + 4][i0] + bQ0;
                            float Q1 = acc[m][nt3 + 4][i0 + 1] + bQ1;
                            float R0 = acc[m][nt3 + 8][i0] + bR0;
                            float R1 = acc[m][nt3 + 8][i0 + 1] + bR1;
                            float v0 = fmaxf(fmaf(P0, 1.f / (1.f + __expf(-Q0)), R0), 0.f);
                            float v1 = fmaxf(fmaf(P1, 1.f / (1.f + __expf(-Q1)), R1), 0.f);
                            *(float2*)&out[((size_t)(b * 56 + t) * N_NODES + n) * 64 + co] =
                                make_float2(v0, v1);
                        }
                    }
                }
            }
        }
    }
}

// ---------------- Gated temporal conv via tf32 mma.sync (generic) ----------------
template<int Cin, int CINP, int Cout, int Kt, int Tin, int Tout, int TP, int NG,
         int KSUB, int CO, bool ACP, int MINB>
__global__ void __launch_bounds__((NG * (TP / 16) / 2) * 32, MINB)
tconv_mma(const float* __restrict__ x, const uint32_t* __restrict__ wt,
          const float* __restrict__ bias, float* __restrict__ out)
{
    constexpr int MTN   = TP / 16;
    constexpr int TILES = NG * MTN;
    constexpr int NW    = TILES / 2;
    constexpr int THREADS = NW * 32;
    constexpr int XS    = TP + Kt - 1;
    constexpr int SA    = CINP + 4;
    constexpr int COLS  = 3 * CO;
    constexpr int SB    = COLS + 8;
    constexpr int NT    = COLS / 8;
    constexpr int COCH  = Cout / CO;
    constexpr int NKS   = CINP / KSUB;
    constexpr int KPI   = Kt * NKS;
    constexpr int ITERS = COCH * KPI;
    constexpr int BUFSZ = KSUB * SB;
    constexpr int CO4   = CO / 4;
    static_assert(TILES % 2 == 0, "even tiles");

    extern __shared__ uint32_t sh[];
    uint32_t* As = sh;
    uint32_t* Bs = sh + NG * XS * SA;

    const int n0  = blockIdx.x * NG;
    const int b   = blockIdx.y;
    const int tid = threadIdx.x;
    const int wid = tid >> 5, lane = tid & 31;
    const int gid = lane >> 2, tig = lane & 3;

    const int tile0 = 2 * wid, tile1 = 2 * wid + 1;
    const int nl[2]  = { tile0 / MTN, tile1 / MTN };
    const int t0s[2] = { (tile0 % MTN) * 16, (tile1 % MTN) * 16 };

    if (ACP) {
        constexpr int C4 = CINP / 4;
        for (int i = tid; i < NG * XS * C4; i += THREADS) {
            int nlx = i / (XS * C4);
            int r   = i % (XS * C4);
            int tp = r / C4, c4 = r % C4;
            int nn = n0 + nlx;
            bool ok = (nn < N_NODES) && (tp < Tin);
            const float* src = x + ((size_t)(b * Tin + (ok ? tp : 0)) * N_NODES
                                    + (nn < N_NODES ? nn : 0)) * Cin + c4 * 4;
            cpa16(sptr(As + nlx * XS * SA + tp * SA + c4 * 4), src, ok ? 16 : 0);
        }
    } else {
        for (int i = tid; i < NG * XS * CINP; i += THREADS) {
            int nlx = i / (XS * CINP);
            int r   = i % (XS * CINP);
            int tp = r / CINP, ci = r % CINP;
            int nn = n0 + nlx;
            float v = 0.f;
            if (nn < N_NODES && tp < Tin && ci < Cin)
                v = x[((size_t)(b * Tin + tp) * N_NODES + nn) * Cin + ci];
            As[nlx * XS * SA + tp * SA + ci] = f2tf32v(v);
        }
    }

    auto stageB = [&](int it) {
        int cc = it / KPI, r = it % KPI, k = r / NKS, ks = r % NKS;
        uint32_t* Bb = Bs + (it & 1) * BUFSZ;
        for (int i = tid; i < KSUB * 3 * CO4; i += THREADS) {
            int cil = i / (3 * CO4);
            int rr  = i % (3 * CO4);
            int g   = rr / CO4, c4 = rr % CO4;
            const uint32_t* src = wt + ((size_t)(g * Kt + k) * CINP + ks * KSUB + cil) * Cout
                                     + cc * CO + c4 * 4;
            cpa16(sptr(Bb + cil * SB + g * CO + c4 * 4), src, 16);
        }
    };

    stageB(0);
    cpa_commit();

    const uint32_t* A0 = As + nl[0] * XS * SA;
    const uint32_t* A1 = As + nl[1] * XS * SA;

    float acc[2][NT][4];
    #pragma unroll
    for (int m = 0; m < 2; m++)
        #pragma unroll
        for (int i = 0; i < NT; i++) { acc[m][i][0] = acc[m][i][1] = acc[m][i][2] = acc[m][i][3] = 0.f; }

    #pragma unroll 1
    for (int it = 0; it < ITERS; ++it) {
        cpa_waitall();
        __syncthreads();
        if (it + 1 < ITERS) { stageB(it + 1); cpa_commit(); }

        const int r = it % KPI, k = r / NKS, ks = r % NKS;
        const uint32_t* Bb = Bs + (it & 1) * BUFSZ;
        #pragma unroll
        for (int kk = 0; kk < KSUB / 8; kk++) {
            uint32_t a0[4], a1[4];
            {
                const uint32_t* ap = A0 + (t0s[0] + gid + k) * SA + ks * KSUB + kk * 8 + tig;
                a0[0] = ap[0]; a0[1] = ap[8 * SA]; a0[2] = ap[4]; a0[3] = ap[8 * SA + 4];
            }
            {
                const uint32_t* ap = A1 + (t0s[1] + gid + k) * SA + ks * KSUB + kk * 8 + tig;
                a1[0] = ap[0]; a1[1] = ap[8 * SA]; a1[2] = ap[4]; a1[3] = ap[8 * SA + 4];
            }
            #pragma unroll
            for (int nt = 0; nt < NT; nt++) {
                const uint32_t* bp = Bb + (kk * 8 + tig) * SB + nt * 8 + gid;
                uint32_t bf[2] = { bp[0], bp[4 * SB] };
                mma_tf32(acc[0][nt], a0, bf);
                mma_tf32(acc[1][nt], a1, bf);
            }
        }

        if ((it + 1) % KPI == 0) {
            const int cc = it / KPI;
            #pragma unroll
            for (int m = 0; m < 2; m++) {
                const int n = n0 + nl[m];
                if (n < N_NODES) {
                    #pragma unroll
                    for (int nt3 = 0; nt3 < NT / 3; nt3++) {
                        int co = cc * CO + nt3 * 8 + tig * 2;
                        float bP0 = bias[co],            bP1 = bias[co + 1];
                        float bQ0 = bias[Cout + co],     bQ1 = bias[Cout + co + 1];
                        float bR0 = bias[2 * Cout + co], bR1 = bias[2 * Cout + co + 1];
                        #pragma unroll
                        for (int half = 0; half < 2; half++) {
                            int t = t0s[m] + gid + half * 8;
                            if (t < Tout) {
                                int i0 = half * 2;
                                float P0 = acc[m][nt3][i0] + bP0;
                                float P1 = acc[m][nt3][i0 + 1] + bP1;
                                float Q0 = acc[m][nt3 + NT / 3][i0] + bQ0;
                                float Q1 = acc[m][nt3 + NT / 3][i0 + 1] + bQ1;
                                float R0 = acc[m][nt3 + 2 * NT / 3][i0] + bR0;
                                float R1 = acc[m][nt3 + 2 * NT / 3][i0 + 1] + bR1;
                                float v0 = fmaxf(fmaf(P0, 1.f / (1.f + __expf(-Q0)), R0), 0.f);
                                float v1 = fmaxf(fmaf(P1, 1.f / (1.f + __expf(-Q1)), R1), 0.f);
                                *(float2*)&out[((size_t)(b * Tout + t) * N_NODES + n) * Cout + co] =
                                    make_float2(v0, v1);
                            }
                        }
                    }
                }
            }
            #pragma unroll
            for (int m = 0; m < 2; m++)
                #pragma unroll
                for (int i = 0; i < NT; i++) { acc[m][i][0] = acc[m][i][1] = acc[m][i][2] = acc[m][i][3] = 0.f; }
        }
    }
}

// ---------------- Fused Chebyshev with tf32 MMA combine (1024 thr) ----------------
__global__ void __launch_bounds__(1024, 1)
cheb_mma_kernel(const float* __restrict__ zin, const uint32_t* __restrict__ bpimg,
                const float* __restrict__ bias, float* __restrict__ out,
                const int* __restrict__ rowptr, const int* __restrict__ cols,
                const float* __restrict__ norms)
{
    extern __shared__ float fs[];
    float* As = fs;                                   // 224*196
    uint32_t* Ws = (uint32_t*)(fs + 224 * 196);       // 192*72

    const int bt  = blockIdx.x;
    const int tid = threadIdx.x;
    const size_t base = (size_t)bt * N_NODES * 64;

    for (int i = tid; i < N_NODES * 16; i += 1024) {
        int n = i >> 4, c4 = i & 15;
        cpa16(sptr(As + n * 196 + c4 * 4), zin + base + (size_t)n * 64 + c4 * 4, 16);
    }
    cpa_commit();
    for (int i = tid; i < 3456; i += 1024)
        cpa16(sptr(Ws + i * 4), bpimg + i * 4, 16);
    cpa_commit();
    for (int i = tid; i < 14 * 196; i += 1024)
        As[(210 + i / 196) * 196 + (i % 196)] = 0.f;

    cpa_wait1();
    __syncthreads();

    const int wid = tid >> 5, lane = tid & 31;
    for (int nn = wid; nn < N_NODES; nn += 32) {
        int s = rowptr[nn], e = rowptr[nn + 1];
        float a0 = 0.f, a1 = 0.f;
        for (int i = s; i < e; i++) {
            int c = cols[i]; float w_ = norms[i];
            a0 = fmaf(w_, As[c * 196 + lane], a0);
            a1 = fmaf(w_, As[c * 196 + 32 + lane], a1);
        }
        As[nn * 196 + 64 + lane] = a0;
        As[nn * 196 + 96 + lane] = a1;
    }
    __syncthreads();
    for (int nn = wid; nn < N_NODES; nn += 32) {
        int s = rowptr[nn], e = rowptr[nn + 1];
        float a0 = 0.f, a1 = 0.f;
        for (int i = s; i < e; i++) {
            int c = cols[i]; float w_ = norms[i];
            a0 = fmaf(w_, As[c * 196 + 64 + lane], a0);
            a1 = fmaf(w_, As[c * 196 + 96 + lane], a1);
        }
        As[nn * 196 + 128 + lane] = a0;
        As[nn * 196 + 160 + lane] = a1;
    }
    cpa_waitall();
    __syncthreads();

    if (wid < 28) {
        const int gid = lane >> 2, tig = lane & 3;
        const int mt = wid >> 1, nh = wid & 1;
        const int m0 = mt * 16;
        float acc[4][4];
        #pragma unroll
        for (int i = 0; i < 4; i++) { acc[i][0] = acc[i][1] = acc[i][2] = acc[i][3] = 0.f; }

        #pragma unroll
        for (int kk = 0; kk < 8; kk++) {
            const float* ap = As + (m0 + gid) * 196 + kk * 8 + tig;
            uint32_t hi[4] = { f2tf32v(ap[0]), f2tf32v(ap[8 * 196]),
                               f2tf32v(ap[4]), f2tf32v(ap[8 * 196 + 4]) };
            #pragma unroll
            for (int j = 0; j < 4; j++) {
                int nt = nh * 4 + j;
                const uint32_t* bp = Ws + (kk * 8 + tig) * 72 + nt * 8 + gid;
                uint32_t bf[2] = { bp[0], bp[4 * 72] };
                mma_tf32(acc[j], hi, bf);
            }
        }
        #pragma unroll 4
        for (int kk = 8; kk < 24; kk++) {
            const float* ap = As + (m0 + gid) * 196 + kk * 8 + tig;
            float af[4] = { ap[0], ap[8 * 196], ap[4], ap[8 * 196 + 4] };
            uint32_t hi[4], lo[4];
            #pragma unroll
            for (int e = 0; e < 4; e++) {
                hi[e] = f2tf32v(af[e]);
                lo[e] = f2tf32v(af[e] - __uint_as_float(hi[e]));
            }
            #pragma unroll
            for (int j = 0; j < 4; j++) {
                int nt = nh * 4 + j;
                const uint32_t* bp = Ws + (kk * 8 + tig) * 72 + nt * 8 + gid;
                uint32_t bf[2] = { bp[0], bp[4 * 72] };
                mma_tf32(acc[j], hi, bf);
                mma_tf32(acc[j], lo, bf);
            }
        }

        #pragma unroll
        for (int j = 0; j < 4; j++) {
            int g = (nh * 4 + j) * 8 + tig * 2;
            float b0 = bias[g], b1 = bias[g + 1];
            int n_lo = m0 + gid, n_hi = m0 + gid + 8;
            if (n_lo < N_NODES) {
                float v0 = roundtf(fmaxf(acc[j][0] + b0, 0.f));
                float v1 = roundtf(fmaxf(acc[j][1] + b1, 0.f));
                *(float2*)&out[base + (size_t)n_lo * 64 + g] = make_float2(v0, v1);
            }
            if (n_hi < N_NODES) {
                float v0 = roundtf(fmaxf(acc[j][2] + b0, 0.f));
                float v1 = roundtf(fmaxf(acc[j][3] + b1, 0.f));
                *(float2*)&out[base + (size_t)n_hi * 64 + g] = make_float2(v0, v1);
            }
        }
    }
}

// ---------------- BatchNorm over node channel (in-place, float4, 1024 thr) ----------------
template<int C, bool RND>
__global__ void __launch_bounds__(1024, 1)
bn_kernel(float* __restrict__ x, const float* __restrict__ gamma,
          const float* __restrict__ beta, int BT, int N)
{
    constexpr int C4 = C / 4;
    const int n   = blockIdx.x;
    const int tid = threadIdx.x;  // 1024
    const int M4  = BT * C4;
    float4* x4 = (float4*)x;
    float s = 0.f, s2 = 0.f;
    for (int i = tid; i < M4; i += 1024) {
        int bt = i / C4, c4 = i % C4;
        float4 v = x4[((size_t)bt * N + n) * C4 + c4];
        s  += v.x + v.y + v.z + v.w;
        s2 += v.x * v.x + v.y * v.y + v.z * v.z + v.w * v.w;
    }
    __shared__ float rs[1024], rs2[1024];
    __shared__ float mean_s, istd_s;
    rs[tid] = s; rs2[tid] = s2;
    __syncthreads();
    for (int o = 512; o > 0; o >>= 1) {
        if (tid < o) { rs[tid] += rs[tid + o]; rs2[tid] += rs2[tid + o]; }
        __syncthreads();
    }
    if (tid == 0) {
        float inv = 1.f / (float)(BT * C);
        float mean = rs[0] * inv;
        float var  = rs2[0] * inv - mean * mean;
        mean_s = mean;
        istd_s = rsqrtf(var + 1e-5f);
    }
    __syncthreads();
    const float gm = gamma[n], bt_ = beta[n];
    const float mean = mean_s, istd = istd_s;
    for (int i = tid; i < M4; i += 1024) {
        int bt = i / C4, c4 = i % C4;
        size_t a = ((size_t)bt * N + n) * C4 + c4;
        float4 v = x4[a];
        v.x = (v.x - mean) * istd * gm + bt_;
        v.y = (v.y - mean) * istd * gm + bt_;
        v.z = (v.z - mean) * istd * gm + bt_;
        v.w = (v.w - mean) * istd * gm + bt_;
        if (RND) { v.x = roundtf(v.x); v.y = roundtf(v.y); v.z = roundtf(v.z); v.w = roundtf(v.w); }
        x4[a] = v;
    }
}

// ---------------- Fused BN(C=16) + FC: out = BN(x) @ fc_w + fc_b (512 thr) ----------------
__global__ void __launch_bounds__(512, 2)
bnfc_kernel(const float* __restrict__ x, const float* __restrict__ gamma,
            const float* __restrict__ beta, const float* __restrict__ fw,
            const float* __restrict__ fb, float* __restrict__ out,
            int BT, int N)
{
    const int n   = blockIdx.x;
    const int tid = threadIdx.x;  // 512
    const int M4  = BT * 4;
    const float4* x4 = (const float4*)x;

    __shared__ float fws[48];
    __shared__ float fbs[3];
    if (tid < 48) fws[tid] = fw[tid];
    if (tid < 3)  fbs[tid] = fb[tid];

    float s = 0.f, s2 = 0.f;
    for (int i = tid; i < M4; i += 512) {
        int bt = i >> 2, c4 = i & 3;
        float4 v = x4[((size_t)bt * N + n) * 4 + c4];
        s  += v.x + v.y + v.z + v.w;
        s2 += v.x * v.x + v.y * v.y + v.z * v.z + v.w * v.w;
    }
    __shared__ float rs[512], rs2[512];
    __shared__ float mean_s, istd_s;
    rs[tid] = s; rs2[tid] = s2;
    __syncthreads();
    for (int o = 256; o > 0; o >>= 1) {
        if (tid < o) { rs[tid] += rs[tid + o]; rs2[tid] += rs2[tid + o]; }
        __syncthreads();
    }
    if (tid == 0) {
        float inv = 1.f / (float)(BT * 16);
        float mean = rs[0] * inv;
        float var  = rs2[0] * inv - mean * mean;
        mean_s = mean;
        istd_s = rsqrtf(var + 1e-5f);
    }
    __syncthreads();
    const float gm = gamma[n], bt_ = beta[n];
    const float mean = mean_s, istd = istd_s;

    for (int bt = tid; bt < BT; bt += 512) {
        const float4* row = &x4[((size_t)bt * N + n) * 4];
        float o0 = fbs[0], o1 = fbs[1], o2 = fbs[2];
        #pragma unroll
        for (int c4 = 0; c4 < 4; c4++) {
            float4 v = row[c4];
            float h0 = (v.x - mean) * istd * gm + bt_;
            float h1 = (v.y - mean) * istd * gm + bt_;
            float h2 = (v.z - mean) * istd * gm + bt_;
            float h3 = (v.w - mean) * istd * gm + bt_;
            int c = c4 * 4;
            o0 = fmaf(h0, fws[(c + 0) * 3 + 0], o0); o1 = fmaf(h0, fws[(c + 0) * 3 + 1], o1); o2 = fmaf(h0, fws[(c + 0) * 3 + 2], o2);
            o0 = fmaf(h1, fws[(c + 1) * 3 + 0], o0); o1 = fmaf(h1, fws[(c + 1) * 3 + 1], o1); o2 = fmaf(h1, fws[(c + 1) * 3 + 2], o2);
            o0 = fmaf(h2, fws[(c + 2) * 3 + 0], o0); o1 = fmaf(h2, fws[(c + 2) * 3 + 1], o1); o2 = fmaf(h2, fws[(c + 2) * 3 + 2], o2);
            o0 = fmaf(h3, fws[(c + 3) * 3 + 0], o0); o1 = fmaf(h3, fws[(c + 3) * 3 + 1], o1); o2 = fmaf(h3, fws[(c + 3) * 3 + 2], o2);
        }
        size_t r = (size_t)bt * N + n;
        out[r * 3 + 0] = o0;
        out[r * 3 + 1] = o1;
        out[r * 3 + 2] = o2;
    }
}

// ---------------- Launch ----------------
extern "C" void kernel_launch(void* const* d_in, const int* in_sizes, int n_in,
                              void* d_out, int out_size)
{
    const float* x        = (const float*)d_in[0];
    const int*   eidx     = (const int*)d_in[1];
    const float* eattr    = (const float*)d_in[2];
    const float* b1_t1_w  = (const float*)d_in[3];
    const float* b1_t1_b  = (const float*)d_in[4];
    const float* b1_ch_w  = (const float*)d_in[5];
    const float* b1_ch_b  = (const float*)d_in[6];
    const float* b1_t2_w  = (const float*)d_in[7];
    const float* b1_t2_b  = (const float*)d_in[8];
    const float* b1_bn_g  = (const float*)d_in[9];
    const float* b1_bn_b  = (const float*)d_in[10];
    const float* b2_t1_w  = (const float*)d_in[11];
    const float* b2_t1_b  = (const float*)d_in[12];
    const float* b2_ch_w  = (const float*)d_in[13];
    const float* b2_ch_b  = (const float*)d_in[14];
    const float* b2_t2_w  = (const float*)d_in[15];
    const float* b2_t2_b  = (const float*)d_in[16];
    const float* b2_bn_g  = (const float*)d_in[17];
    const float* b2_bn_b  = (const float*)d_in[18];
    const float* fc_w     = (const float*)d_in[19];
    const float* fc_b     = (const float*)d_in[20];

    float *bufA, *bufB, *bufC, *nrm, *xpad;
    int *rowptr, *cols; uint32_t *wt, *bp;
    cudaGetSymbolAddress((void**)&bufA,  g_bufA);
    cudaGetSymbolAddress((void**)&bufB,  g_bufB);
    cudaGetSymbolAddress((void**)&bufC,  g_bufC);
    cudaGetSymbolAddress((void**)&xpad,  g_xpad);
    cudaGetSymbolAddress((void**)&rowptr, g_rowptr);
    cudaGetSymbolAddress((void**)&cols,  g_cols);
    cudaGetSymbolAddress((void**)&nrm,   g_norm);
    cudaGetSymbolAddress((void**)&wt,    g_wt);
    cudaGetSymbolAddress((void**)&bp,    g_bp);

    const int N = N_NODES;

    // instantiations:           Cin CINP Cout Kt Tin Tout TP NG KSUB CO  ACP  MINB
    auto k_b1t2 = tconv_mma<64, 64, 128, 9, 56, 48, 48, 4, 64, 32, true, 2>;  // 6 warps, 2 blk/SM
    auto k_b2t1 = tconv_mma<128, 128, 64, 5, 48, 44, 48, 6, 64, 32, true, 1>; // 9 warps, 1 blk/SM
    auto k_b2t2 = tconv_mma<64, 64, 16, 5, 44, 40, 48, 4, 64, 16, true, 2>;   // 6 warps, 2 blk/SM

    const int sm_t1c  = (4 * 72 * 20 + 144 * 104) * 4;       // 82,944
    const int sm_b1t2 = (4 * 56 * 68 + 2 * 64 * 104) * 4;    // 114,176
    const int sm_b2t1 = (6 * 52 * 132 + 2 * 64 * 104) * 4;   // 217,984
    const int sm_b2t2 = (4 * 52 * 68 + 2 * 64 * 56) * 4;     // 85,248
    const int sm_cheb = (224 * 196 + 192 * 72) * 4;          // 230,912

    cudaFuncSetAttribute(t1conv_kernel, cudaFuncAttributeMaxDynamicSharedMemorySize, sm_t1c);
    cudaFuncSetAttribute(k_b1t2, cudaFuncAttributeMaxDynamicSharedMemorySize, sm_b1t2);
    cudaFuncSetAttribute(k_b2t1, cudaFuncAttributeMaxDynamicSharedMemorySize, sm_b2t1);
    cudaFuncSetAttribute(k_b2t2, cudaFuncAttributeMaxDynamicSharedMemorySize, sm_b2t2);
    cudaFuncSetAttribute(cheb_mma_kernel, cudaFuncAttributeMaxDynamicSharedMemorySize, sm_cheb);

    // ---- prep ----
    build_csr_kernel<<<1, 256>>>(eidx, eattr, rowptr, cols, nrm);
    wconv_kernel<<<(387072 + 255) / 256, 256>>>(b1_t1_w, b1_t2_w, b2_t1_w, b2_t2_w, wt);
    bp_build_kernel<<<(2 * 13824 + 255) / 256, 256>>>(b1_ch_w, b2_ch_w);
    xpad_kernel<<<1184, 512>>>(x);

    // ======== Block 1 ========
    t1conv_kernel<<<dim3(53, BATCH), 256, sm_t1c>>>(xpad, wt + WOFF1, b1_t1_b, bufA);
    cheb_mma_kernel<<<32 * 56, 1024, sm_cheb>>>(bufA, bp, b1_ch_b, bufB, rowptr, cols, nrm);
    k_b1t2<<<dim3(53, BATCH), 192, sm_b1t2>>>(bufB, wt + WOFF2, b1_t2_b, bufC);
    bn_kernel<128, true><<<N, 1024>>>(bufC, b1_bn_g, b1_bn_b, 32 * 48, N);

    // ======== Block 2 ========
    k_b2t1<<<dim3(35, BATCH), 288, sm_b2t1>>>(bufC, wt + WOFF3, b2_t1_b, bufA);
    cheb_mma_kernel<<<32 * 44, 1024, sm_cheb>>>(bufA, bp + 13824, b2_ch_b, bufB, rowptr, cols, nrm);
    k_b2t2<<<dim3(53, BATCH), 192, sm_b2t2>>>(bufB, wt + WOFF4, b2_t2_b, bufC);

    // ---- fused BN2 + FC ----
    bnfc_kernel<<<N, 512>>>(bufC, b2_bn_g, b2_bn_b, fc_w, fc_b, (float*)d_out, 32 * 40, N);

    (void)in_sizes; (void)n_in; (void)out_size;
}

// round 17
// speedup vs baseline: 1.7445x; 1.0491x over previous
#include <cuda_runtime.h>
#include <cuda_bf16.h>
#include <cstdint>

// ---------------- Problem constants ----------------
#define N_NODES 210
#define N_EDGES 4200
#define BATCH   32

// ---------------- Static device scratch ----------------
__device__ float    g_bufA[32ll * 56 * 210 * 64];   // 24.08M floats
__device__ float    g_bufB[32ll * 56 * 210 * 64];
__device__ float    g_bufC[32ll * 48 * 210 * 128];  // 41.29M floats
__device__ float    g_xpad[32ll * 64 * 210 * 16];   // padded tf32-rounded input (6.88M)
__device__ int      g_rowptr[N_NODES + 1];
__device__ int      g_cols[N_EDGES];
__device__ float    g_norm[N_EDGES];
__device__ uint32_t g_wt[387072];                   // tf32 tconv weights
__device__ uint32_t g_bp[2 * 13824];                // folded cheb W images (192x72) x2

// region offsets in g_wt
#define WOFF1 0        // b1_t1 padded (3,9,16,64)   = 27648
#define WOFF2 27648    // b1_t2        (3,9,64,128)  = 221184
#define WOFF3 248832   // b2_t1        (3,5,128,64)  = 122880
#define WOFF4 371712   // b2_t2        (3,5,64,16)   = 15360

// ---------------- helpers ----------------
__device__ __forceinline__ uint32_t f2tf32v(float x) {
    uint32_t r; asm("cvt.rna.tf32.f32 %0, %1;" : "=r"(r) : "f"(x)); return r;
}
__device__ __forceinline__ float roundtf(float x) {
    return __uint_as_float(f2tf32v(x));
}
__device__ __forceinline__ void mma_tf32(float c[4], const uint32_t a[4], const uint32_t b[2]) {
    asm volatile("mma.sync.aligned.m16n8k8.row.col.f32.tf32.tf32.f32 "
        "{%0,%1,%2,%3}, {%4,%5,%6,%7}, {%8,%9}, {%0,%1,%2,%3};"
        : "+f"(c[0]), "+f"(c[1]), "+f"(c[2]), "+f"(c[3])
        : "r"(a[0]), "r"(a[1]), "r"(a[2]), "r"(a[3]), "r"(b[0]), "r"(b[1]));
}
__device__ __forceinline__ uint32_t sptr(const void* p) {
    return (uint32_t)__cvta_generic_to_shared(p);
}
__device__ __forceinline__ void cpa16(uint32_t dst, const void* src, int sz) {
    asm volatile("cp.async.cg.shared.global [%0], [%1], 16, %2;"
                 :: "r"(dst), "l"(src), "r"(sz));
}
__device__ __forceinline__ void cpa_commit() { asm volatile("cp.async.commit_group;"); }
__device__ __forceinline__ void cpa_waitall() { asm volatile("cp.async.wait_group 0;"); }
__device__ __forceinline__ void cpa_wait1()  { asm volatile("cp.async.wait_group 1;"); }

// ---------------- Input pad prepass: x (B,64,210,14) -> xpad (B,64,210,16) tf32 ----------------
__global__ void xpad_kernel(const float* __restrict__ x)
{
    const int total = 32 * 64 * 210 * 16;
    for (int i = blockIdx.x * blockDim.x + threadIdx.x; i < total; i += gridDim.x * blockDim.x) {
        int c = i & 15;
        int r = i >> 4;          // (b*64+t)*210+n
        float v = (c < 14) ? roundtf(x[(size_t)r * 14 + c]) : 0.f;
        g_xpad[i] = v;
    }
}

// ---------------- Weight prepass: fp32 -> tf32 (padded for b1_t1) ----------------
__global__ void wconv_kernel(const float* __restrict__ w1, const float* __restrict__ w2,
                             const float* __restrict__ w3, const float* __restrict__ w4,
                             uint32_t* __restrict__ out)
{
    int i = blockIdx.x * blockDim.x + threadIdx.x;
    if (i < 27648) {  // b1_t1 padded: (g,k,ci<16,co<64); src (3,1,9,14,64)
        int co = i & 63; int r = i >> 6;
        int ci = r % 16; r /= 16;
        int k = r % 9;  int g = r / 9;
        float v = (ci < 14) ? w1[((g * 9 + k) * 14 + ci) * 64 + co] : 0.f;
        out[i] = f2tf32v(v);
        return;
    }
    int j = i - WOFF2;
    if (j >= 0 && j < 221184) { out[i] = f2tf32v(w2[j]); return; }
    j = i - WOFF3;
    if (j >= 0 && j < 122880) { out[i] = f2tf32v(w3[j]); return; }
    j = i - WOFF4;
    if (j >= 0 && j < 15360)  { out[i] = f2tf32v(w4[j]); return; }
}

// ---------------- Folded cheb W images: [W0-W2 ; W1 ; 2*W2] tf32, stride 72 ----------------
__global__ void bp_build_kernel(const float* __restrict__ W1, const float* __restrict__ W2)
{
    int i = blockIdx.x * blockDim.x + threadIdx.x;
    if (i >= 2 * 13824) return;
    int which = i / 13824, r = i % 13824;
    int row = r / 72, g = r % 72;
    int term = row >> 6, h = row & 63;
    const float* W = which ? W2 : W1;
    float v = 0.f;
    if (g < 64) {
        if (term == 0)      v = W[h * 64 + g] - W[2 * 4096 + h * 64 + g];
        else if (term == 1) v = W[4096 + h * 64 + g];
        else                v = 2.f * W[2 * 4096 + h * 64 + g];
    }
    g_bp[i] = f2tf32v(v);
}

// ---------------- CSR build (deterministic, 1 block) ----------------
__global__ void build_csr_kernel(const int* __restrict__ edge_index,
                                 const float* __restrict__ eattr,
                                 int* __restrict__ rowptr,
                                 int* __restrict__ cols,
                                 float* __restrict__ norms)
{
    __shared__ int   row_s[N_EDGES];
    __shared__ short col_s[N_EDGES];
    __shared__ float attr_s[N_EDGES];
    __shared__ int   cnt_s[N_NODES + 1];
    __shared__ float dis_s[N_NODES];

    const int tid = threadIdx.x;  // 256
    for (int i = tid; i < N_EDGES; i += 256) {
        row_s[i]  = edge_index[i];
        col_s[i]  = (short)edge_index[N_EDGES + i];
        attr_s[i] = eattr[i];
    }
    __syncthreads();

    if (tid < N_NODES) {
        float deg = 0.f; int cnt = 0;
        for (int e = 0; e < N_EDGES; e++) {
            if (row_s[e] == tid) { deg += attr_s[e]; cnt++; }
        }
        cnt_s[tid] = cnt;
        dis_s[tid] = (deg > 0.f) ? rsqrtf(deg) : 0.f;
    }
    __syncthreads();
    if (tid == 0) {
        int acc = 0;
        for (int n = 0; n < N_NODES; n++) { int c = cnt_s[n]; cnt_s[n] = acc; acc += c; }
        cnt_s[N_NODES] = acc;
    }
    __syncthreads();
    if (tid <= N_NODES) rowptr[tid] = cnt_s[tid];
    if (tid < N_NODES) {
        int wpos = cnt_s[tid];
        const float disr = dis_s[tid];
        for (int e = 0; e < N_EDGES; e++) {
            if (row_s[e] == tid) {
                int c = col_s[e];
                cols[wpos]  = c;
                norms[wpos] = -disr * attr_s[e] * dis_s[c];
                wpos++;
            }
        }
    }
}

// ---------------- b1_t1 dedicated kernel: all weights smem-resident, 2 stages ----------------
__global__ void __launch_bounds__(256, 2)
t1conv_kernel(const float* __restrict__ x, const uint32_t* __restrict__ wt,
              const float* __restrict__ bias, float* __restrict__ out)
{
    extern __shared__ uint32_t sh[];
    uint32_t* As = sh;            // 4*72*20 = 5760
    uint32_t* Bs = sh + 5760;     // 144*104 = 14976

    const int n0  = blockIdx.x * 4;
    const int b   = blockIdx.y;
    const int tid = threadIdx.x;
    const int wid = tid >> 5, lane = tid & 31;
    const int gid = lane >> 2, tig = lane & 3;

    const int tile0 = 2 * wid, tile1 = 2 * wid + 1;
    const int nl0 = tile0 >> 2, nl1 = tile1 >> 2;
    const int t00 = (tile0 & 3) * 16, t01 = (tile1 & 3) * 16;

    for (int i = tid; i < 4 * 72 * 4; i += 256) {
        int nlx = i / (72 * 4);
        int r   = i % (72 * 4);
        int tp = r >> 2, c4 = r & 3;
        int nn = n0 + nlx;
        bool ok = (nn < N_NODES) && (tp < 64);
        const float* src = x + ((size_t)(b * 64 + (ok ? tp : 0)) * N_NODES
                                + (nn < N_NODES ? nn : 0)) * 16 + c4 * 4;
        cpa16(sptr(As + nlx * 72 * 20 + tp * 20 + c4 * 4), src, ok ? 16 : 0);
    }

    auto stageB = [&](int cc) {
        for (int i = tid; i < 144 * 24; i += 256) {
            int cil = i / 24;
            int rr  = i % 24;
            int g = rr >> 3, c4 = rr & 7;
            const uint32_t* src = wt + ((size_t)g * 144 + cil) * 64 + cc * 32 + c4 * 4;
            cpa16(sptr(Bs + cil * 104 + g * 32 + c4 * 4), src, 16);
        }
    };

    stageB(0);
    cpa_commit();

    const uint32_t* A0 = As + nl0 * 72 * 20;
    const uint32_t* A1 = As + nl1 * 72 * 20;

    #pragma unroll 1
    for (int cc = 0; cc < 2; cc++) {
        if (cc) {
            __syncthreads();
            stageB(1);
            cpa_commit();
        }
        cpa_waitall();
        __syncthreads();

        float acc[2][12][4];
        #pragma unroll
        for (int m = 0; m < 2; m++)
            #pragma unroll
            for (int i = 0; i < 12; i++) { acc[m][i][0] = acc[m][i][1] = acc[m][i][2] = acc[m][i][3] = 0.f; }

        #pragma unroll 1
        for (int k = 0; k < 9; k++) {
            #pragma unroll
            for (int kk = 0; kk < 2; kk++) {
                uint32_t a0[4], a1[4];
                {
                    const uint32_t* ap = A0 + (t00 + gid + k) * 20 + kk * 8 + tig;
                    a0[0] = ap[0]; a0[1] = ap[8 * 20]; a0[2] = ap[4]; a0[3] = ap[8 * 20 + 4];
                }
                {
                    const uint32_t* ap = A1 + (t01 + gid + k) * 20 + kk * 8 + tig;
                    a1[0] = ap[0]; a1[1] = ap[8 * 20]; a1[2] = ap[4]; a1[3] = ap[8 * 20 + 4];
                }
                const int brow = k * 16 + kk * 8 + tig;
                #pragma unroll
                for (int nt = 0; nt < 12; nt++) {
                    const uint32_t* bp = Bs + brow * 104 + nt * 8 + gid;
                    uint32_t bf[2] = { bp[0], bp[4 * 104] };
                    mma_tf32(acc[0][nt], a0, bf);
                    mma_tf32(acc[1][nt], a1, bf);
                }
            }
        }

        const int nls[2] = { nl0, nl1 };
        const int t0s[2] = { t00, t01 };
        #pragma unroll
        for (int m = 0; m < 2; m++) {
            const int n = n0 + nls[m];
            if (n < N_NODES) {
                #pragma unroll
                for (int nt3 = 0; nt3 < 4; nt3++) {
                    int co = cc * 32 + nt3 * 8 + tig * 2;
                    float bP0 = bias[co],       bP1 = bias[co + 1];
                    float bQ0 = bias[64 + co],  bQ1 = bias[64 + co + 1];
                    float bR0 = bias[128 + co], bR1 = bias[128 + co + 1];
                    #pragma unroll
                    for (int half = 0; half < 2; half++) {
                        int t = t0s[m] + gid + half * 8;
                        if (t < 56) {
                            int i0 = half * 2;
                            float P0 = acc[m][nt3][i0] + bP0;
                            float P1 = acc[m][nt3][i0 + 1] + bP1;
                            float Q0 = acc[m][nt3 + 4][i0] + bQ0;
                            float Q1 = acc[m][nt3 + 4][i0 + 1] + bQ1;
                            float R0 = acc[m][nt3 + 8][i0] + bR0;
                            float R1 = acc[m][nt3 + 8][i0 + 1] + bR1;
                            float v0 = fmaxf(fmaf(P0, 1.f / (1.f + __expf(-Q0)), R0), 0.f);
                            float v1 = fmaxf(fmaf(P1, 1.f / (1.f + __expf(-Q1)), R1), 0.f);
                            *(float2*)&out[((size_t)(b * 56 + t) * N_NODES + n) * 64 + co] =
                                make_float2(v0, v1);
                        }
                    }
                }
            }
        }
    }
}

// ---------------- b2_t1 dedicated kernel: K-split A slab -> 2 blocks/SM ----------------
// x (B,48,210,128) -> out (B,44,210,64). Schedule (cc,h): (0,0),(0,1),(1,1),(1,0).
__global__ void __launch_bounds__(192, 2)
b2t1_kernel(const float* __restrict__ x, const uint32_t* __restrict__ wt,
            const float* __restrict__ bias, float* __restrict__ out)
{
    // NG=4, TP=48, XS=52, SA=68 (64ch half + 4), CO=32, COLS=96, SB=104, NT=12
    extern __shared__ uint32_t sh[];
    uint32_t* As = sh;            // 4*52*68 = 14144
    uint32_t* Bs = sh + 14144;    // 2 * 64*104 = 13312

    const int n0  = blockIdx.x * 4;
    const int b   = blockIdx.y;
    const int tid = threadIdx.x;  // 192
    const int wid = tid >> 5, lane = tid & 31;
    const int gid = lane >> 2, tig = lane & 3;

    const int tile0 = 2 * wid, tile1 = 2 * wid + 1;   // MTN=3
    const int nl0 = tile0 / 3, nl1 = tile1 / 3;
    const int t00 = (tile0 % 3) * 16, t01 = (tile1 % 3) * 16;

    // stage A slab for channel half h (64 channels)
    auto stageA = [&](int h) {
        for (int i = tid; i < 4 * 52 * 16; i += 192) {
            int nlx = i / (52 * 16);
            int r   = i % (52 * 16);
            int tp = r >> 4, c4 = r & 15;
            int nn = n0 + nlx;
            bool ok = (nn < N_NODES) && (tp < 48);
            const float* src = x + ((size_t)(b * 48 + (ok ? tp : 0)) * N_NODES
                                    + (nn < N_NODES ? nn : 0)) * 128 + h * 64 + c4 * 4;
            cpa16(sptr(As + nlx * 52 * 68 + tp * 68 + c4 * 4), src, ok ? 16 : 0);
        }
    };
    // stage B chunk: (cc, k, h) -> 64 rows x 96 cols into buf
    auto stageB = [&](int cc, int k, int h, int buf) {
        for (int i = tid; i < 64 * 24; i += 192) {
            int cil = i / 24;
            int rr  = i % 24;
            int g = rr >> 3, c4 = rr & 7;
            const uint32_t* src = wt + ((size_t)(g * 5 + k) * 128 + h * 64 + cil) * 64
                                     + cc * 32 + c4 * 4;
            cpa16(sptr(Bs + buf * 6656 + cil * 104 + g * 32 + c4 * 4), src, 16);
        }
    };

    const int SCC[4] = { 0, 0, 1, 1 };
    const int SHH[4] = { 0, 1, 1, 0 };

    stageA(0);
    stageB(0, 0, 0, 0);
    cpa_commit();

    const uint32_t* A0 = As + nl0 * 52 * 68;
    const uint32_t* A1 = As + nl1 * 52 * 68;

    float acc[2][12][4];
    #pragma unroll
    for (int m = 0; m < 2; m++)
        #pragma unroll
        for (int i = 0; i < 12; i++) { acc[m][i][0] = acc[m][i][1] = acc[m][i][2] = acc[m][i][3] = 0.f; }

    int it = 0;
    #pragma unroll 1
    for (int s = 0; s < 4; s++) {
        const int cc = SCC[s];
        #pragma unroll 1
        for (int k = 0; k < 5; k++) {
            cpa_waitall();
            __syncthreads();
            int nit = it + 1;
            if (nit < 20) {
                int ns = nit / 5, nk = nit % 5;
                stageB(SCC[ns], nk, SHH[ns], nit & 1);
                cpa_commit();
            }
            const uint32_t* Bb = Bs + (it & 1) * 6656;
            #pragma unroll
            for (int kk = 0; kk < 8; kk++) {
                uint32_t a0[4], a1[4];
                {
                    const uint32_t* ap = A0 + (t00 + gid + k) * 68 + kk * 8 + tig;
                    a0[0] = ap[0]; a0[1] = ap[8 * 68]; a0[2] = ap[4]; a0[3] = ap[8 * 68 + 4];
                }
                {
                    const uint32_t* ap = A1 + (t01 + gid + k) * 68 + kk * 8 + tig;
                    a1[0] = ap[0]; a1[1] = ap[8 * 68]; a1[2] = ap[4]; a1[3] = ap[8 * 68 + 4];
                }
                #pragma unroll
                for (int nt = 0; nt < 12; nt++) {
                    const uint32_t* bp = Bb + (kk * 8 + tig) * 104 + nt * 8 + gid;
                    uint32_t bf[2] = { bp[0], bp[4 * 104] };
                    mma_tf32(acc[0][nt], a0, bf);
                    mma_tf32(acc[1][nt], a1, bf);
                }
            }
            it++;
        }

        if (s == 1 || s == 3) {
            // epilogue for co-chunk cc (both k-halves done)
            const int nls[2] = { nl0, nl1 };
            const int t0s[2] = { t00, t01 };
            #pragma unroll
            for (int m = 0; m < 2; m++) {
                const int n = n0 + nls[m];
                if (n < N_NODES) {
                    #pragma unroll
                    for (int nt3 = 0; nt3 < 4; nt3++) {
                        int co = cc * 32 + nt3 * 8 + tig * 2;
                        float bP0 = bias[co],       bP1 = bias[co + 1];
                        float bQ0 = bias[64 + co],  bQ1 = bias[64 + co + 1];
                        float bR0 = bias[128 + co], bR1 = bias[128 + co + 1];
                        #pragma unroll
                        for (int half = 0; half < 2; half++) {
                            int t = t0s[m] + gid + half * 8;
                            if (t < 44) {
                                int i0 = half * 2;
                                float P0 = acc[m][nt3][i0] + bP0;
                                float P1 = acc[m][nt3][i0 + 1] + bP1;
                                float Q0 = acc[m][nt3 + 4][i0] + bQ0;
                                float Q1 = acc[m][nt3 + 4][i0 + 1] + bQ1;
                                float R0 = acc[m][nt3 + 8][i0] + bR0;
                                float R1 = acc[m][nt3 + 8][i0 + 1] + bR1;
                                float v0 = fmaxf(fmaf(P0, 1.f / (1.f + __expf(-Q0)), R0), 0.f);
                                float v1 = fmaxf(fmaf(P1, 1.f / (1.f + __expf(-Q1)), R1), 0.f);
                                *(float2*)&out[((size_t)(b * 44 + t) * N_NODES + n) * 64 + co] =
                                    make_float2(v0, v1);
                            }
                        }
                    }
                }
            }
            #pragma unroll
            for (int m = 0; m < 2; m++)
                #pragma unroll
                for (int i = 0; i < 12; i++) { acc[m][i][0] = acc[m][i][1] = acc[m][i][2] = acc[m][i][3] = 0.f; }
        }

        if (s < 3 && SHH[s + 1] != SHH[s]) {
            __syncthreads();          // all MMA reads of A(h) complete
            stageA(SHH[s + 1]);
            cpa_commit();
        }
    }
}

// ---------------- Gated temporal conv via tf32 mma.sync (generic) ----------------
template<int Cin, int CINP, int Cout, int Kt, int Tin, int Tout, int TP, int NG,
         int KSUB, int CO, bool ACP, int MINB>
__global__ void __launch_bounds__((NG * (TP / 16) / 2) * 32, MINB)
tconv_mma(const float* __restrict__ x, const uint32_t* __restrict__ wt,
          const float* __restrict__ bias, float* __restrict__ out)
{
    constexpr int MTN   = TP / 16;
    constexpr int TILES = NG * MTN;
    constexpr int NW    = TILES / 2;
    constexpr int THREADS = NW * 32;
    constexpr int XS    = TP + Kt - 1;
    constexpr int SA    = CINP + 4;
    constexpr int COLS  = 3 * CO;
    constexpr int SB    = COLS + 8;
    constexpr int NT    = COLS / 8;
    constexpr int COCH  = Cout / CO;
    constexpr int NKS   = CINP / KSUB;
    constexpr int KPI   = Kt * NKS;
    constexpr int ITERS = COCH * KPI;
    constexpr int BUFSZ = KSUB * SB;
    constexpr int CO4   = CO / 4;
    static_assert(TILES % 2 == 0, "even tiles");

    extern __shared__ uint32_t sh[];
    uint32_t* As = sh;
    uint32_t* Bs = sh + NG * XS * SA;

    const int n0  = blockIdx.x * NG;
    const int b   = blockIdx.y;
    const int tid = threadIdx.x;
    const int wid = tid >> 5, lane = tid & 31;
    const int gid = lane >> 2, tig = lane & 3;

    const int tile0 = 2 * wid, tile1 = 2 * wid + 1;
    const int nl[2]  = { tile0 / MTN, tile1 / MTN };
    const int t0s[2] = { (tile0 % MTN) * 16, (tile1 % MTN) * 16 };

    if (ACP) {
        constexpr int C4 = CINP / 4;
        for (int i = tid; i < NG * XS * C4; i += THREADS) {
            int nlx = i / (XS * C4);
            int r   = i % (XS * C4);
            int tp = r / C4, c4 = r % C4;
            int nn = n0 + nlx;
            bool ok = (nn < N_NODES) && (tp < Tin);
            const float* src = x + ((size_t)(b * Tin + (ok ? tp : 0)) * N_NODES
                                    + (nn < N_NODES ? nn : 0)) * Cin + c4 * 4;
            cpa16(sptr(As + nlx * XS * SA + tp * SA + c4 * 4), src, ok ? 16 : 0);
        }
    } else {
        for (int i = tid; i < NG * XS * CINP; i += THREADS) {
            int nlx = i / (XS * CINP);
            int r   = i % (XS * CINP);
            int tp = r / CINP, ci = r % CINP;
            int nn = n0 + nlx;
            float v = 0.f;
            if (nn < N_NODES && tp < Tin && ci < Cin)
                v = x[((size_t)(b * Tin + tp) * N_NODES + nn) * Cin + ci];
            As[nlx * XS * SA + tp * SA + ci] = f2tf32v(v);
        }
    }

    auto stageB = [&](int it) {
        int cc = it / KPI, r = it % KPI, k = r / NKS, ks = r % NKS;
        uint32_t* Bb = Bs + (it & 1) * BUFSZ;
        for (int i = tid; i < KSUB * 3 * CO4; i += THREADS) {
            int cil = i / (3 * CO4);
            int rr  = i % (3 * CO4);
            int g   = rr / CO4, c4 = rr % CO4;
            const uint32_t* src = wt + ((size_t)(g * Kt + k) * CINP + ks * KSUB + cil) * Cout
                                     + cc * CO + c4 * 4;
            cpa16(sptr(Bb + cil * SB + g * CO + c4 * 4), src, 16);
        }
    };

    stageB(0);
    cpa_commit();

    const uint32_t* A0 = As + nl[0] * XS * SA;
    const uint32_t* A1 = As + nl[1] * XS * SA;

    float acc[2][NT][4];
    #pragma unroll
    for (int m = 0; m < 2; m++)
        #pragma unroll
        for (int i = 0; i < NT; i++) { acc[m][i][0] = acc[m][i][1] = acc[m][i][2] = acc[m][i][3] = 0.f; }

    #pragma unroll 1
    for (int it = 0; it < ITERS; ++it) {
        cpa_waitall();
        __syncthreads();
        if (it + 1 < ITERS) { stageB(it + 1); cpa_commit(); }

        const int r = it % KPI, k = r / NKS, ks = r % NKS;
        const uint32_t* Bb = Bs + (it & 1) * BUFSZ;
        #pragma unroll
        for (int kk = 0; kk < KSUB / 8; kk++) {
            uint32_t a0[4], a1[4];
            {
                const uint32_t* ap = A0 + (t0s[0] + gid + k) * SA + ks * KSUB + kk * 8 + tig;
                a0[0] = ap[0]; a0[1] = ap[8 * SA]; a0[2] = ap[4]; a0[3] = ap[8 * SA + 4];
            }
            {
                const uint32_t* ap = A1 + (t0s[1] + gid + k) * SA + ks * KSUB + kk * 8 + tig;
                a1[0] = ap[0]; a1[1] = ap[8 * SA]; a1[2] = ap[4]; a1[3] = ap[8 * SA + 4];
            }
            #pragma unroll
            for (int nt = 0; nt < NT; nt++) {
                const uint32_t* bp = Bb + (kk * 8 + tig) * SB + nt * 8 + gid;
                uint32_t bf[2] = { bp[0], bp[4 * SB] };
                mma_tf32(acc[0][nt], a0, bf);
                mma_tf32(acc[1][nt], a1, bf);
            }
        }

        if ((it + 1) % KPI == 0) {
            const int cc = it / KPI;
            #pragma unroll
            for (int m = 0; m < 2; m++) {
                const int n = n0 + nl[m];
                if (n < N_NODES) {
                    #pragma unroll
                    for (int nt3 = 0; nt3 < NT / 3; nt3++) {
                        int co = cc * CO + nt3 * 8 + tig * 2;
                        float bP0 = bias[co],            bP1 = bias[co + 1];
                        float bQ0 = bias[Cout + co],     bQ1 = bias[Cout + co + 1];
                        float bR0 = bias[2 * Cout + co], bR1 = bias[2 * Cout + co + 1];
                        #pragma unroll
                        for (int half = 0; half < 2; half++) {
                            int t = t0s[m] + gid + half * 8;
                            if (t < Tout) {
                                int i0 = half * 2;
                                float P0 = acc[m][nt3][i0] + bP0;
                                float P1 = acc[m][nt3][i0 + 1] + bP1;
                                float Q0 = acc[m][nt3 + NT / 3][i0] + bQ0;
                                float Q1 = acc[m][nt3 + NT / 3][i0 + 1] + bQ1;
                                float R0 = acc[m][nt3 + 2 * NT / 3][i0] + bR0;
                                float R1 = acc[m][nt3 + 2 * NT / 3][i0 + 1] + bR1;
                                float v0 = fmaxf(fmaf(P0, 1.f / (1.f + __expf(-Q0)), R0), 0.f);
                                float v1 = fmaxf(fmaf(P1, 1.f / (1.f + __expf(-Q1)), R1), 0.f);
                                *(float2*)&out[((size_t)(b * Tout + t) * N_NODES + n) * Cout + co] =
                                    make_float2(v0, v1);
                            }
                        }
                    }
                }
            }
            #pragma unroll
            for (int m = 0; m < 2; m++)
                #pragma unroll
                for (int i = 0; i < NT; i++) { acc[m][i][0] = acc[m][i][1] = acc[m][i][2] = acc[m][i][3] = 0.f; }
        }
    }
}

// ---------------- Fused Chebyshev with tf32 MMA combine (1024 thr) ----------------
__global__ void __launch_bounds__(1024, 1)
cheb_mma_kernel(const float* __restrict__ zin, const uint32_t* __restrict__ bpimg,
                const float* __restrict__ bias, float* __restrict__ out,
                const int* __restrict__ rowptr, const int* __restrict__ cols,
                const float* __restrict__ norms)
{
    extern __shared__ float fs[];
    float* As = fs;                                   // 224*196
    uint32_t* Ws = (uint32_t*)(fs + 224 * 196);       // 192*72

    const int bt  = blockIdx.x;
    const int tid = threadIdx.x;
    const size_t base = (size_t)bt * N_NODES * 64;

    for (int i = tid; i < N_NODES * 16; i += 1024) {
        int n = i >> 4, c4 = i & 15;
        cpa16(sptr(As + n * 196 + c4 * 4), zin + base + (size_t)n * 64 + c4 * 4, 16);
    }
    cpa_commit();
    for (int i = tid; i < 3456; i += 1024)
        cpa16(sptr(Ws + i * 4), bpimg + i * 4, 16);
    cpa_commit();
    for (int i = tid; i < 14 * 196; i += 1024)
        As[(210 + i / 196) * 196 + (i % 196)] = 0.f;

    cpa_wait1();
    __syncthreads();

    const int wid = tid >> 5, lane = tid & 31;
    for (int nn = wid; nn < N_NODES; nn += 32) {
        int s = rowptr[nn], e = rowptr[nn + 1];
        float a0 = 0.f, a1 = 0.f;
        for (int i = s; i < e; i++) {
            int c = cols[i]; float w_ = norms[i];
            a0 = fmaf(w_, As[c * 196 + lane], a0);
            a1 = fmaf(w_, As[c * 196 + 32 + lane], a1);
        }
        As[nn * 196 + 64 + lane] = a0;
        As[nn * 196 + 96 + lane] = a1;
    }
    __syncthreads();
    for (int nn = wid; nn < N_NODES; nn += 32) {
        int s = rowptr[nn], e = rowptr[nn + 1];
        float a0 = 0.f, a1 = 0.f;
        for (int i = s; i < e; i++) {
            int c = cols[i]; float w_ = norms[i];
            a0 = fmaf(w_, As[c * 196 + 64 + lane], a0);
            a1 = fmaf(w_, As[c * 196 + 96 + lane], a1);
        }
        As[nn * 196 + 128 + lane] = a0;
        As[nn * 196 + 160 + lane] = a1;
    }
    cpa_waitall();
    __syncthreads();

    if (wid < 28) {
        const int gid = lane >> 2, tig = lane & 3;
        const int mt = wid >> 1, nh = wid & 1;
        const int m0 = mt * 16;
        float acc[4][4];
        #pragma unroll
        for (int i = 0; i < 4; i++) { acc[i][0] = acc[i][1] = acc[i][2] = acc[i][3] = 0.f; }

        #pragma unroll
        for (int kk = 0; kk < 8; kk++) {
            const float* ap = As + (m0 + gid) * 196 + kk * 8 + tig;
            uint32_t hi[4] = { f2tf32v(ap[0]), f2tf32v(ap[8 * 196]),
                               f2tf32v(ap[4]), f2tf32v(ap[8 * 196 + 4]) };
            #pragma unroll
            for (int j = 0; j < 4; j++) {
                int nt = nh * 4 + j;
                const uint32_t* bp = Ws + (kk * 8 + tig) * 72 + nt * 8 + gid;
                uint32_t bf[2] = { bp[0], bp[4 * 72] };
                mma_tf32(acc[j], hi, bf);
            }
        }
        #pragma unroll 4
        for (int kk = 8; kk < 24; kk++) {
            const float* ap = As + (m0 + gid) * 196 + kk * 8 + tig;
            float af[4] = { ap[0], ap[8 * 196], ap[4], ap[8 * 196 + 4] };
            uint32_t hi[4], lo[4];
            #pragma unroll
            for (int e = 0; e < 4; e++) {
                hi[e] = f2tf32v(af[e]);
                lo[e] = f2tf32v(af[e] - __uint_as_float(hi[e]));
            }
            #pragma unroll
            for (int j = 0; j < 4; j++) {
                int nt = nh * 4 + j;
                const uint32_t* bp = Ws + (kk * 8 + tig) * 72 + nt * 8 + gid;
                uint32_t bf[2] = { bp[0], bp[4 * 72] };
                mma_tf32(acc[j], hi, bf);
                mma_tf32(acc[j], lo, bf);
            }
        }

        #pragma unroll
        for (int j = 0; j < 4; j++) {
            int g = (nh * 4 + j) * 8 + tig * 2;
            float b0 = bias[g], b1 = bias[g + 1];
            int n_lo = m0 + gid, n_hi = m0 + gid + 8;
            if (n_lo < N_NODES) {
                float v0 = roundtf(fmaxf(acc[j][0] + b0, 0.f));
                float v1 = roundtf(fmaxf(acc[j][1] + b1, 0.f));
                *(float2*)&out[base + (size_t)n_lo * 64 + g] = make_float2(v0, v1);
            }
            if (n_hi < N_NODES) {
                float v0 = roundtf(fmaxf(acc[j][2] + b0, 0.f));
                float v1 = roundtf(fmaxf(acc[j][3] + b1, 0.f));
                *(float2*)&out[base + (size_t)n_hi * 64 + g] = make_float2(v0, v1);
            }
        }
    }
}

// ---------------- BatchNorm over node channel (in-place, float4, 1024 thr) ----------------
template<int C, bool RND>
__global__ void __launch_bounds__(1024, 1)
bn_kernel(float* __restrict__ x, const float* __restrict__ gamma,
          const float* __restrict__ beta, int BT, int N)
{
    constexpr int C4 = C / 4;
    const int n   = blockIdx.x;
    const int tid = threadIdx.x;  // 1024
    const int M4  = BT * C4;
    float4* x4 = (float4*)x;
    float s = 0.f, s2 = 0.f;
    for (int i = tid; i < M4; i += 1024) {
        int bt = i / C4, c4 = i % C4;
        float4 v = x4[((size_t)bt * N + n) * C4 + c4];
        s  += v.x + v.y + v.z + v.w;
        s2 += v.x * v.x + v.y * v.y + v.z * v.z + v.w * v.w;
    }
    __shared__ float rs[1024], rs2[1024];
    __shared__ float mean_s, istd_s;
    rs[tid] = s; rs2[tid] = s2;
    __syncthreads();
    for (int o = 512; o > 0; o >>= 1) {
        if (tid < o) { rs[tid] += rs[tid + o]; rs2[tid] += rs2[tid + o]; }
        __syncthreads();
    }
    if (tid == 0) {
        float inv = 1.f / (float)(BT * C);
        float mean = rs[0] * inv;
        float var  = rs2[0] * inv - mean * mean;
        mean_s = mean;
        istd_s = rsqrtf(var + 1e-5f);
    }
    __syncthreads();
    const float gm = gamma[n], bt_ = beta[n];
    const float mean = mean_s, istd = istd_s;
    for (int i = tid; i < M4; i += 1024) {
        int bt = i / C4, c4 = i % C4;
        size_t a = ((size_t)bt * N + n) * C4 + c4;
        float4 v = x4[a];
        v.x = (v.x - mean) * istd * gm + bt_;
        v.y = (v.y - mean) * istd * gm + bt_;
        v.z = (v.z - mean) * istd * gm + bt_;
        v.w = (v.w - mean) * istd * gm + bt_;
        if (RND) { v.x = roundtf(v.x); v.y = roundtf(v.y); v.z = roundtf(v.z); v.w = roundtf(v.w); }
        x4[a] = v;
    }
}

// ---------------- Fused BN(C=16) + FC: out = BN(x) @ fc_w + fc_b (512 thr) ----------------
__global__ void __launch_bounds__(512, 2)
bnfc_kernel(const float* __restrict__ x, const float* __restrict__ gamma,
            const float* __restrict__ beta, const float* __restrict__ fw,
            const float* __restrict__ fb, float* __restrict__ out,
            int BT, int N)
{
    const int n   = blockIdx.x;
    const int tid = threadIdx.x;  // 512
    const int M4  = BT * 4;
    const float4* x4 = (const float4*)x;

    __shared__ float fws[48];
    __shared__ float fbs[3];
    if (tid < 48) fws[tid] = fw[tid];
    if (tid < 3)  fbs[tid] = fb[tid];

    float s = 0.f, s2 = 0.f;
    for (int i = tid; i < M4; i += 512) {
        int bt = i >> 2, c4 = i & 3;
        float4 v = x4[((size_t)bt * N + n) * 4 + c4];
        s  += v.x + v.y + v.z + v.w;
        s2 += v.x * v.x + v.y * v.y + v.z * v.z + v.w * v.w;
    }
    __shared__ float rs[512], rs2[512];
    __shared__ float mean_s, istd_s;
    rs[tid] = s; rs2[tid] = s2;
    __syncthreads();
    for (int o = 256; o > 0; o >>= 1) {
        if (tid < o) { rs[tid] += rs[tid + o]; rs2[tid] += rs2[tid + o]; }
        __syncthreads();
    }
    if (tid == 0) {
        float inv = 1.f / (float)(BT * 16);
        float mean = rs[0] * inv;
        float var  = rs2[0] * inv - mean * mean;
        mean_s = mean;
        istd_s = rsqrtf(var + 1e-5f);
    }
    __syncthreads();
    const float gm = gamma[n], bt_ = beta[n];
    const float mean = mean_s, istd = istd_s;

    for (int bt = tid; bt < BT; bt += 512) {
        const float4* row = &x4[((size_t)bt * N + n) * 4];
        float o0 = fbs[0], o1 = fbs[1], o2 = fbs[2];
        #pragma unroll
        for (int c4 = 0; c4 < 4; c4++) {
            float4 v = row[c4];
            float h0 = (v.x - mean) * istd * gm + bt_;
            float h1 = (v.y - mean) * istd * gm + bt_;
            float h2 = (v.z - mean) * istd * gm + bt_;
            float h3 = (v.w - mean) * istd * gm + bt_;
            int c = c4 * 4;
            o0 = fmaf(h0, fws[(c + 0) * 3 + 0], o0); o1 = fmaf(h0, fws[(c + 0) * 3 + 1], o1); o2 = fmaf(h0, fws[(c + 0) * 3 + 2], o2);
            o0 = fmaf(h1, fws[(c + 1) * 3 + 0], o0); o1 = fmaf(h1, fws[(c + 1) * 3 + 1], o1); o2 = fmaf(h1, fws[(c + 1) * 3 + 2], o2);
            o0 = fmaf(h2, fws[(c + 2) * 3 + 0], o0); o1 = fmaf(h2, fws[(c + 2) * 3 + 1], o1); o2 = fmaf(h2, fws[(c + 2) * 3 + 2], o2);
            o0 = fmaf(h3, fws[(c + 3) * 3 + 0], o0); o1 = fmaf(h3, fws[(c + 3) * 3 + 1], o1); o2 = fmaf(h3, fws[(c + 3) * 3 + 2], o2);
        }
        size_t r = (size_t)bt * N + n;
        out[r * 3 + 0] = o0;
        out[r * 3 + 1] = o1;
        out[r * 3 + 2] = o2;
    }
}

// ---------------- Launch ----------------
extern "C" void kernel_launch(void* const* d_in, const int* in_sizes, int n_in,
                              void* d_out, int out_size)
{
    const float* x        = (const float*)d_in[0];
    const int*   eidx     = (const int*)d_in[1];
    const float* eattr    = (const float*)d_in[2];
    const float* b1_t1_w  = (const float*)d_in[3];
    const float* b1_t1_b  = (const float*)d_in[4];
    const float* b1_ch_w  = (const float*)d_in[5];
    const float* b1_ch_b  = (const float*)d_in[6];
    const float* b1_t2_w  = (const float*)d_in[7];
    const float* b1_t2_b  = (const float*)d_in[8];
    const float* b1_bn_g  = (const float*)d_in[9];
    const float* b1_bn_b  = (const float*)d_in[10];
    const float* b2_t1_w  = (const float*)d_in[11];
    const float* b2_t1_b  = (const float*)d_in[12];
    const float* b2_ch_w  = (const float*)d_in[13];
    const float* b2_ch_b  = (const float*)d_in[14];
    const float* b2_t2_w  = (const float*)d_in[15];
    const float* b2_t2_b  = (const float*)d_in[16];
    const float* b2_bn_g  = (const float*)d_in[17];
    const float* b2_bn_b  = (const float*)d_in[18];
    const float* fc_w     = (const float*)d_in[19];
    const float* fc_b     = (const float*)d_in[20];

    float *bufA, *bufB, *bufC, *nrm, *xpad;
    int *rowptr, *cols; uint32_t *wt, *bp;
    cudaGetSymbolAddress((void**)&bufA,  g_bufA);
    cudaGetSymbolAddress((void**)&bufB,  g_bufB);
    cudaGetSymbolAddress((void**)&bufC,  g_bufC);
    cudaGetSymbolAddress((void**)&xpad,  g_xpad);
    cudaGetSymbolAddress((void**)&rowptr, g_rowptr);
    cudaGetSymbolAddress((void**)&cols,  g_cols);
    cudaGetSymbolAddress((void**)&nrm,   g_norm);
    cudaGetSymbolAddress((void**)&wt,    g_wt);
    cudaGetSymbolAddress((void**)&bp,    g_bp);

    const int N = N_NODES;

    // instantiations:           Cin CINP Cout Kt Tin Tout TP NG KSUB CO  ACP  MINB
    auto k_b1t2 = tconv_mma<64, 64, 128, 9, 56, 48, 48, 4, 64, 32, true, 2>;  // 6 warps, 2 blk/SM
    auto k_b2t2 = tconv_mma<64, 64, 16, 5, 44, 40, 48, 4, 64, 16, true, 2>;   // 6 warps, 2 blk/SM

    const int sm_t1c  = (4 * 72 * 20 + 144 * 104) * 4;       // 82,944
    const int sm_b1t2 = (4 * 56 * 68 + 2 * 64 * 104) * 4;    // 114,176
    const int sm_b2t1 = (4 * 52 * 68 + 2 * 64 * 104) * 4;    // 109,824 (K-split)
    const int sm_b2t2 = (4 * 52 * 68 + 2 * 64 * 56) * 4;     // 85,248
    const int sm_cheb = (224 * 196 + 192 * 72) * 4;          // 230,912

    cudaFuncSetAttribute(t1conv_kernel, cudaFuncAttributeMaxDynamicSharedMemorySize, sm_t1c);
    cudaFuncSetAttribute(k_b1t2, cudaFuncAttributeMaxDynamicSharedMemorySize, sm_b1t2);
    cudaFuncSetAttribute(b2t1_kernel, cudaFuncAttributeMaxDynamicSharedMemorySize, sm_b2t1);
    cudaFuncSetAttribute(k_b2t2, cudaFuncAttributeMaxDynamicSharedMemorySize, sm_b2t2);
    cudaFuncSetAttribute(cheb_mma_kernel, cudaFuncAttributeMaxDynamicSharedMemorySize, sm_cheb);

    // ---- prep ----
    build_csr_kernel<<<1, 256>>>(eidx, eattr, rowptr, cols, nrm);
    wconv_kernel<<<(387072 + 255) / 256, 256>>>(b1_t1_w, b1_t2_w, b2_t1_w, b2_t2_w, wt);
    bp_build_kernel<<<(2 * 13824 + 255) / 256, 256>>>(b1_ch_w, b2_ch_w);
    xpad_kernel<<<1184, 512>>>(x);

    // ======== Block 1 ========
    t1conv_kernel<<<dim3(53, BATCH), 256, sm_t1c>>>(xpad, wt + WOFF1, b1_t1_b, bufA);
    cheb_mma_kernel<<<32 * 56, 1024, sm_cheb>>>(bufA, bp, b1_ch_b, bufB, rowptr, cols, nrm);
    k_b1t2<<<dim3(53, BATCH), 192, sm_b1t2>>>(bufB, wt + WOFF2, b1_t2_b, bufC);
    bn_kernel<128, true><<<N, 1024>>>(bufC, b1_bn_g, b1_bn_b, 32 * 48, N);

    // ======== Block 2 ========
    b2t1_kernel<<<dim3(53, BATCH), 192, sm_b2t1>>>(bufC, wt + WOFF3, b2_t1_b, bufA);
    cheb_mma_kernel<<<32 * 44, 1024, sm_cheb>>>(bufA, bp + 13824, b2_ch_b, bufB, rowptr, cols, nrm);
    k_b2t2<<<dim3(53, BATCH), 192, sm_b2t2>>>(bufB, wt + WOFF4, b2_t2_b, bufC);

    // ---- fused BN2 + FC ----
    bnfc_kernel<<<N, 512>>>(bufC, b2_bn_g, b2_bn_b, fc_w, fc_b, (float*)d_out, 32 * 40, N);

    (void)in_sizes; (void)n_in; (void)out_size;
}